// round 1
// baseline (speedup 1.0000x reference)
#include <cuda_runtime.h>
#include <cuda_bf16.h>
#include <math.h>

// ---------------- problem constants ----------------
#define BB 4
#define TT 1024
#define EE 768
#define LL 6
#define HH 6
#define HD 128
#define VV 32000
#define FF (4*EE)          // 3072
#define BT (BB*TT)         // 4096
#define BTV ((long long)BT*VV)

// ---------------- scratch (device globals; no allocations allowed) ----------------
__device__ float g_x [BT*EE];
__device__ float g_h [BT*EE];
__device__ float g_q [BT*EE];
__device__ float g_k [BT*EE];
__device__ float g_v [BT*EE];
__device__ float g_o [BT*EE];
__device__ float g_ff[BT*FF];
__device__ float g_att[(long long)BB*HH*TT*TT];   // 100.7 MB
__device__ float g_nll[BT];
__device__ float g_logits_fb[BTV];                // fallback if out_size < BT*V
__device__ int   g_is64_idx;
__device__ int   g_is64_tgt;

// ---------------- int64-vs-int32 detection ----------------
// JAX may canonicalize int64 -> int32 (x64 disabled). If truly int64 (values
// in [0,32000)), every odd 32-bit word is 0. int32 token streams are ~never
// 64-consecutive-zero at odd positions.
__global__ void detect_kernel(const int* __restrict__ idx, const int* __restrict__ tgt) {
    if (threadIdx.x == 0 && blockIdx.x == 0) {
        int a = 1, b = 1;
        for (int i = 1; i < 129; i += 2) {
            if (idx[i] != 0) a = 0;
            if (tgt[i] != 0) b = 0;
        }
        g_is64_idx = a;
        g_is64_tgt = b;
    }
}

__device__ __forceinline__ long long load_token(const void* p, int r, int is64) {
    if (is64) return ((const long long*)p)[r];
    return (long long)((const int*)p)[r];
}

// ---------------- embedding ----------------
__global__ void embed_kernel(const void* __restrict__ idxv,
                             const float* __restrict__ tok,
                             const float* __restrict__ pos,
                             float* __restrict__ x) {
    int r = blockIdx.x;                 // 0..BT-1
    long long token = load_token(idxv, r, g_is64_idx);
    int t = r % TT;
    const float* te = tok + token * EE;
    const float* pe = pos + (long long)t * EE;
    float* xr = x + (long long)r * EE;
    for (int e = threadIdx.x; e < EE; e += blockDim.x)
        xr[e] = te[e] + pe[e];
}

// ---------------- layernorm (one block per row, 256 thr, E=768 -> 3/thr) ----------------
__global__ void layernorm_kernel(const float* __restrict__ x, float* __restrict__ y,
                                 const float* __restrict__ s, const float* __restrict__ b) {
    int r = blockIdx.x;
    const float* row = x + (long long)r * EE;
    float* out = y + (long long)r * EE;
    int tid = threadIdx.x;
    __shared__ float red[256];

    float v0 = row[tid], v1 = row[tid + 256], v2 = row[tid + 512];
    float sum = v0 + v1 + v2;
    red[tid] = sum; __syncthreads();
    for (int k = 128; k > 0; k >>= 1) { if (tid < k) red[tid] += red[tid + k]; __syncthreads(); }
    float mean = red[0] * (1.0f / EE);
    __syncthreads();

    float d0 = v0 - mean, d1 = v1 - mean, d2 = v2 - mean;
    red[tid] = d0*d0 + d1*d1 + d2*d2; __syncthreads();
    for (int k = 128; k > 0; k >>= 1) { if (tid < k) red[tid] += red[tid + k]; __syncthreads(); }
    float inv = rsqrtf(red[0] * (1.0f / EE) + 1e-5f);

    out[tid      ] = d0 * inv * s[tid      ] + b[tid      ];
    out[tid + 256] = d1 * inv * s[tid + 256] + b[tid + 256];
    out[tid + 512] = d2 * inv * s[tid + 512] + b[tid + 512];
}

// ---------------- generic batched SGEMM ----------------
// C[m,n] = sum_k A[m,k] * (TRANSB ? B[n,k] : B[k,n])   (+bias, +relu, +=C)
// z-batched: z -> (zb = z/Hdiv, zh = z%Hdiv); per-operand offsets.
// All dims must be multiples of 64 (M,N) and 16 (K) -- true for every call here.
#define GBM 64
#define GBN 64
#define GBK 16

template<bool TRANSB>
__global__ void __launch_bounds__(256)
sgemm_kernel(const float* __restrict__ A, int lda, long long aOffB, long long aOffH,
             const float* __restrict__ Bm, int ldb, long long bOffB, long long bOffH,
             float* __restrict__ C, int ldc, long long cOffB, long long cOffH,
             int M, int N, int K, int Hdiv,
             const float* __restrict__ bias, int epi, int causal, int kLimit) {
    int z  = blockIdx.z;
    int zb = z / Hdiv, zh = z - zb * Hdiv;
    A  += zb * aOffB + zh * aOffH;
    Bm += zb * bOffB + zh * bOffH;
    C  += zb * cOffB + zh * cOffH;

    int m0 = blockIdx.y * GBM;
    int n0 = blockIdx.x * GBN;
    if (causal && n0 > m0 + GBM - 1) return;   // fully masked block of QK^T
    int Keff = K;
    if (kLimit) Keff = min(K, m0 + GBM);       // attn rows only reach col <= row

    __shared__ float As[GBK][GBM + 4];
    __shared__ float Bs[GBK][GBN + 4];

    int tid = threadIdx.x;
    int tx = tid & 15, ty = tid >> 4;
    int rowA = tid >> 2;            // 0..63
    int kA4  = (tid & 3) * 4;       // 0,4,8,12
    int rowBk = tid >> 4;           // 0..15   (non-trans B: k index)
    int colB4 = (tid & 15) * 4;     // 0..60

    float acc[4][4] = {};

    for (int k0 = 0; k0 < Keff; k0 += GBK) {
        float4 a4 = *(const float4*)(A + (long long)(m0 + rowA) * lda + k0 + kA4);
        As[kA4 + 0][rowA] = a4.x;
        As[kA4 + 1][rowA] = a4.y;
        As[kA4 + 2][rowA] = a4.z;
        As[kA4 + 3][rowA] = a4.w;
        if (TRANSB) {
            float4 b4 = *(const float4*)(Bm + (long long)(n0 + rowA) * ldb + k0 + kA4);
            Bs[kA4 + 0][rowA] = b4.x;
            Bs[kA4 + 1][rowA] = b4.y;
            Bs[kA4 + 2][rowA] = b4.z;
            Bs[kA4 + 3][rowA] = b4.w;
        } else {
            float4 b4 = *(const float4*)(Bm + (long long)(k0 + rowBk) * ldb + n0 + colB4);
            *(float4*)&Bs[rowBk][colB4] = b4;
        }
        __syncthreads();

        #pragma unroll
        for (int kk = 0; kk < GBK; kk++) {
            float a[4], bvv[4];
            #pragma unroll
            for (int i = 0; i < 4; i++) a[i]   = As[kk][ty * 4 + i];
            #pragma unroll
            for (int j = 0; j < 4; j++) bvv[j] = Bs[kk][tx * 4 + j];
            #pragma unroll
            for (int i = 0; i < 4; i++)
                #pragma unroll
                for (int j = 0; j < 4; j++)
                    acc[i][j] += a[i] * bvv[j];
        }
        __syncthreads();
    }

    #pragma unroll
    for (int i = 0; i < 4; i++) {
        int m = m0 + ty * 4 + i;
        float* crow = C + (long long)m * ldc + n0 + tx * 4;
        #pragma unroll
        for (int j = 0; j < 4; j++) {
            float val = acc[i][j];
            if (bias) val += bias[n0 + tx * 4 + j];
            if (epi == 1) val = fmaxf(val, 0.0f);
            if (epi == 2) val += crow[j];
            crow[j] = val;
        }
    }
}

// ---------------- causal softmax over attention scores ----------------
__global__ void softmax_causal_kernel(float* __restrict__ att) {
    int i = blockIdx.x;     // query index 0..T-1
    int z = blockIdx.y;     // b*H+h
    float* row = att + (long long)z * TT * TT + (long long)i * TT;
    const float scale = 0.0883883476483184406f;   // 1/sqrt(128)
    int tid = threadIdx.x;  // 128 threads, 8 cols each
    __shared__ float red[128];

    float vloc[8];
    float m = -1e30f;
    #pragma unroll
    for (int c = 0; c < 8; c++) {
        int j = tid + c * 128;
        float s = (j <= i) ? row[j] * scale : -1e30f;
        vloc[c] = s;
        m = fmaxf(m, s);
    }
    red[tid] = m; __syncthreads();
    for (int k = 64; k > 0; k >>= 1) { if (tid < k) red[tid] = fmaxf(red[tid], red[tid + k]); __syncthreads(); }
    m = red[0]; __syncthreads();

    float sum = 0.0f;
    #pragma unroll
    for (int c = 0; c < 8; c++) {
        int j = tid + c * 128;
        float e = (j <= i) ? __expf(vloc[c] - m) : 0.0f;
        vloc[c] = e;
        sum += e;
    }
    red[tid] = sum; __syncthreads();
    for (int k = 64; k > 0; k >>= 1) { if (tid < k) red[tid] += red[tid + k]; __syncthreads(); }
    float inv = 1.0f / red[0];

    #pragma unroll
    for (int c = 0; c < 8; c++)
        row[tid + c * 128] = vloc[c] * inv;
}

// ---------------- per-row NLL via streaming logsumexp ----------------
__global__ void loss_rows_kernel(const float* __restrict__ logits,
                                 const void* __restrict__ tgtv,
                                 float* __restrict__ nll) {
    int r = blockIdx.x;
    const float* row = logits + (long long)r * VV;
    int tid = threadIdx.x;   // 256
    float m = -1e30f, s = 0.0f;
    for (int j = tid; j < VV; j += 256) {
        float v = row[j];
        if (v > m) { s = s * __expf(m - v) + 1.0f; m = v; }
        else       { s += __expf(v - m); }
    }
    __shared__ float sm[256], ss[256];
    sm[tid] = m; ss[tid] = s; __syncthreads();
    for (int k = 128; k > 0; k >>= 1) {
        if (tid < k) {
            float m2 = sm[tid + k], s2 = ss[tid + k];
            float mm = fmaxf(sm[tid], m2);
            ss[tid] = ss[tid] * __expf(sm[tid] - mm) + s2 * __expf(m2 - mm);
            sm[tid] = mm;
        }
        __syncthreads();
    }
    if (tid == 0) {
        long long t = load_token(tgtv, r, g_is64_tgt);
        nll[r] = (sm[0] + logf(ss[0])) - row[t];
    }
}

__global__ void loss_final_kernel(const float* __restrict__ nll, float* __restrict__ out, int n) {
    __shared__ float red[256];
    int tid = threadIdx.x;
    float s = 0.0f;
    for (int j = tid; j < BT; j += 256) s += nll[j];
    red[tid] = s; __syncthreads();
    for (int k = 128; k > 0; k >>= 1) { if (tid < k) red[tid] += red[tid + k]; __syncthreads(); }
    float mean = red[0] * (1.0f / BT);
    for (int i = tid; i < n; i += 256) out[i] = mean;
}

// ---------------- host-side helpers ----------------
static void launch_gemm(bool transB,
                        const float* A, int lda, long long aB, long long aH,
                        const float* Bm, int ldb, long long bB, long long bH,
                        float* C, int ldc, long long cB, long long cH,
                        int M, int N, int K, int Hdiv, int Z,
                        const float* bias, int epi, int causal, int kLimit) {
    dim3 grid(N / GBN, M / GBM, Z), blk(256);
    if (transB)
        sgemm_kernel<true ><<<grid, blk>>>(A, lda, aB, aH, Bm, ldb, bB, bH, C, ldc, cB, cH,
                                           M, N, K, Hdiv, bias, epi, causal, kLimit);
    else
        sgemm_kernel<false><<<grid, blk>>>(A, lda, aB, aH, Bm, ldb, bB, bH, C, ldc, cB, cH,
                                           M, N, K, Hdiv, bias, epi, causal, kLimit);
}

extern "C" void kernel_launch(void* const* d_in, const int* in_sizes, int n_in,
                              void* d_out, int out_size) {
    // inputs in setup_inputs() order
    const void*  idx  = d_in[0];
    const void*  tgt  = d_in[1];
    const float* tok  = (const float*)d_in[2];
    const float* pos  = (const float*)d_in[3];
    const float* Wq   = (const float*)d_in[4];
    const float* bq   = (const float*)d_in[5];
    const float* Wk   = (const float*)d_in[6];
    const float* bk   = (const float*)d_in[7];
    const float* Wv   = (const float*)d_in[8];
    const float* bv   = (const float*)d_in[9];
    const float* Wo   = (const float*)d_in[10];
    const float* bo   = (const float*)d_in[11];
    const float* w1   = (const float*)d_in[12];
    const float* b1   = (const float*)d_in[13];
    const float* w2   = (const float*)d_in[14];
    const float* b2   = (const float*)d_in[15];
    const float* ln1s = (const float*)d_in[16];
    const float* ln1b = (const float*)d_in[17];
    const float* ln2s = (const float*)d_in[18];
    const float* ln2b = (const float*)d_in[19];
    const float* lnfs = (const float*)d_in[20];
    const float* lnfb = (const float*)d_in[21];
    const float* Wlm  = (const float*)d_in[22];
    const float* blm  = (const float*)d_in[23];

    float *x, *h, *q, *k, *v, *o, *ff, *att, *nll, *logits_fb;
    cudaGetSymbolAddress((void**)&x,   g_x);
    cudaGetSymbolAddress((void**)&h,   g_h);
    cudaGetSymbolAddress((void**)&q,   g_q);
    cudaGetSymbolAddress((void**)&k,   g_k);
    cudaGetSymbolAddress((void**)&v,   g_v);
    cudaGetSymbolAddress((void**)&o,   g_o);
    cudaGetSymbolAddress((void**)&ff,  g_ff);
    cudaGetSymbolAddress((void**)&att, g_att);
    cudaGetSymbolAddress((void**)&nll, g_nll);
    cudaGetSymbolAddress((void**)&logits_fb, g_logits_fb);

    float* out = (float*)d_out;
    float* logits = ((long long)out_size >= BTV) ? out : logits_fb;
    float* lossPtr = nullptr;
    int nLoss = 0;
    if ((long long)out_size > BTV) { lossPtr = out + BTV; nLoss = out_size - (int)BTV; }
    else if ((long long)out_size < BTV) { lossPtr = out; nLoss = out_size; }

    detect_kernel<<<1, 32>>>((const int*)idx, (const int*)tgt);
    embed_kernel<<<BT, 256>>>(idx, tok, pos, x);

    const long long ZTE  = (long long)TT * EE;      // per-batch stride in q/k/v/o
    const long long ZATT = (long long)TT * TT;      // per-head stride in att
    for (int l = 0; l < LL; l++) {
        const float* Wq_l = Wq + (long long)l * EE * EE;
        const float* Wk_l = Wk + (long long)l * EE * EE;
        const float* Wv_l = Wv + (long long)l * EE * EE;
        const float* Wo_l = Wo + (long long)l * EE * EE;
        const float* w1_l = w1 + (long long)l * EE * FF;
        const float* w2_l = w2 + (long long)l * FF * EE;

        // h = LN1(x)
        layernorm_kernel<<<BT, 256>>>(x, h, ln1s + l * EE, ln1b + l * EE);

        // q,k,v = h @ W + b
        launch_gemm(false, h, EE, 0, 0, Wq_l, EE, 0, 0, q, EE, 0, 0,
                    BT, EE, EE, 1, 1, bq + l * EE, 0, 0, 0);
        launch_gemm(false, h, EE, 0, 0, Wk_l, EE, 0, 0, k, EE, 0, 0,
                    BT, EE, EE, 1, 1, bk + l * EE, 0, 0, 0);
        launch_gemm(false, h, EE, 0, 0, Wv_l, EE, 0, 0, v, EE, 0, 0,
                    BT, EE, EE, 1, 1, bv + l * EE, 0, 0, 0);

        // scores[z] = q_z @ k_z^T  (z = b*H + h), causal blocks skipped
        launch_gemm(true, q, EE, ZTE, HD, k, EE, ZTE, HD,
                    att, TT, (long long)HH * ZATT, ZATT,
                    TT, TT, HD, HH, BB * HH, nullptr, 0, 1, 0);

        softmax_causal_kernel<<<dim3(TT, BB * HH), 128>>>(att);

        // o[z] = att_z @ v_z   (K limited to row-block's causal extent)
        launch_gemm(false, att, TT, (long long)HH * ZATT, ZATT, v, EE, ZTE, HD,
                    o, EE, ZTE, HD,
                    TT, HD, TT, HH, BB * HH, nullptr, 0, 0, 1);

        // x += o @ Wo + bo
        launch_gemm(false, o, EE, 0, 0, Wo_l, EE, 0, 0, x, EE, 0, 0,
                    BT, EE, EE, 1, 1, bo + l * EE, 2, 0, 0);

        // h = LN2(x)
        layernorm_kernel<<<BT, 256>>>(x, h, ln2s + l * EE, ln2b + l * EE);

        // ff = relu(h @ w1 + b1);  x += ff @ w2 + b2
        launch_gemm(false, h, EE, 0, 0, w1_l, FF, 0, 0, ff, FF, 0, 0,
                    BT, FF, EE, 1, 1, b1 + (long long)l * FF, 1, 0, 0);
        launch_gemm(false, ff, FF, 0, 0, w2_l, EE, 0, 0, x, EE, 0, 0,
                    BT, EE, FF, 1, 1, b2 + l * EE, 2, 0, 0);
    }

    // final LN + LM head
    layernorm_kernel<<<BT, 256>>>(x, h, lnfs, lnfb);
    launch_gemm(false, h, EE, 0, 0, Wlm, VV, 0, 0, logits, VV, 0, 0,
                BT, VV, EE, 1, 1, blm, 0, 0, 0);

    // loss
    loss_rows_kernel<<<BT, 256>>>(logits, tgt, nll);
    if (nLoss > 0)
        loss_final_kernel<<<1, 256>>>(nll, lossPtr, nLoss);
}

// round 3
// speedup vs baseline: 3.1339x; 3.1339x over previous
#include <cuda_runtime.h>
#include <cuda_bf16.h>
#include <math.h>
#include <stdint.h>

// ---------------- problem constants ----------------
#define BB 4
#define TT 1024
#define EE 768
#define LL 6
#define HH 6
#define HD 128
#define VV 32000
#define FF (4*EE)          // 3072
#define BT (BB*TT)         // 4096
#define BTV ((long long)BT*VV)

// ---------------- scratch (device globals; no allocations allowed) ----------------
__device__ float g_x [BT*EE];
__device__ float g_h [BT*EE];
__device__ float g_q [BT*EE];
__device__ float g_k [BT*EE];
__device__ float g_v [BT*EE];
__device__ float g_o [BT*EE];
__device__ float g_ff[BT*FF];
__device__ float g_att[(long long)BB*HH*TT*TT];   // 100.7 MB
__device__ float g_nll[BT];
__device__ float g_logits_fb[BTV];                // fallback if out_size < BT*V
__device__ int   g_is64_idx;
__device__ int   g_is64_tgt;
// transposed (K-major [N,K]) operands, all pre-rounded to tf32 (rna)
__device__ float g_wqT [LL*EE*EE];
__device__ float g_wkT [LL*EE*EE];
__device__ float g_wvT [LL*EE*EE];
__device__ float g_woT [LL*EE*EE];
__device__ float g_w1T [(long long)LL*EE*FF];
__device__ float g_w2T [(long long)LL*EE*FF];
__device__ float g_wlmT[(long long)EE*VV];
__device__ float g_vT  [(long long)BB*HH*HD*TT];

// ---------------- small helpers ----------------
__device__ __forceinline__ uint32_t smem_u32(const void* p) {
    uint32_t a;
    asm("{ .reg .u64 t; cvta.to.shared.u64 t, %1; cvt.u32.u64 %0, t; }" : "=r"(a) : "l"(p));
    return a;
}

__device__ __forceinline__ float rna_tf32(float x) {
    uint32_t u;
    asm("cvt.rna.tf32.f32 %0, %1;" : "=r"(u) : "f"(x));
    return __uint_as_float(u);
}

__device__ __forceinline__ void cp_async16(uint32_t saddr, const void* gaddr) {
    asm volatile("cp.async.cg.shared.global [%0], [%1], 16;" :: "r"(saddr), "l"(gaddr));
}

// tf32 mma.sync: D(16x8) += A(16x8) * B(8x8), row.col
__device__ __forceinline__ void mma_tf32(float* c, const uint32_t* a, const uint32_t* b) {
    asm volatile(
        "mma.sync.aligned.m16n8k8.row.col.f32.tf32.tf32.f32 "
        "{%0,%1,%2,%3}, {%4,%5,%6,%7}, {%8,%9}, {%0,%1,%2,%3};"
        : "+f"(c[0]), "+f"(c[1]), "+f"(c[2]), "+f"(c[3])
        : "r"(a[0]), "r"(a[1]), "r"(a[2]), "r"(a[3]), "r"(b[0]), "r"(b[1]));
}

// ---------------- int64-vs-int32 detection ----------------
__global__ void detect_kernel(const int* __restrict__ idx, const int* __restrict__ tgt) {
    if (threadIdx.x == 0 && blockIdx.x == 0) {
        int a = 1, b = 1;
        for (int i = 1; i < 129; i += 2) {
            if (idx[i] != 0) a = 0;
            if (tgt[i] != 0) b = 0;
        }
        g_is64_idx = a;
        g_is64_tgt = b;
    }
}

__device__ __forceinline__ long long load_token(const void* p, int r, int is64) {
    if (is64) return ((const long long*)p)[r];
    return (long long)((const int*)p)[r];
}

// ---------------- embedding ----------------
__global__ void embed_kernel(const void* __restrict__ idxv,
                             const float* __restrict__ tok,
                             const float* __restrict__ pos,
                             float* __restrict__ x) {
    int r = blockIdx.x;
    long long token = load_token(idxv, r, g_is64_idx);
    int t = r % TT;
    const float* te = tok + token * EE;
    const float* pe = pos + (long long)t * EE;
    float* xr = x + (long long)r * EE;
    for (int e = threadIdx.x; e < EE; e += blockDim.x)
        xr[e] = te[e] + pe[e];
}

// ---------------- layernorm (rna-rounded output: it always feeds a GEMM) ----------------
__global__ void layernorm_kernel(const float* __restrict__ x, float* __restrict__ y,
                                 const float* __restrict__ s, const float* __restrict__ b) {
    int r = blockIdx.x;
    const float* row = x + (long long)r * EE;
    float* out = y + (long long)r * EE;
    int tid = threadIdx.x;
    __shared__ float red[256];

    float v0 = row[tid], v1 = row[tid + 256], v2 = row[tid + 512];
    red[tid] = v0 + v1 + v2; __syncthreads();
    for (int k = 128; k > 0; k >>= 1) { if (tid < k) red[tid] += red[tid + k]; __syncthreads(); }
    float mean = red[0] * (1.0f / EE);
    __syncthreads();

    float d0 = v0 - mean, d1 = v1 - mean, d2 = v2 - mean;
    red[tid] = d0*d0 + d1*d1 + d2*d2; __syncthreads();
    for (int k = 128; k > 0; k >>= 1) { if (tid < k) red[tid] += red[tid + k]; __syncthreads(); }
    float inv = rsqrtf(red[0] * (1.0f / EE) + 1e-5f);

    out[tid      ] = rna_tf32(d0 * inv * s[tid      ] + b[tid      ]);
    out[tid + 256] = rna_tf32(d1 * inv * s[tid + 256] + b[tid + 256]);
    out[tid + 512] = rna_tf32(d2 * inv * s[tid + 512] + b[tid + 512]);
}

// ---------------- generic batched transpose (rna output) ----------------
__global__ void transpose_kernel(const float* __restrict__ src, float* __restrict__ dst,
                                 int srs, int drs,
                                 long long sB, long long sH, long long dB, long long dH,
                                 int Hdiv) {
    int z = blockIdx.z, zb = z / Hdiv, zh = z - zb * Hdiv;
    src += zb * sB + zh * sH;
    dst += zb * dB + zh * dH;
    __shared__ float tile[32][33];
    int c0 = blockIdx.x * 32, r0 = blockIdx.y * 32;
    int tx = threadIdx.x, ty = threadIdx.y;   // 32 x 8
    #pragma unroll
    for (int i = 0; i < 32; i += 8)
        tile[ty + i][tx] = src[(long long)(r0 + ty + i) * srs + c0 + tx];
    __syncthreads();
    #pragma unroll
    for (int i = 0; i < 32; i += 8)
        dst[(long long)(c0 + ty + i) * drs + r0 + tx] = rna_tf32(tile[tx][ty + i]);
}

// ---------------- tf32 mma.sync GEMM ----------------
// C[m,n] = sum_k A[m,k] * B[n,k]   (A [M,K] K-major, B [N,K] K-major)
// M,N multiples of 128; K multiple of 32.
// epi bits: 1=relu, 2=residual-add, 4=rna output. bias applied if non-null.
#define NST 3
#define SSTRIDE 36                       // floats per smem row (144B: 16B aligned, conflict-free)
#define STAGE_F (2*128*SSTRIDE)          // floats per stage (A+B)
#define TC_SMEM (NST*STAGE_F*4)          // 110592 bytes

__device__ __forceinline__ void load_chunk(const float* __restrict__ A, int lda,
                                           const float* __restrict__ Bm, int ldb,
                                           uint32_t sA, uint32_t sB,
                                           int m0, int n0, int k0, int tid) {
    #pragma unroll
    for (int t = 0; t < 4; t++) {
        int seg = tid + t * 256;
        int row = seg >> 3, kq = seg & 7;
        cp_async16(sA + (uint32_t)(row * (SSTRIDE*4) + kq * 16),
                   A + (long long)(m0 + row) * lda + k0 + kq * 4);
    }
    #pragma unroll
    for (int t = 0; t < 4; t++) {
        int seg = tid + t * 256;
        int row = seg >> 3, kq = seg & 7;
        cp_async16(sB + (uint32_t)(row * (SSTRIDE*4) + kq * 16),
                   Bm + (long long)(n0 + row) * ldb + k0 + kq * 4);
    }
}

__global__ void __launch_bounds__(256, 2)
tc_gemm(const float* __restrict__ A, int lda, long long aOffB, long long aOffH,
        const float* __restrict__ Bm, int ldb, long long bOffB, long long bOffH,
        float* __restrict__ C, int ldc, long long cOffB, long long cOffH,
        int K, int Hdiv, const float* __restrict__ bias, int epi, int causal, int kLimit) {
    int m0 = blockIdx.y * 128, n0 = blockIdx.x * 128;
    if (causal && n0 > m0 + 127) return;   // fully-masked QK^T block

    int z = blockIdx.z, zb = z / Hdiv, zh = z - zb * Hdiv;
    A  += zb * aOffB + zh * aOffH;
    Bm += zb * bOffB + zh * bOffH;
    C  += zb * cOffB + zh * cOffH;

    int Keff = kLimit ? min(K, m0 + 128) : K;
    int nchunks = Keff >> 5;

    extern __shared__ float sm[];
    uint32_t sb = smem_u32(sm);
    int tid = threadIdx.x, wid = tid >> 5, lane = tid & 31;
    int wm = wid & 1, wn = wid >> 1;       // 2 x 4 warp grid; warp tile 64x32
    int lr = lane >> 2, lc = lane & 3;

    float acc[4][4][4];
    #pragma unroll
    for (int i = 0; i < 4; i++)
        #pragma unroll
        for (int j = 0; j < 4; j++)
            #pragma unroll
            for (int e = 0; e < 4; e++) acc[i][j][e] = 0.0f;

    // prologue: NST-1 stages in flight
    #pragma unroll
    for (int s = 0; s < NST - 1; s++) {
        if (s < nchunks)
            load_chunk(A, lda, Bm, ldb, sb + s * (STAGE_F*4), sb + s * (STAGE_F*4) + 128*SSTRIDE*4,
                       m0, n0, s * 32, tid);
        asm volatile("cp.async.commit_group;" ::: "memory");
    }

    for (int c = 0; c < nchunks; c++) {
        asm volatile("cp.async.wait_group %0;" :: "n"(NST - 2) : "memory");
        __syncthreads();

        int cn = c + NST - 1;
        if (cn < nchunks) {
            int sn = cn % NST;
            load_chunk(A, lda, Bm, ldb, sb + sn * (STAGE_F*4), sb + sn * (STAGE_F*4) + 128*SSTRIDE*4,
                       m0, n0, cn * 32, tid);
        }
        asm volatile("cp.async.commit_group;" ::: "memory");

        const float* As = sm + (c % NST) * STAGE_F;
        const float* Bs = As + 128 * SSTRIDE;

        #pragma unroll
        for (int ks = 0; ks < 4; ks++) {
            uint32_t afr[4][4], bfr[4][2];
            #pragma unroll
            for (int i = 0; i < 4; i++) {
                const float* ab = As + (wm * 64 + i * 16 + lr) * SSTRIDE + ks * 8 + lc;
                afr[i][0] = __float_as_uint(ab[0]);
                afr[i][1] = __float_as_uint(ab[8 * SSTRIDE]);
                afr[i][2] = __float_as_uint(ab[4]);
                afr[i][3] = __float_as_uint(ab[8 * SSTRIDE + 4]);
            }
            #pragma unroll
            for (int j = 0; j < 4; j++) {
                const float* bb = Bs + (wn * 32 + j * 8 + lr) * SSTRIDE + ks * 8 + lc;
                bfr[j][0] = __float_as_uint(bb[0]);
                bfr[j][1] = __float_as_uint(bb[4]);
            }
            #pragma unroll
            for (int i = 0; i < 4; i++)
                #pragma unroll
                for (int j = 0; j < 4; j++)
                    mma_tf32(acc[i][j], afr[i], bfr[j]);
        }
        __syncthreads();
    }

    // epilogue: direct global writes (float2 per fragment half)
    #pragma unroll
    for (int i = 0; i < 4; i++) {
        #pragma unroll
        for (int half = 0; half < 2; half++) {
            int m = m0 + wm * 64 + i * 16 + half * 8 + lr;
            float* crow = C + (long long)m * ldc;
            #pragma unroll
            for (int j = 0; j < 4; j++) {
                int n = n0 + wn * 32 + j * 8 + lc * 2;
                float v0 = acc[i][j][half * 2 + 0];
                float v1 = acc[i][j][half * 2 + 1];
                if (bias) { v0 += bias[n]; v1 += bias[n + 1]; }
                if (epi & 1) { v0 = fmaxf(v0, 0.0f); v1 = fmaxf(v1, 0.0f); }
                if (epi & 2) { v0 += crow[n]; v1 += crow[n + 1]; }
                if (epi & 4) { v0 = rna_tf32(v0); v1 = rna_tf32(v1); }
                *(float2*)(crow + n) = make_float2(v0, v1);
            }
        }
    }
}

// ---------------- causal softmax (rna output: feeds attn@V GEMM) ----------------
__global__ void softmax_causal_kernel(float* __restrict__ att) {
    int i = blockIdx.x;
    int z = blockIdx.y;
    float* row = att + (long long)z * TT * TT + (long long)i * TT;
    const float scale = 0.0883883476483184406f;   // 1/sqrt(128)
    int tid = threadIdx.x;
    __shared__ float red[128];

    float vloc[8];
    float m = -1e30f;
    #pragma unroll
    for (int c = 0; c < 8; c++) {
        int j = tid + c * 128;
        float s = (j <= i) ? row[j] * scale : -1e30f;
        vloc[c] = s;
        m = fmaxf(m, s);
    }
    red[tid] = m; __syncthreads();
    for (int k = 64; k > 0; k >>= 1) { if (tid < k) red[tid] = fmaxf(red[tid], red[tid + k]); __syncthreads(); }
    m = red[0]; __syncthreads();

    float sum = 0.0f;
    #pragma unroll
    for (int c = 0; c < 8; c++) {
        int j = tid + c * 128;
        float e = (j <= i) ? __expf(vloc[c] - m) : 0.0f;
        vloc[c] = e;
        sum += e;
    }
    red[tid] = sum; __syncthreads();
    for (int k = 64; k > 0; k >>= 1) { if (tid < k) red[tid] += red[tid + k]; __syncthreads(); }
    float inv = 1.0f / red[0];

    #pragma unroll
    for (int c = 0; c < 8; c++)
        row[tid + c * 128] = rna_tf32(vloc[c] * inv);
}

// ---------------- per-row NLL via streaming logsumexp ----------------
__global__ void loss_rows_kernel(const float* __restrict__ logits,
                                 const void* __restrict__ tgtv,
                                 float* __restrict__ nll) {
    int r = blockIdx.x;
    const float* row = logits + (long long)r * VV;
    int tid = threadIdx.x;
    float m = -1e30f, s = 0.0f;
    for (int j = tid; j < VV; j += 256) {
        float v = row[j];
        if (v > m) { s = s * __expf(m - v) + 1.0f; m = v; }
        else       { s += __expf(v - m); }
    }
    __shared__ float sm[256], ss[256];
    sm[tid] = m; ss[tid] = s; __syncthreads();
    for (int k = 128; k > 0; k >>= 1) {
        if (tid < k) {
            float m2 = sm[tid + k], s2 = ss[tid + k];
            float mm = fmaxf(sm[tid], m2);
            ss[tid] = ss[tid] * __expf(sm[tid] - mm) + s2 * __expf(m2 - mm);
            sm[tid] = mm;
        }
        __syncthreads();
    }
    if (tid == 0) {
        long long t = load_token(tgtv, r, g_is64_tgt);
        nll[r] = (sm[0] + logf(ss[0])) - row[t];
    }
}

__global__ void loss_final_kernel(const float* __restrict__ nll, float* __restrict__ out, int n) {
    __shared__ float red[256];
    int tid = threadIdx.x;
    float s = 0.0f;
    for (int j = tid; j < BT; j += 256) s += nll[j];
    red[tid] = s; __syncthreads();
    for (int k = 128; k > 0; k >>= 1) { if (tid < k) red[tid] += red[tid + k]; __syncthreads(); }
    float mean = red[0] * (1.0f / BT);
    for (int i = tid; i < n; i += 256) out[i] = mean;
}

// ---------------- host-side helpers ----------------
static void tcg(const float* A, int lda, long long aB, long long aH,
                const float* Bm, int ldb, long long bB, long long bH,
                float* C, int ldc, long long cB, long long cH,
                int M, int N, int K, int Hdiv, int Z,
                const float* bias, int epi, int causal, int kLimit) {
    dim3 grid(N / 128, M / 128, Z);
    tc_gemm<<<grid, 256, TC_SMEM>>>(A, lda, aB, aH, Bm, ldb, bB, bH, C, ldc, cB, cH,
                                    K, Hdiv, bias, epi, causal, kLimit);
}

static void tr(const float* s, float* d, int R, int C, int srs, int drs,
               long long sB, long long sH, long long dB, long long dH,
               int Hdiv, int Z) {
    dim3 grid(C / 32, R / 32, Z), blk(32, 8);
    transpose_kernel<<<grid, blk>>>(s, d, srs, drs, sB, sH, dB, dH, Hdiv);
}

extern "C" void kernel_launch(void* const* d_in, const int* in_sizes, int n_in,
                              void* d_out, int out_size) {
    const void*  idx  = d_in[0];
    const void*  tgt  = d_in[1];
    const float* tok  = (const float*)d_in[2];
    const float* pos  = (const float*)d_in[3];
    const float* Wq   = (const float*)d_in[4];
    const float* bq   = (const float*)d_in[5];
    const float* Wk   = (const float*)d_in[6];
    const float* bk   = (const float*)d_in[7];
    const float* Wv   = (const float*)d_in[8];
    const float* bv   = (const float*)d_in[9];
    const float* Wo   = (const float*)d_in[10];
    const float* bo   = (const float*)d_in[11];
    const float* w1   = (const float*)d_in[12];
    const float* b1   = (const float*)d_in[13];
    const float* w2   = (const float*)d_in[14];
    const float* b2   = (const float*)d_in[15];
    const float* ln1s = (const float*)d_in[16];
    const float* ln1b = (const float*)d_in[17];
    const float* ln2s = (const float*)d_in[18];
    const float* ln2b = (const float*)d_in[19];
    const float* lnfs = (const float*)d_in[20];
    const float* lnfb = (const float*)d_in[21];
    const float* Wlm  = (const float*)d_in[22];
    const float* blm  = (const float*)d_in[23];

    float *x, *h, *q, *k, *v, *o, *ff, *att, *nll, *logits_fb;
    float *wqT, *wkT, *wvT, *woT, *w1T, *w2T, *wlmT, *vT;
    cudaGetSymbolAddress((void**)&x,    g_x);
    cudaGetSymbolAddress((void**)&h,    g_h);
    cudaGetSymbolAddress((void**)&q,    g_q);
    cudaGetSymbolAddress((void**)&k,    g_k);
    cudaGetSymbolAddress((void**)&v,    g_v);
    cudaGetSymbolAddress((void**)&o,    g_o);
    cudaGetSymbolAddress((void**)&ff,   g_ff);
    cudaGetSymbolAddress((void**)&att,  g_att);
    cudaGetSymbolAddress((void**)&nll,  g_nll);
    cudaGetSymbolAddress((void**)&logits_fb, g_logits_fb);
    cudaGetSymbolAddress((void**)&wqT,  g_wqT);
    cudaGetSymbolAddress((void**)&wkT,  g_wkT);
    cudaGetSymbolAddress((void**)&wvT,  g_wvT);
    cudaGetSymbolAddress((void**)&woT,  g_woT);
    cudaGetSymbolAddress((void**)&w1T,  g_w1T);
    cudaGetSymbolAddress((void**)&w2T,  g_w2T);
    cudaGetSymbolAddress((void**)&wlmT, g_wlmT);
    cudaGetSymbolAddress((void**)&vT,   g_vT);

    cudaFuncSetAttribute(tc_gemm, cudaFuncAttributeMaxDynamicSharedMemorySize, TC_SMEM);

    float* out = (float*)d_out;
    float* logits = ((long long)out_size >= BTV) ? out : logits_fb;
    float* lossPtr = nullptr;
    int nLoss = 0;
    if ((long long)out_size > BTV) { lossPtr = out + BTV; nLoss = out_size - (int)BTV; }
    else if ((long long)out_size < BTV) { lossPtr = out; nLoss = out_size; }

    detect_kernel<<<1, 32>>>((const int*)idx, (const int*)tgt);
    embed_kernel<<<BT, 256>>>(idx, tok, pos, x);

    const long long E2 = (long long)EE * EE;
    const long long EF = (long long)EE * FF;
    // pre-transpose all weights to [N,K] (tf32-rounded)
    tr(Wq,  wqT,  EE, EE, EE, EE, E2, 0, E2, 0, 1, LL);
    tr(Wk,  wkT,  EE, EE, EE, EE, E2, 0, E2, 0, 1, LL);
    tr(Wv,  wvT,  EE, EE, EE, EE, E2, 0, E2, 0, 1, LL);
    tr(Wo,  woT,  EE, EE, EE, EE, E2, 0, E2, 0, 1, LL);
    tr(w1,  w1T,  EE, FF, FF, EE, EF, 0, EF, 0, 1, LL);
    tr(w2,  w2T,  FF, EE, EE, FF, EF, 0, EF, 0, 1, LL);
    tr(Wlm, wlmT, EE, VV, VV, EE, 0, 0, 0, 0, 1, 1);

    const long long ZTE  = (long long)TT * EE;      // per-batch stride in q/k/v/o
    const long long ZATT = (long long)TT * TT;      // per-head stride in att
    const long long ZVT  = (long long)HD * TT;      // per-head stride in vT

    for (int l = 0; l < LL; l++) {
        // h = rna(LN1(x))
        layernorm_kernel<<<BT, 256>>>(x, h, ln1s + l * EE, ln1b + l * EE);

        // q,k,v = rna(h @ W + b)
        tcg(h, EE, 0, 0, wqT + l * E2, EE, 0, 0, q, EE, 0, 0,
            BT, EE, EE, 1, 1, bq + l * EE, 4, 0, 0);
        tcg(h, EE, 0, 0, wkT + l * E2, EE, 0, 0, k, EE, 0, 0,
            BT, EE, EE, 1, 1, bk + l * EE, 4, 0, 0);
        tcg(h, EE, 0, 0, wvT + l * E2, EE, 0, 0, v, EE, 0, 0,
            BT, EE, EE, 1, 1, bv + l * EE, 4, 0, 0);

        // vT[b,h,d,t] = rna(v[b,t,h,d])
        tr(v, vT, TT, HD, EE, TT, ZTE, HD, (long long)HH * ZVT, ZVT, HH, BB * HH);

        // scores = q @ k^T (causal blocks skipped)
        tcg(q, EE, ZTE, HD, k, EE, ZTE, HD,
            att, TT, (long long)HH * ZATT, ZATT,
            TT, TT, HD, HH, BB * HH, nullptr, 0, 1, 0);

        softmax_causal_kernel<<<dim3(TT, BB * HH), 128>>>(att);

        // o = rna(att @ v)   (K limited to causal extent of the row block)
        tcg(att, TT, (long long)HH * ZATT, ZATT, vT, TT, (long long)HH * ZVT, ZVT,
            o, EE, ZTE, HD,
            TT, HD, TT, HH, BB * HH, nullptr, 4, 0, 1);

        // x += o @ Wo + bo
        tcg(o, EE, 0, 0, woT + l * E2, EE, 0, 0, x, EE, 0, 0,
            BT, EE, EE, 1, 1, bo + l * EE, 2, 0, 0);

        // h = rna(LN2(x))
        layernorm_kernel<<<BT, 256>>>(x, h, ln2s + l * EE, ln2b + l * EE);

        // ff = rna(relu(h @ w1 + b1));  x += ff @ w2 + b2
        tcg(h, EE, 0, 0, w1T + l * EF, EE, 0, 0, ff, FF, 0, 0,
            BT, FF, EE, 1, 1, b1 + (long long)l * FF, 5, 0, 0);
        tcg(ff, FF, 0, 0, w2T + l * EF, FF, 0, 0, x, EE, 0, 0,
            BT, EE, FF, 1, 1, b2 + l * EE, 2, 0, 0);
    }

    // final LN + LM head
    layernorm_kernel<<<BT, 256>>>(x, h, lnfs, lnfb);
    tcg(h, EE, 0, 0, wlmT, EE, 0, 0, logits, VV, 0, 0,
        BT, VV, EE, 1, 1, blm, 0, 0, 0);

    // loss
    loss_rows_kernel<<<BT, 256>>>(logits, tgt, nll);
    if (nLoss > 0)
        loss_final_kernel<<<1, 256>>>(nll, lossPtr, nLoss);
}

// round 4
// speedup vs baseline: 3.4816x; 1.1110x over previous
#include <cuda_runtime.h>
#include <cuda_bf16.h>
#include <math.h>
#include <stdint.h>

// ---------------- problem constants ----------------
#define BB 4
#define TT 1024
#define EE 768
#define LL 6
#define HH 6
#define HD 128
#define VV 32000
#define FF (4*EE)          // 3072
#define BT (BB*TT)         // 4096
#define BTV ((long long)BT*VV)
#define QKV3 (3*EE)        // 2304

// ---------------- scratch (device globals; no allocations allowed) ----------------
__device__ float g_x [BT*EE];
__device__ float g_h [BT*EE];
__device__ float g_qkv[(long long)BT*QKV3];
__device__ float g_o [BT*EE];
__device__ float g_ff[BT*FF];
__device__ float g_nll[BT];
__device__ float g_logits_fb[BTV];
__device__ int   g_is64_idx;
__device__ int   g_is64_tgt;
// transposed (K-major [N,K]) operands, all pre-rounded to tf32 (rna)
__device__ float g_wqkvT[(long long)LL*QKV3*EE];
__device__ float g_bqkv [LL*QKV3];
__device__ float g_woT [LL*EE*EE];
__device__ float g_w1T [(long long)LL*EE*FF];
__device__ float g_w2T [(long long)LL*EE*FF];
__device__ float g_wlmT[(long long)EE*VV];
__device__ float g_vT  [(long long)BB*HH*HD*TT];

// ---------------- small helpers ----------------
__device__ __forceinline__ uint32_t smem_u32(const void* p) {
    uint32_t a;
    asm("{ .reg .u64 t; cvta.to.shared.u64 t, %1; cvt.u32.u64 %0, t; }" : "=r"(a) : "l"(p));
    return a;
}

__device__ __forceinline__ float rna_tf32(float x) {
    uint32_t u;
    asm("cvt.rna.tf32.f32 %0, %1;" : "=r"(u) : "f"(x));
    return __uint_as_float(u);
}

__device__ __forceinline__ void cp_async16(uint32_t saddr, const void* gaddr) {
    asm volatile("cp.async.cg.shared.global [%0], [%1], 16;" :: "r"(saddr), "l"(gaddr));
}

// tf32 mma.sync: D(16x8) += A(16x8) * B(8x8), row.col
__device__ __forceinline__ void mma_tf32(float* c, const uint32_t* a, const uint32_t* b) {
    asm volatile(
        "mma.sync.aligned.m16n8k8.row.col.f32.tf32.tf32.f32 "
        "{%0,%1,%2,%3}, {%4,%5,%6,%7}, {%8,%9}, {%0,%1,%2,%3};"
        : "+f"(c[0]), "+f"(c[1]), "+f"(c[2]), "+f"(c[3])
        : "r"(a[0]), "r"(a[1]), "r"(a[2]), "r"(a[3]), "r"(b[0]), "r"(b[1]));
}

// ---------------- int64-vs-int32 detection ----------------
__global__ void detect_kernel(const int* __restrict__ idx, const int* __restrict__ tgt) {
    if (threadIdx.x == 0 && blockIdx.x == 0) {
        int a = 1, b = 1;
        for (int i = 1; i < 129; i += 2) {
            if (idx[i] != 0) a = 0;
            if (tgt[i] != 0) b = 0;
        }
        g_is64_idx = a;
        g_is64_tgt = b;
    }
}

__device__ __forceinline__ long long load_token(const void* p, int r, int is64) {
    if (is64) return ((const long long*)p)[r];
    return (long long)((const int*)p)[r];
}

// ---------------- embedding ----------------
__global__ void embed_kernel(const void* __restrict__ idxv,
                             const float* __restrict__ tok,
                             const float* __restrict__ pos,
                             float* __restrict__ x) {
    int r = blockIdx.x;
    long long token = load_token(idxv, r, g_is64_idx);
    int t = r % TT;
    const float* te = tok + token * EE;
    const float* pe = pos + (long long)t * EE;
    float* xr = x + (long long)r * EE;
    for (int e = threadIdx.x; e < EE; e += blockDim.x)
        xr[e] = te[e] + pe[e];
}

// ---------------- layernorm (rna output: always feeds a GEMM) ----------------
__global__ void layernorm_kernel(const float* __restrict__ x, float* __restrict__ y,
                                 const float* __restrict__ s, const float* __restrict__ b) {
    int r = blockIdx.x;
    const float* row = x + (long long)r * EE;
    float* out = y + (long long)r * EE;
    int tid = threadIdx.x;
    __shared__ float red[256];

    float v0 = row[tid], v1 = row[tid + 256], v2 = row[tid + 512];
    red[tid] = v0 + v1 + v2; __syncthreads();
    for (int k = 128; k > 0; k >>= 1) { if (tid < k) red[tid] += red[tid + k]; __syncthreads(); }
    float mean = red[0] * (1.0f / EE);
    __syncthreads();

    float d0 = v0 - mean, d1 = v1 - mean, d2 = v2 - mean;
    red[tid] = d0*d0 + d1*d1 + d2*d2; __syncthreads();
    for (int k = 128; k > 0; k >>= 1) { if (tid < k) red[tid] += red[tid + k]; __syncthreads(); }
    float inv = rsqrtf(red[0] * (1.0f / EE) + 1e-5f);

    out[tid      ] = rna_tf32(d0 * inv * s[tid      ] + b[tid      ]);
    out[tid + 256] = rna_tf32(d1 * inv * s[tid + 256] + b[tid + 256]);
    out[tid + 512] = rna_tf32(d2 * inv * s[tid + 512] + b[tid + 512]);
}

// ---------------- generic batched transpose (rna output) ----------------
__global__ void transpose_kernel(const float* __restrict__ src, float* __restrict__ dst,
                                 int srs, int drs,
                                 long long sB, long long sH, long long dB, long long dH,
                                 int Hdiv) {
    int z = blockIdx.z, zb = z / Hdiv, zh = z - zb * Hdiv;
    src += zb * sB + zh * sH;
    dst += zb * dB + zh * dH;
    __shared__ float tile[32][33];
    int c0 = blockIdx.x * 32, r0 = blockIdx.y * 32;
    int tx = threadIdx.x, ty = threadIdx.y;   // 32 x 8
    #pragma unroll
    for (int i = 0; i < 32; i += 8)
        tile[ty + i][tx] = src[(long long)(r0 + ty + i) * srs + c0 + tx];
    __syncthreads();
    #pragma unroll
    for (int i = 0; i < 32; i += 8)
        dst[(long long)(c0 + ty + i) * drs + r0 + tx] = rna_tf32(tile[tx][ty + i]);
}

// ---------------- bias concat for merged QKV ----------------
__global__ void concat_bias_kernel(const float* __restrict__ bq, const float* __restrict__ bk,
                                   const float* __restrict__ bv, float* __restrict__ bqkv) {
    int l = blockIdx.y;
    int n = blockIdx.x * 256 + threadIdx.x;
    if (n < QKV3) {
        float v;
        if (n < EE)            v = bq[l * EE + n];
        else if (n < 2 * EE)   v = bk[l * EE + n - EE];
        else                   v = bv[l * EE + n - 2 * EE];
        bqkv[l * QKV3 + n] = v;
    }
}

// ---------------- tf32 mma.sync GEMM ----------------
// C[m,n] = sum_k A[m,k] * B[n,k]   (A [M,K] K-major, B [N,K] K-major)
// M,N multiples of 128; K multiple of 32.
// epi bits: 1=relu, 2=residual-add, 4=rna output. bias applied if non-null.
#define NST 3
#define SSTRIDE 36
#define STAGE_F (2*128*SSTRIDE)
#define TC_SMEM (NST*STAGE_F*4)          // 110592 bytes

__device__ __forceinline__ void load_chunk(const float* __restrict__ A, int lda,
                                           const float* __restrict__ Bm, int ldb,
                                           uint32_t sA, uint32_t sB,
                                           int m0, int n0, int k0, int tid) {
    #pragma unroll
    for (int t = 0; t < 4; t++) {
        int seg = tid + t * 256;
        int row = seg >> 3, kq = seg & 7;
        cp_async16(sA + (uint32_t)(row * (SSTRIDE*4) + kq * 16),
                   A + (long long)(m0 + row) * lda + k0 + kq * 4);
    }
    #pragma unroll
    for (int t = 0; t < 4; t++) {
        int seg = tid + t * 256;
        int row = seg >> 3, kq = seg & 7;
        cp_async16(sB + (uint32_t)(row * (SSTRIDE*4) + kq * 16),
                   Bm + (long long)(n0 + row) * ldb + k0 + kq * 4);
    }
}

__global__ void __launch_bounds__(256, 2)
tc_gemm(const float* __restrict__ A, int lda, long long aOffB, long long aOffH,
        const float* __restrict__ Bm, int ldb, long long bOffB, long long bOffH,
        float* __restrict__ C, int ldc, long long cOffB, long long cOffH,
        int K, int Hdiv, const float* __restrict__ bias, int epi) {
    int m0 = blockIdx.y * 128, n0 = blockIdx.x * 128;

    int z = blockIdx.z, zb = z / Hdiv, zh = z - zb * Hdiv;
    A  += zb * aOffB + zh * aOffH;
    Bm += zb * bOffB + zh * bOffH;
    C  += zb * cOffB + zh * cOffH;

    int nchunks = K >> 5;

    extern __shared__ float sm[];
    uint32_t sb = smem_u32(sm);
    int tid = threadIdx.x, wid = tid >> 5, lane = tid & 31;
    int wm = wid & 1, wn = wid >> 1;       // 2 x 4 warp grid; warp tile 64x32
    int lr = lane >> 2, lc = lane & 3;

    float acc[4][4][4];
    #pragma unroll
    for (int i = 0; i < 4; i++)
        #pragma unroll
        for (int j = 0; j < 4; j++)
            #pragma unroll
            for (int e = 0; e < 4; e++) acc[i][j][e] = 0.0f;

    #pragma unroll
    for (int s = 0; s < NST - 1; s++) {
        if (s < nchunks)
            load_chunk(A, lda, Bm, ldb, sb + s * (STAGE_F*4), sb + s * (STAGE_F*4) + 128*SSTRIDE*4,
                       m0, n0, s * 32, tid);
        asm volatile("cp.async.commit_group;" ::: "memory");
    }

    for (int c = 0; c < nchunks; c++) {
        asm volatile("cp.async.wait_group %0;" :: "n"(NST - 2) : "memory");
        __syncthreads();

        int cn = c + NST - 1;
        if (cn < nchunks) {
            int sn = cn % NST;
            load_chunk(A, lda, Bm, ldb, sb + sn * (STAGE_F*4), sb + sn * (STAGE_F*4) + 128*SSTRIDE*4,
                       m0, n0, cn * 32, tid);
        }
        asm volatile("cp.async.commit_group;" ::: "memory");

        const float* As = sm + (c % NST) * STAGE_F;
        const float* Bs = As + 128 * SSTRIDE;

        #pragma unroll
        for (int ks = 0; ks < 4; ks++) {
            uint32_t afr[4][4], bfr[4][2];
            #pragma unroll
            for (int i = 0; i < 4; i++) {
                const float* ab = As + (wm * 64 + i * 16 + lr) * SSTRIDE + ks * 8 + lc;
                afr[i][0] = __float_as_uint(ab[0]);
                afr[i][1] = __float_as_uint(ab[8 * SSTRIDE]);
                afr[i][2] = __float_as_uint(ab[4]);
                afr[i][3] = __float_as_uint(ab[8 * SSTRIDE + 4]);
            }
            #pragma unroll
            for (int j = 0; j < 4; j++) {
                const float* bb = Bs + (wn * 32 + j * 8 + lr) * SSTRIDE + ks * 8 + lc;
                bfr[j][0] = __float_as_uint(bb[0]);
                bfr[j][1] = __float_as_uint(bb[4]);
            }
            #pragma unroll
            for (int i = 0; i < 4; i++)
                #pragma unroll
                for (int j = 0; j < 4; j++)
                    mma_tf32(acc[i][j], afr[i], bfr[j]);
        }
        __syncthreads();
    }

    #pragma unroll
    for (int i = 0; i < 4; i++) {
        #pragma unroll
        for (int half = 0; half < 2; half++) {
            int m = m0 + wm * 64 + i * 16 + half * 8 + lr;
            float* crow = C + (long long)m * ldc;
            #pragma unroll
            for (int j = 0; j < 4; j++) {
                int n = n0 + wn * 32 + j * 8 + lc * 2;
                float v0 = acc[i][j][half * 2 + 0];
                float v1 = acc[i][j][half * 2 + 1];
                if (bias) { v0 += bias[n]; v1 += bias[n + 1]; }
                if (epi & 1) { v0 = fmaxf(v0, 0.0f); v1 = fmaxf(v1, 0.0f); }
                if (epi & 2) { v0 += crow[n]; v1 += crow[n + 1]; }
                if (epi & 4) { v0 = rna_tf32(v0); v1 = rna_tf32(v1); }
                *(float2*)(crow + n) = make_float2(v0, v1);
            }
        }
    }
}

// ---------------- fused flash attention ----------------
// One CTA per (m-block i, z=(b,h)). Q tile resident in smem; stream K_j/V_j.
// S = Q K^T (tf32 MMA), online softmax (stats via smem), P -> smem (K buffer),
// O += P V (tf32 MMA). vT supplies V as [d][t] K-major B operand.
#define FSTR 132
#define FQ_OFF 0
#define FK_OFF (128*FSTR)
#define FV_OFF (2*128*FSTR)
#define FRED_OFF (3*128*FSTR)            // sred[128][4]
#define FM_OFF  (FRED_OFF + 512)         // m_s[128]
#define FL_OFF  (FM_OFF + 128)           // l_s[128]
#define FC_OFF  (FL_OFF + 128)           // corr_s[128]
#define FLASH_SMEM ((FC_OFF + 128)*4)    // 206336 bytes

__device__ __forceinline__ void load_tile128(uint32_t sdst, const float* __restrict__ g,
                                             int ldg, int tid) {
    #pragma unroll
    for (int t = 0; t < 16; t++) {
        int seg = tid + t * 256;         // 0..4095
        int row = seg >> 5, kq = seg & 31;
        cp_async16(sdst + (uint32_t)(row * (FSTR*4) + kq * 16),
                   g + (long long)row * ldg + kq * 4);
    }
}

__global__ void __launch_bounds__(256, 1)
flash_kernel(const float* __restrict__ qkv, const float* __restrict__ vT,
             float* __restrict__ o) {
    int i = 7 - blockIdx.x;              // heavy blocks first
    int z = blockIdx.y;
    int b = z / HH, h = z - b * HH;

    extern __shared__ float fs[];
    uint32_t sb = smem_u32(fs);
    int tid = threadIdx.x, wid = tid >> 5, lane = tid & 31;
    int wm = wid & 1, wn = wid >> 1;
    int lr = lane >> 2, lc = lane & 3;

    const float* qg = qkv + ((long long)(b * TT + i * 128)) * QKV3 + h * HD;
    const float* kg = qkv + ((long long)(b * TT)) * QKV3 + EE + h * HD;
    const float* vg = vT + (long long)z * HD * TT;

    load_tile128(sb + FQ_OFF*4, qg, QKV3, tid);
    asm volatile("cp.async.commit_group;" ::: "memory");

    if (tid < 128) { fs[FM_OFF + tid] = -1e30f; fs[FL_OFF + tid] = 0.0f; }

    float oacc[4][4][4];
    #pragma unroll
    for (int a = 0; a < 4; a++)
        #pragma unroll
        for (int j = 0; j < 4; j++)
            #pragma unroll
            for (int e = 0; e < 4; e++) oacc[a][j][e] = 0.0f;

    const float scale = 0.0883883476483184406f;   // 1/sqrt(128)

    for (int j = 0; j <= i; j++) {
        load_tile128(sb + FK_OFF*4, kg + (long long)(j * 128) * QKV3, QKV3, tid);
        asm volatile("cp.async.commit_group;" ::: "memory");
        load_tile128(sb + FV_OFF*4, vg + j * 128, TT, tid);
        asm volatile("cp.async.commit_group;" ::: "memory");
        asm volatile("cp.async.wait_group 1;" ::: "memory");   // Q + K done
        __syncthreads();

        // ---- S = Q K^T ----
        float sacc[4][4][4];
        #pragma unroll
        for (int a = 0; a < 4; a++)
            #pragma unroll
            for (int jt = 0; jt < 4; jt++)
                #pragma unroll
                for (int e = 0; e < 4; e++) sacc[a][jt][e] = 0.0f;

        const float* Qs = fs + FQ_OFF;
        const float* Ks = fs + FK_OFF;
        #pragma unroll
        for (int kk = 0; kk < 16; kk++) {
            uint32_t afr[4][4], bfr[4][2];
            #pragma unroll
            for (int a = 0; a < 4; a++) {
                const float* ab = Qs + (wm * 64 + a * 16 + lr) * FSTR + kk * 8 + lc;
                afr[a][0] = __float_as_uint(ab[0]);
                afr[a][1] = __float_as_uint(ab[8 * FSTR]);
                afr[a][2] = __float_as_uint(ab[4]);
                afr[a][3] = __float_as_uint(ab[8 * FSTR + 4]);
            }
            #pragma unroll
            for (int jt = 0; jt < 4; jt++) {
                const float* bb = Ks + (wn * 32 + jt * 8 + lr) * FSTR + kk * 8 + lc;
                bfr[jt][0] = __float_as_uint(bb[0]);
                bfr[jt][1] = __float_as_uint(bb[4]);
            }
            #pragma unroll
            for (int a = 0; a < 4; a++)
                #pragma unroll
                for (int jt = 0; jt < 4; jt++)
                    mma_tf32(sacc[a][jt], afr[a], bfr[jt]);
        }

        // ---- scale + causal mask + row max ----
        float pmax[4][2];
        #pragma unroll
        for (int a = 0; a < 4; a++) { pmax[a][0] = -1e30f; pmax[a][1] = -1e30f; }
        #pragma unroll
        for (int a = 0; a < 4; a++)
            #pragma unroll
            for (int jt = 0; jt < 4; jt++)
                #pragma unroll
                for (int e = 0; e < 4; e++) {
                    int half = e >> 1;
                    float sv = sacc[a][jt][e] * scale;
                    if (j == i) {
                        int mr = wm * 64 + a * 16 + half * 8 + lr;
                        int nc = wn * 32 + jt * 8 + 2 * lc + (e & 1);
                        if (nc > mr) sv = -1e30f;
                    }
                    sacc[a][jt][e] = sv;
                    pmax[a][half] = fmaxf(pmax[a][half], sv);
                }
        #pragma unroll
        for (int a = 0; a < 4; a++)
            #pragma unroll
            for (int half = 0; half < 2; half++) {
                float v = pmax[a][half];
                v = fmaxf(v, __shfl_xor_sync(0xFFFFFFFF, v, 1));
                v = fmaxf(v, __shfl_xor_sync(0xFFFFFFFF, v, 2));
                pmax[a][half] = v;
            }
        if (lc == 0) {
            #pragma unroll
            for (int a = 0; a < 4; a++)
                #pragma unroll
                for (int half = 0; half < 2; half++)
                    fs[FRED_OFF + (wm * 64 + a * 16 + half * 8 + lr) * 4 + wn] = pmax[a][half];
        }
        __syncthreads();

        if (wn == 0 && lc == 0) {
            #pragma unroll
            for (int a = 0; a < 4; a++)
                #pragma unroll
                for (int half = 0; half < 2; half++) {
                    int r = wm * 64 + a * 16 + half * 8 + lr;
                    float m4 = fmaxf(fmaxf(fs[FRED_OFF + r*4], fs[FRED_OFF + r*4 + 1]),
                                     fmaxf(fs[FRED_OFF + r*4 + 2], fs[FRED_OFF + r*4 + 3]));
                    float mold = fs[FM_OFF + r];
                    float mnew = fmaxf(mold, m4);
                    fs[FC_OFF + r] = __expf(mold - mnew);
                    fs[FM_OFF + r] = mnew;
                }
        }
        __syncthreads();

        // ---- P = exp(S - m); rescale O; store P to K buffer; row sums ----
        float mn[4][2], cr[4][2], psum[4][2];
        #pragma unroll
        for (int a = 0; a < 4; a++)
            #pragma unroll
            for (int half = 0; half < 2; half++) {
                int r = wm * 64 + a * 16 + half * 8 + lr;
                mn[a][half] = fs[FM_OFF + r];
                cr[a][half] = fs[FC_OFF + r];
                psum[a][half] = 0.0f;
            }
        float* Ps = fs + FK_OFF;
        #pragma unroll
        for (int a = 0; a < 4; a++)
            #pragma unroll
            for (int jt = 0; jt < 4; jt++) {
                #pragma unroll
                for (int half = 0; half < 2; half++) {
                    float p0 = __expf(sacc[a][jt][half*2 + 0] - mn[a][half]);
                    float p1 = __expf(sacc[a][jt][half*2 + 1] - mn[a][half]);
                    psum[a][half] += p0 + p1;
                    oacc[a][jt][half*2 + 0] *= cr[a][half];
                    oacc[a][jt][half*2 + 1] *= cr[a][half];
                    int r = wm * 64 + a * 16 + half * 8 + lr;
                    int nc = wn * 32 + jt * 8 + 2 * lc;
                    *(float2*)(Ps + r * FSTR + nc) = make_float2(rna_tf32(p0), rna_tf32(p1));
                }
            }
        #pragma unroll
        for (int a = 0; a < 4; a++)
            #pragma unroll
            for (int half = 0; half < 2; half++) {
                float v = psum[a][half];
                v += __shfl_xor_sync(0xFFFFFFFF, v, 1);
                v += __shfl_xor_sync(0xFFFFFFFF, v, 2);
                psum[a][half] = v;
            }
        if (lc == 0) {
            #pragma unroll
            for (int a = 0; a < 4; a++)
                #pragma unroll
                for (int half = 0; half < 2; half++)
                    fs[FRED_OFF + (wm * 64 + a * 16 + half * 8 + lr) * 4 + wn] = psum[a][half];
        }
        asm volatile("cp.async.wait_group 0;" ::: "memory");   // V ready
        __syncthreads();

        if (wn == 0 && lc == 0) {
            #pragma unroll
            for (int a = 0; a < 4; a++)
                #pragma unroll
                for (int half = 0; half < 2; half++) {
                    int r = wm * 64 + a * 16 + half * 8 + lr;
                    float s4 = fs[FRED_OFF + r*4] + fs[FRED_OFF + r*4 + 1]
                             + fs[FRED_OFF + r*4 + 2] + fs[FRED_OFF + r*4 + 3];
                    fs[FL_OFF + r] = fs[FL_OFF + r] * fs[FC_OFF + r] + s4;
                }
        }

        // ---- O += P V ----
        const float* Vs = fs + FV_OFF;
        #pragma unroll
        for (int kk = 0; kk < 16; kk++) {
            uint32_t afr[4][4], bfr[4][2];
            #pragma unroll
            for (int a = 0; a < 4; a++) {
                const float* ab = Ps + (wm * 64 + a * 16 + lr) * FSTR + kk * 8 + lc;
                afr[a][0] = __float_as_uint(ab[0]);
                afr[a][1] = __float_as_uint(ab[8 * FSTR]);
                afr[a][2] = __float_as_uint(ab[4]);
                afr[a][3] = __float_as_uint(ab[8 * FSTR + 4]);
            }
            #pragma unroll
            for (int jt = 0; jt < 4; jt++) {
                const float* bb = Vs + (wn * 32 + jt * 8 + lr) * FSTR + kk * 8 + lc;
                bfr[jt][0] = __float_as_uint(bb[0]);
                bfr[jt][1] = __float_as_uint(bb[4]);
            }
            #pragma unroll
            for (int a = 0; a < 4; a++)
                #pragma unroll
                for (int jt = 0; jt < 4; jt++)
                    mma_tf32(oacc[a][jt], afr[a], bfr[jt]);
        }
        __syncthreads();   // protect Ks/Vs before next iteration's loads
    }

    // ---- epilogue: O / l, rna, store ----
    float* og = o + ((long long)(b * TT + i * 128)) * EE + h * HD;
    #pragma unroll
    for (int a = 0; a < 4; a++)
        #pragma unroll
        for (int half = 0; half < 2; half++) {
            int r = wm * 64 + a * 16 + half * 8 + lr;
            float linv = 1.0f / fs[FL_OFF + r];
            float* orow = og + (long long)r * EE;
            #pragma unroll
            for (int jt = 0; jt < 4; jt++) {
                int nc = wn * 32 + jt * 8 + 2 * lc;
                float v0 = rna_tf32(oacc[a][jt][half*2 + 0] * linv);
                float v1 = rna_tf32(oacc[a][jt][half*2 + 1] * linv);
                *(float2*)(orow + nc) = make_float2(v0, v1);
            }
        }
}

// ---------------- per-row NLL via streaming logsumexp ----------------
__global__ void loss_rows_kernel(const float* __restrict__ logits,
                                 const void* __restrict__ tgtv,
                                 float* __restrict__ nll) {
    int r = blockIdx.x;
    const float* row = logits + (long long)r * VV;
    int tid = threadIdx.x;
    float m = -1e30f, s = 0.0f;
    for (int j = tid; j < VV; j += 256) {
        float v = row[j];
        if (v > m) { s = s * __expf(m - v) + 1.0f; m = v; }
        else       { s += __expf(v - m); }
    }
    __shared__ float sm[256], ss[256];
    sm[tid] = m; ss[tid] = s; __syncthreads();
    for (int k = 128; k > 0; k >>= 1) {
        if (tid < k) {
            float m2 = sm[tid + k], s2 = ss[tid + k];
            float mm = fmaxf(sm[tid], m2);
            ss[tid] = ss[tid] * __expf(sm[tid] - mm) + s2 * __expf(m2 - mm);
            sm[tid] = mm;
        }
        __syncthreads();
    }
    if (tid == 0) {
        long long t = load_token(tgtv, r, g_is64_tgt);
        nll[r] = (sm[0] + logf(ss[0])) - row[t];
    }
}

__global__ void loss_final_kernel(const float* __restrict__ nll, float* __restrict__ out, int n) {
    __shared__ float red[256];
    int tid = threadIdx.x;
    float s = 0.0f;
    for (int j = tid; j < BT; j += 256) s += nll[j];
    red[tid] = s; __syncthreads();
    for (int k = 128; k > 0; k >>= 1) { if (tid < k) red[tid] += red[tid + k]; __syncthreads(); }
    float mean = red[0] * (1.0f / BT);
    for (int i = tid; i < n; i += 256) out[i] = mean;
}

// ---------------- host-side helpers ----------------
static void tcg(const float* A, int lda, const float* Bm, int ldb,
                float* C, int ldc, int M, int N, int K,
                const float* bias, int epi) {
    dim3 grid(N / 128, M / 128, 1);
    tc_gemm<<<grid, 256, TC_SMEM>>>(A, lda, 0, 0, Bm, ldb, 0, 0, C, ldc, 0, 0,
                                    K, 1, bias, epi);
}

static void tr(const float* s, float* d, int R, int C, int srs, int drs,
               long long sB, long long sH, long long dB, long long dH,
               int Hdiv, int Z) {
    dim3 grid(C / 32, R / 32, Z), blk(32, 8);
    transpose_kernel<<<grid, blk>>>(s, d, srs, drs, sB, sH, dB, dH, Hdiv);
}

extern "C" void kernel_launch(void* const* d_in, const int* in_sizes, int n_in,
                              void* d_out, int out_size) {
    const void*  idx  = d_in[0];
    const void*  tgt  = d_in[1];
    const float* tok  = (const float*)d_in[2];
    const float* pos  = (const float*)d_in[3];
    const float* Wq   = (const float*)d_in[4];
    const float* bq   = (const float*)d_in[5];
    const float* Wk   = (const float*)d_in[6];
    const float* bk   = (const float*)d_in[7];
    const float* Wv   = (const float*)d_in[8];
    const float* bv   = (const float*)d_in[9];
    const float* Wo   = (const float*)d_in[10];
    const float* bo   = (const float*)d_in[11];
    const float* w1   = (const float*)d_in[12];
    const float* b1   = (const float*)d_in[13];
    const float* w2   = (const float*)d_in[14];
    const float* b2   = (const float*)d_in[15];
    const float* ln1s = (const float*)d_in[16];
    const float* ln1b = (const float*)d_in[17];
    const float* ln2s = (const float*)d_in[18];
    const float* ln2b = (const float*)d_in[19];
    const float* lnfs = (const float*)d_in[20];
    const float* lnfb = (const float*)d_in[21];
    const float* Wlm  = (const float*)d_in[22];
    const float* blm  = (const float*)d_in[23];

    float *x, *h, *qkv, *o, *ff, *nll, *logits_fb;
    float *wqkvT, *bqkv, *woT, *w1T, *w2T, *wlmT, *vT;
    cudaGetSymbolAddress((void**)&x,    g_x);
    cudaGetSymbolAddress((void**)&h,    g_h);
    cudaGetSymbolAddress((void**)&qkv,  g_qkv);
    cudaGetSymbolAddress((void**)&o,    g_o);
    cudaGetSymbolAddress((void**)&ff,   g_ff);
    cudaGetSymbolAddress((void**)&nll,  g_nll);
    cudaGetSymbolAddress((void**)&logits_fb, g_logits_fb);
    cudaGetSymbolAddress((void**)&wqkvT, g_wqkvT);
    cudaGetSymbolAddress((void**)&bqkv,  g_bqkv);
    cudaGetSymbolAddress((void**)&woT,  g_woT);
    cudaGetSymbolAddress((void**)&w1T,  g_w1T);
    cudaGetSymbolAddress((void**)&w2T,  g_w2T);
    cudaGetSymbolAddress((void**)&wlmT, g_wlmT);
    cudaGetSymbolAddress((void**)&vT,   g_vT);

    cudaFuncSetAttribute(tc_gemm, cudaFuncAttributeMaxDynamicSharedMemorySize, TC_SMEM);
    cudaFuncSetAttribute(flash_kernel, cudaFuncAttributeMaxDynamicSharedMemorySize, FLASH_SMEM);

    float* out = (float*)d_out;
    float* logits = ((long long)out_size >= BTV) ? out : logits_fb;
    float* lossPtr = nullptr;
    int nLoss = 0;
    if ((long long)out_size > BTV) { lossPtr = out + BTV; nLoss = out_size - (int)BTV; }
    else if ((long long)out_size < BTV) { lossPtr = out; nLoss = out_size; }

    detect_kernel<<<1, 32>>>((const int*)idx, (const int*)tgt);
    embed_kernel<<<BT, 256>>>(idx, tok, pos, x);

    const long long E2   = (long long)EE * EE;
    const long long EF   = (long long)EE * FF;
    const long long LQ3  = (long long)QKV3 * EE;   // per-layer wqkvT stride
    // merged QKV weight transpose: wqkvT[l][n=0..2303][k=0..767]
    tr(Wq, wqkvT,             EE, EE, EE, EE, E2, 0, LQ3, 0, 1, LL);
    tr(Wk, wqkvT + EE*EE,     EE, EE, EE, EE, E2, 0, LQ3, 0, 1, LL);
    tr(Wv, wqkvT + 2*EE*EE,   EE, EE, EE, EE, E2, 0, LQ3, 0, 1, LL);
    concat_bias_kernel<<<dim3(9, LL), 256>>>(bq, bk, bv, bqkv);
    tr(Wo,  woT,  EE, EE, EE, EE, E2, 0, E2, 0, 1, LL);
    tr(w1,  w1T,  EE, FF, FF, EE, EF, 0, EF, 0, 1, LL);
    tr(w2,  w2T,  FF, EE, EE, FF, EF, 0, EF, 0, 1, LL);
    tr(Wlm, wlmT, EE, VV, VV, EE, 0, 0, 0, 0, 1, 1);

    const long long ZVT = (long long)HD * TT;   // per-head stride in vT

    for (int l = 0; l < LL; l++) {
        // h = rna(LN1(x))
        layernorm_kernel<<<BT, 256>>>(x, h, ln1s + l * EE, ln1b + l * EE);

        // qkv = rna(h @ Wqkv + bqkv)   [BT x 2304]
        tcg(h, EE, wqkvT + l * LQ3, EE, qkv, QKV3, BT, QKV3, EE,
            bqkv + l * QKV3, 4);

        // vT[b,h,d,t] = rna(v[b,t,h,d])  (v = qkv cols 1536..2303)
        tr(qkv + 2 * EE, vT, TT, HD, QKV3, TT,
           (long long)TT * QKV3, HD, (long long)HH * ZVT, ZVT, HH, BB * HH);

        // fused attention -> o (rna'd)
        flash_kernel<<<dim3(8, BB * HH), 256, FLASH_SMEM>>>(qkv, vT, o);

        // x += o @ Wo + bo
        tcg(o, EE, woT + l * E2, EE, x, EE, BT, EE, EE, bo + l * EE, 2);

        // h = rna(LN2(x))
        layernorm_kernel<<<BT, 256>>>(x, h, ln2s + l * EE, ln2b + l * EE);

        // ff = rna(relu(h @ w1 + b1));  x += ff @ w2 + b2
        tcg(h, EE, w1T + l * EF, EE, ff, FF, BT, FF, EE, b1 + (long long)l * FF, 5);
        tcg(ff, FF, w2T + l * EF, FF, x, EE, BT, EE, FF, b2 + l * EE, 2);
    }

    // final LN + LM head
    layernorm_kernel<<<BT, 256>>>(x, h, lnfs, lnfb);
    tcg(h, EE, wlmT, EE, logits, VV, BT, VV, EE, blm, 0);

    // loss
    loss_rows_kernel<<<BT, 256>>>(logits, tgt, nll);
    if (nLoss > 0)
        loss_final_kernel<<<1, 256>>>(nll, lossPtr, nLoss);
}

// round 5
// speedup vs baseline: 3.4989x; 1.0050x over previous
#include <cuda_runtime.h>
#include <cuda_bf16.h>
#include <math.h>
#include <stdint.h>

// ---------------- problem constants ----------------
#define BB 4
#define TT 1024
#define EE 768
#define LL 6
#define HH 6
#define HD 128
#define VV 32000
#define FF (4*EE)          // 3072
#define BT (BB*TT)         // 4096
#define BTV ((long long)BT*VV)
#define QKV3 (3*EE)        // 2304

// ---------------- scratch (device globals; no allocations allowed) ----------------
__device__ float g_x [BT*EE];
__device__ float g_h [BT*EE];
__device__ float g_qkv[(long long)BT*QKV3];
__device__ float g_o [BT*EE];
__device__ float g_ff[BT*FF];
__device__ float g_nll[BT];
__device__ float g_logits_fb[BTV];
__device__ int   g_is64_idx;
__device__ int   g_is64_tgt;
// transposed (K-major [N,K]) operands, all pre-rounded to tf32 (rna)
__device__ float g_wqkvT[(long long)LL*QKV3*EE];
__device__ float g_bqkv [LL*QKV3];
__device__ float g_woT [LL*EE*EE];
__device__ float g_w1T [(long long)LL*EE*FF];
__device__ float g_w2T [(long long)LL*EE*FF];
__device__ float g_wlmT[(long long)EE*VV];
__device__ float g_vT  [(long long)BB*HH*HD*TT];

// ---------------- small helpers ----------------
__device__ __forceinline__ uint32_t smem_u32(const void* p) {
    uint32_t a;
    asm("{ .reg .u64 t; cvta.to.shared.u64 t, %1; cvt.u32.u64 %0, t; }" : "=r"(a) : "l"(p));
    return a;
}

__device__ __forceinline__ float rna_tf32(float x) {
    uint32_t u;
    asm("cvt.rna.tf32.f32 %0, %1;" : "=r"(u) : "f"(x));
    return __uint_as_float(u);
}

__device__ __forceinline__ void cp_async16(uint32_t saddr, const void* gaddr) {
    asm volatile("cp.async.cg.shared.global [%0], [%1], 16;" :: "r"(saddr), "l"(gaddr));
}

// tf32 mma.sync: D(16x8) += A(16x8) * B(8x8), row.col
__device__ __forceinline__ void mma_tf32(float* c, const uint32_t* a, const uint32_t* b) {
    asm volatile(
        "mma.sync.aligned.m16n8k8.row.col.f32.tf32.tf32.f32 "
        "{%0,%1,%2,%3}, {%4,%5,%6,%7}, {%8,%9}, {%0,%1,%2,%3};"
        : "+f"(c[0]), "+f"(c[1]), "+f"(c[2]), "+f"(c[3])
        : "r"(a[0]), "r"(a[1]), "r"(a[2]), "r"(a[3]), "r"(b[0]), "r"(b[1]));
}

// ---------------- int64-vs-int32 detection ----------------
__global__ void detect_kernel(const int* __restrict__ idx, const int* __restrict__ tgt) {
    if (threadIdx.x == 0 && blockIdx.x == 0) {
        int a = 1, b = 1;
        for (int i = 1; i < 129; i += 2) {
            if (idx[i] != 0) a = 0;
            if (tgt[i] != 0) b = 0;
        }
        g_is64_idx = a;
        g_is64_tgt = b;
    }
}

__device__ __forceinline__ long long load_token(const void* p, int r, int is64) {
    if (is64) return ((const long long*)p)[r];
    return (long long)((const int*)p)[r];
}

// ---------------- embedding ----------------
__global__ void embed_kernel(const void* __restrict__ idxv,
                             const float* __restrict__ tok,
                             const float* __restrict__ pos,
                             float* __restrict__ x) {
    int r = blockIdx.x;
    long long token = load_token(idxv, r, g_is64_idx);
    int t = r % TT;
    const float* te = tok + token * EE;
    const float* pe = pos + (long long)t * EE;
    float* xr = x + (long long)r * EE;
    for (int e = threadIdx.x; e < EE; e += blockDim.x)
        xr[e] = te[e] + pe[e];
}

// ---------------- layernorm (rna output: always feeds a GEMM) ----------------
__global__ void layernorm_kernel(const float* __restrict__ x, float* __restrict__ y,
                                 const float* __restrict__ s, const float* __restrict__ b) {
    int r = blockIdx.x;
    const float* row = x + (long long)r * EE;
    float* out = y + (long long)r * EE;
    int tid = threadIdx.x;
    __shared__ float red[256];

    float v0 = row[tid], v1 = row[tid + 256], v2 = row[tid + 512];
    red[tid] = v0 + v1 + v2; __syncthreads();
    for (int k = 128; k > 0; k >>= 1) { if (tid < k) red[tid] += red[tid + k]; __syncthreads(); }
    float mean = red[0] * (1.0f / EE);
    __syncthreads();

    float d0 = v0 - mean, d1 = v1 - mean, d2 = v2 - mean;
    red[tid] = d0*d0 + d1*d1 + d2*d2; __syncthreads();
    for (int k = 128; k > 0; k >>= 1) { if (tid < k) red[tid] += red[tid + k]; __syncthreads(); }
    float inv = rsqrtf(red[0] * (1.0f / EE) + 1e-5f);

    out[tid      ] = rna_tf32(d0 * inv * s[tid      ] + b[tid      ]);
    out[tid + 256] = rna_tf32(d1 * inv * s[tid + 256] + b[tid + 256]);
    out[tid + 512] = rna_tf32(d2 * inv * s[tid + 512] + b[tid + 512]);
}

// ---------------- generic batched transpose (rna output) ----------------
__global__ void transpose_kernel(const float* __restrict__ src, float* __restrict__ dst,
                                 int srs, int drs,
                                 long long sB, long long sH, long long dB, long long dH,
                                 int Hdiv) {
    int z = blockIdx.z, zb = z / Hdiv, zh = z - zb * Hdiv;
    src += zb * sB + zh * sH;
    dst += zb * dB + zh * dH;
    __shared__ float tile[32][33];
    int c0 = blockIdx.x * 32, r0 = blockIdx.y * 32;
    int tx = threadIdx.x, ty = threadIdx.y;   // 32 x 8
    #pragma unroll
    for (int i = 0; i < 32; i += 8)
        tile[ty + i][tx] = src[(long long)(r0 + ty + i) * srs + c0 + tx];
    __syncthreads();
    #pragma unroll
    for (int i = 0; i < 32; i += 8)
        dst[(long long)(c0 + ty + i) * drs + r0 + tx] = rna_tf32(tile[tx][ty + i]);
}

// ---------------- bias concat for merged QKV ----------------
__global__ void concat_bias_kernel(const float* __restrict__ bq, const float* __restrict__ bk,
                                   const float* __restrict__ bv, float* __restrict__ bqkv) {
    int l = blockIdx.y;
    int n = blockIdx.x * 256 + threadIdx.x;
    if (n < QKV3) {
        float v;
        if (n < EE)            v = bq[l * EE + n];
        else if (n < 2 * EE)   v = bk[l * EE + n - EE];
        else                   v = bv[l * EE + n - 2 * EE];
        bqkv[l * QKV3 + n] = v;
    }
}

// ---------------- tf32 mma.sync GEMM (128x128 tile) ----------------
// C[m,n] = sum_k A[m,k] * B[n,k]   (A [M,K] K-major, B [N,K] K-major)
// epi bits: 1=relu, 2=residual-add, 4=rna output. bias applied if non-null.
#define NST 3
#define SSTRIDE 36
#define STAGE_F (2*128*SSTRIDE)
#define TC_SMEM (NST*STAGE_F*4)          // 110592 bytes

__device__ __forceinline__ void load_chunk(const float* __restrict__ A, int lda,
                                           const float* __restrict__ Bm, int ldb,
                                           uint32_t sA, uint32_t sB,
                                           int m0, int n0, int k0, int tid) {
    #pragma unroll
    for (int t = 0; t < 4; t++) {
        int seg = tid + t * 256;
        int row = seg >> 3, kq = seg & 7;
        cp_async16(sA + (uint32_t)(row * (SSTRIDE*4) + kq * 16),
                   A + (long long)(m0 + row) * lda + k0 + kq * 4);
    }
    #pragma unroll
    for (int t = 0; t < 4; t++) {
        int seg = tid + t * 256;
        int row = seg >> 3, kq = seg & 7;
        cp_async16(sB + (uint32_t)(row * (SSTRIDE*4) + kq * 16),
                   Bm + (long long)(n0 + row) * ldb + k0 + kq * 4);
    }
}

__global__ void __launch_bounds__(256, 2)
tc_gemm(const float* __restrict__ A, int lda,
        const float* __restrict__ Bm, int ldb,
        float* __restrict__ C, int ldc,
        int K, const float* __restrict__ bias, int epi) {
    int m0 = blockIdx.y * 128, n0 = blockIdx.x * 128;
    int nchunks = K >> 5;

    extern __shared__ float sm[];
    uint32_t sb = smem_u32(sm);
    int tid = threadIdx.x, wid = tid >> 5, lane = tid & 31;
    int wm = wid & 1, wn = wid >> 1;       // 2 x 4 warp grid; warp tile 64x32
    int lr = lane >> 2, lc = lane & 3;

    float acc[4][4][4];
    #pragma unroll
    for (int i = 0; i < 4; i++)
        #pragma unroll
        for (int j = 0; j < 4; j++)
            #pragma unroll
            for (int e = 0; e < 4; e++) acc[i][j][e] = 0.0f;

    #pragma unroll
    for (int s = 0; s < NST - 1; s++) {
        if (s < nchunks)
            load_chunk(A, lda, Bm, ldb, sb + s * (STAGE_F*4), sb + s * (STAGE_F*4) + 128*SSTRIDE*4,
                       m0, n0, s * 32, tid);
        asm volatile("cp.async.commit_group;" ::: "memory");
    }

    for (int c = 0; c < nchunks; c++) {
        asm volatile("cp.async.wait_group %0;" :: "n"(NST - 2) : "memory");
        __syncthreads();

        int cn = c + NST - 1;
        if (cn < nchunks) {
            int sn = cn % NST;
            load_chunk(A, lda, Bm, ldb, sb + sn * (STAGE_F*4), sb + sn * (STAGE_F*4) + 128*SSTRIDE*4,
                       m0, n0, cn * 32, tid);
        }
        asm volatile("cp.async.commit_group;" ::: "memory");

        const float* As = sm + (c % NST) * STAGE_F;
        const float* Bs = As + 128 * SSTRIDE;

        #pragma unroll
        for (int ks = 0; ks < 4; ks++) {
            uint32_t afr[4][4], bfr[4][2];
            #pragma unroll
            for (int i = 0; i < 4; i++) {
                const float* ab = As + (wm * 64 + i * 16 + lr) * SSTRIDE + ks * 8 + lc;
                afr[i][0] = __float_as_uint(ab[0]);
                afr[i][1] = __float_as_uint(ab[8 * SSTRIDE]);
                afr[i][2] = __float_as_uint(ab[4]);
                afr[i][3] = __float_as_uint(ab[8 * SSTRIDE + 4]);
            }
            #pragma unroll
            for (int j = 0; j < 4; j++) {
                const float* bb = Bs + (wn * 32 + j * 8 + lr) * SSTRIDE + ks * 8 + lc;
                bfr[j][0] = __float_as_uint(bb[0]);
                bfr[j][1] = __float_as_uint(bb[4]);
            }
            #pragma unroll
            for (int i = 0; i < 4; i++)
                #pragma unroll
                for (int j = 0; j < 4; j++)
                    mma_tf32(acc[i][j], afr[i], bfr[j]);
        }
        __syncthreads();
    }

    #pragma unroll
    for (int i = 0; i < 4; i++) {
        #pragma unroll
        for (int half = 0; half < 2; half++) {
            int m = m0 + wm * 64 + i * 16 + half * 8 + lr;
            float* crow = C + (long long)m * ldc;
            #pragma unroll
            for (int j = 0; j < 4; j++) {
                int n = n0 + wn * 32 + j * 8 + lc * 2;
                float v0 = acc[i][j][half * 2 + 0];
                float v1 = acc[i][j][half * 2 + 1];
                if (bias) { v0 += bias[n]; v1 += bias[n + 1]; }
                if (epi & 1) { v0 = fmaxf(v0, 0.0f); v1 = fmaxf(v1, 0.0f); }
                if (epi & 2) { v0 += crow[n]; v1 += crow[n + 1]; }
                if (epi & 4) { v0 = rna_tf32(v0); v1 = rna_tf32(v1); }
                *(float2*)(crow + n) = make_float2(v0, v1);
            }
        }
    }
}

// ---------------- tf32 mma.sync GEMM (128x256 tile, warp tile 64x64) ----------------
#define WNST 3
#define WSTAGE_F ((128+256)*SSTRIDE)       // 13824 floats per stage
#define TCW_SMEM (WNST*WSTAGE_F*4)         // 165888 bytes

__device__ __forceinline__ void load_chunk_w(const float* __restrict__ A, int lda,
                                             const float* __restrict__ Bm, int ldb,
                                             uint32_t sA, uint32_t sB,
                                             int m0, int n0, int k0, int tid) {
    #pragma unroll
    for (int t = 0; t < 4; t++) {
        int seg = tid + t * 256;          // 0..1023
        int row = seg >> 3, kq = seg & 7;
        cp_async16(sA + (uint32_t)(row * (SSTRIDE*4) + kq * 16),
                   A + (long long)(m0 + row) * lda + k0 + kq * 4);
    }
    #pragma unroll
    for (int t = 0; t < 8; t++) {
        int seg = tid + t * 256;          // 0..2047
        int row = seg >> 3, kq = seg & 7;
        cp_async16(sB + (uint32_t)(row * (SSTRIDE*4) + kq * 16),
                   Bm + (long long)(n0 + row) * ldb + k0 + kq * 4);
    }
}

__global__ void __launch_bounds__(256, 1)
tc_gemm_wide(const float* __restrict__ A, int lda,
             const float* __restrict__ Bm, int ldb,
             float* __restrict__ C, int ldc,
             int K, const float* __restrict__ bias, int epi) {
    int m0 = blockIdx.y * 128, n0 = blockIdx.x * 256;
    int nchunks = K >> 5;

    extern __shared__ float sm[];
    uint32_t sb = smem_u32(sm);
    int tid = threadIdx.x, wid = tid >> 5, lane = tid & 31;
    int wm = wid & 1, wn = wid >> 1;       // 2 x 4 warp grid; warp tile 64x64
    int lr = lane >> 2, lc = lane & 3;

    float acc[4][8][4];
    #pragma unroll
    for (int i = 0; i < 4; i++)
        #pragma unroll
        for (int j = 0; j < 8; j++)
            #pragma unroll
            for (int e = 0; e < 4; e++) acc[i][j][e] = 0.0f;

    #pragma unroll
    for (int s = 0; s < WNST - 1; s++) {
        if (s < nchunks)
            load_chunk_w(A, lda, Bm, ldb, sb + s * (WSTAGE_F*4), sb + s * (WSTAGE_F*4) + 128*SSTRIDE*4,
                         m0, n0, s * 32, tid);
        asm volatile("cp.async.commit_group;" ::: "memory");
    }

    for (int c = 0; c < nchunks; c++) {
        asm volatile("cp.async.wait_group %0;" :: "n"(WNST - 2) : "memory");
        __syncthreads();

        int cn = c + WNST - 1;
        if (cn < nchunks) {
            int sn = cn % WNST;
            load_chunk_w(A, lda, Bm, ldb, sb + sn * (WSTAGE_F*4), sb + sn * (WSTAGE_F*4) + 128*SSTRIDE*4,
                         m0, n0, cn * 32, tid);
        }
        asm volatile("cp.async.commit_group;" ::: "memory");

        const float* As = sm + (c % WNST) * WSTAGE_F;
        const float* Bs = As + 128 * SSTRIDE;

        #pragma unroll
        for (int ks = 0; ks < 4; ks++) {
            uint32_t afr[4][4];
            #pragma unroll
            for (int i = 0; i < 4; i++) {
                const float* ab = As + (wm * 64 + i * 16 + lr) * SSTRIDE + ks * 8 + lc;
                afr[i][0] = __float_as_uint(ab[0]);
                afr[i][1] = __float_as_uint(ab[8 * SSTRIDE]);
                afr[i][2] = __float_as_uint(ab[4]);
                afr[i][3] = __float_as_uint(ab[8 * SSTRIDE + 4]);
            }
            #pragma unroll
            for (int j = 0; j < 8; j++) {
                uint32_t bfr[2];
                const float* bb = Bs + (wn * 64 + j * 8 + lr) * SSTRIDE + ks * 8 + lc;
                bfr[0] = __float_as_uint(bb[0]);
                bfr[1] = __float_as_uint(bb[4]);
                #pragma unroll
                for (int i = 0; i < 4; i++)
                    mma_tf32(acc[i][j], afr[i], bfr);
            }
        }
        __syncthreads();
    }

    #pragma unroll
    for (int i = 0; i < 4; i++) {
        #pragma unroll
        for (int half = 0; half < 2; half++) {
            int m = m0 + wm * 64 + i * 16 + half * 8 + lr;
            float* crow = C + (long long)m * ldc;
            #pragma unroll
            for (int j = 0; j < 8; j++) {
                int n = n0 + wn * 64 + j * 8 + lc * 2;
                float v0 = acc[i][j][half * 2 + 0];
                float v1 = acc[i][j][half * 2 + 1];
                if (bias) { v0 += bias[n]; v1 += bias[n + 1]; }
                if (epi & 1) { v0 = fmaxf(v0, 0.0f); v1 = fmaxf(v1, 0.0f); }
                if (epi & 2) { v0 += crow[n]; v1 += crow[n + 1]; }
                if (epi & 4) { v0 = rna_tf32(v0); v1 = rna_tf32(v1); }
                *(float2*)(crow + n) = make_float2(v0, v1);
            }
        }
    }
}

// ---------------- fused flash attention ----------------
#define FSTR 132
#define FQ_OFF 0
#define FK_OFF (128*FSTR)
#define FV_OFF (2*128*FSTR)
#define FRED_OFF (3*128*FSTR)
#define FM_OFF  (FRED_OFF + 512)
#define FL_OFF  (FM_OFF + 128)
#define FC_OFF  (FL_OFF + 128)
#define FLASH_SMEM ((FC_OFF + 128)*4)

__device__ __forceinline__ void load_tile128(uint32_t sdst, const float* __restrict__ g,
                                             int ldg, int tid) {
    #pragma unroll
    for (int t = 0; t < 16; t++) {
        int seg = tid + t * 256;
        int row = seg >> 5, kq = seg & 31;
        cp_async16(sdst + (uint32_t)(row * (FSTR*4) + kq * 16),
                   g + (long long)row * ldg + kq * 4);
    }
}

__global__ void __launch_bounds__(256, 1)
flash_kernel(const float* __restrict__ qkv, const float* __restrict__ vT,
             float* __restrict__ o) {
    int i = 7 - blockIdx.x;
    int z = blockIdx.y;
    int b = z / HH, h = z - b * HH;

    extern __shared__ float fs[];
    uint32_t sb = smem_u32(fs);
    int tid = threadIdx.x, wid = tid >> 5, lane = tid & 31;
    int wm = wid & 1, wn = wid >> 1;
    int lr = lane >> 2, lc = lane & 3;

    const float* qg = qkv + ((long long)(b * TT + i * 128)) * QKV3 + h * HD;
    const float* kg = qkv + ((long long)(b * TT)) * QKV3 + EE + h * HD;
    const float* vg = vT + (long long)z * HD * TT;

    load_tile128(sb + FQ_OFF*4, qg, QKV3, tid);
    asm volatile("cp.async.commit_group;" ::: "memory");

    if (tid < 128) { fs[FM_OFF + tid] = -1e30f; fs[FL_OFF + tid] = 0.0f; }

    float oacc[4][4][4];
    #pragma unroll
    for (int a = 0; a < 4; a++)
        #pragma unroll
        for (int j = 0; j < 4; j++)
            #pragma unroll
            for (int e = 0; e < 4; e++) oacc[a][j][e] = 0.0f;

    const float scale = 0.0883883476483184406f;

    for (int j = 0; j <= i; j++) {
        load_tile128(sb + FK_OFF*4, kg + (long long)(j * 128) * QKV3, QKV3, tid);
        asm volatile("cp.async.commit_group;" ::: "memory");
        load_tile128(sb + FV_OFF*4, vg + j * 128, TT, tid);
        asm volatile("cp.async.commit_group;" ::: "memory");
        asm volatile("cp.async.wait_group 1;" ::: "memory");
        __syncthreads();

        float sacc[4][4][4];
        #pragma unroll
        for (int a = 0; a < 4; a++)
            #pragma unroll
            for (int jt = 0; jt < 4; jt++)
                #pragma unroll
                for (int e = 0; e < 4; e++) sacc[a][jt][e] = 0.0f;

        const float* Qs = fs + FQ_OFF;
        const float* Ks = fs + FK_OFF;
        #pragma unroll
        for (int kk = 0; kk < 16; kk++) {
            uint32_t afr[4][4], bfr[4][2];
            #pragma unroll
            for (int a = 0; a < 4; a++) {
                const float* ab = Qs + (wm * 64 + a * 16 + lr) * FSTR + kk * 8 + lc;
                afr[a][0] = __float_as_uint(ab[0]);
                afr[a][1] = __float_as_uint(ab[8 * FSTR]);
                afr[a][2] = __float_as_uint(ab[4]);
                afr[a][3] = __float_as_uint(ab[8 * FSTR + 4]);
            }
            #pragma unroll
            for (int jt = 0; jt < 4; jt++) {
                const float* bb = Ks + (wn * 32 + jt * 8 + lr) * FSTR + kk * 8 + lc;
                bfr[jt][0] = __float_as_uint(bb[0]);
                bfr[jt][1] = __float_as_uint(bb[4]);
            }
            #pragma unroll
            for (int a = 0; a < 4; a++)
                #pragma unroll
                for (int jt = 0; jt < 4; jt++)
                    mma_tf32(sacc[a][jt], afr[a], bfr[jt]);
        }

        float pmax[4][2];
        #pragma unroll
        for (int a = 0; a < 4; a++) { pmax[a][0] = -1e30f; pmax[a][1] = -1e30f; }
        #pragma unroll
        for (int a = 0; a < 4; a++)
            #pragma unroll
            for (int jt = 0; jt < 4; jt++)
                #pragma unroll
                for (int e = 0; e < 4; e++) {
                    int half = e >> 1;
                    float sv = sacc[a][jt][e] * scale;
                    if (j == i) {
                        int mr = wm * 64 + a * 16 + half * 8 + lr;
                        int nc = wn * 32 + jt * 8 + 2 * lc + (e & 1);
                        if (nc > mr) sv = -1e30f;
                    }
                    sacc[a][jt][e] = sv;
                    pmax[a][half] = fmaxf(pmax[a][half], sv);
                }
        #pragma unroll
        for (int a = 0; a < 4; a++)
            #pragma unroll
            for (int half = 0; half < 2; half++) {
                float v = pmax[a][half];
                v = fmaxf(v, __shfl_xor_sync(0xFFFFFFFF, v, 1));
                v = fmaxf(v, __shfl_xor_sync(0xFFFFFFFF, v, 2));
                pmax[a][half] = v;
            }
        if (lc == 0) {
            #pragma unroll
            for (int a = 0; a < 4; a++)
                #pragma unroll
                for (int half = 0; half < 2; half++)
                    fs[FRED_OFF + (wm * 64 + a * 16 + half * 8 + lr) * 4 + wn] = pmax[a][half];
        }
        __syncthreads();

        if (wn == 0 && lc == 0) {
            #pragma unroll
            for (int a = 0; a < 4; a++)
                #pragma unroll
                for (int half = 0; half < 2; half++) {
                    int r = wm * 64 + a * 16 + half * 8 + lr;
                    float m4 = fmaxf(fmaxf(fs[FRED_OFF + r*4], fs[FRED_OFF + r*4 + 1]),
                                     fmaxf(fs[FRED_OFF + r*4 + 2], fs[FRED_OFF + r*4 + 3]));
                    float mold = fs[FM_OFF + r];
                    float mnew = fmaxf(mold, m4);
                    fs[FC_OFF + r] = __expf(mold - mnew);
                    fs[FM_OFF + r] = mnew;
                }
        }
        __syncthreads();

        float mn[4][2], cr[4][2], psum[4][2];
        #pragma unroll
        for (int a = 0; a < 4; a++)
            #pragma unroll
            for (int half = 0; half < 2; half++) {
                int r = wm * 64 + a * 16 + half * 8 + lr;
                mn[a][half] = fs[FM_OFF + r];
                cr[a][half] = fs[FC_OFF + r];
                psum[a][half] = 0.0f;
            }
        float* Ps = fs + FK_OFF;
        #pragma unroll
        for (int a = 0; a < 4; a++)
            #pragma unroll
            for (int jt = 0; jt < 4; jt++) {
                #pragma unroll
                for (int half = 0; half < 2; half++) {
                    float p0 = __expf(sacc[a][jt][half*2 + 0] - mn[a][half]);
                    float p1 = __expf(sacc[a][jt][half*2 + 1] - mn[a][half]);
                    psum[a][half] += p0 + p1;
                    oacc[a][jt][half*2 + 0] *= cr[a][half];
                    oacc[a][jt][half*2 + 1] *= cr[a][half];
                    int r = wm * 64 + a * 16 + half * 8 + lr;
                    int nc = wn * 32 + jt * 8 + 2 * lc;
                    *(float2*)(Ps + r * FSTR + nc) = make_float2(rna_tf32(p0), rna_tf32(p1));
                }
            }
        #pragma unroll
        for (int a = 0; a < 4; a++)
            #pragma unroll
            for (int half = 0; half < 2; half++) {
                float v = psum[a][half];
                v += __shfl_xor_sync(0xFFFFFFFF, v, 1);
                v += __shfl_xor_sync(0xFFFFFFFF, v, 2);
                psum[a][half] = v;
            }
        if (lc == 0) {
            #pragma unroll
            for (int a = 0; a < 4; a++)
                #pragma unroll
                for (int half = 0; half < 2; half++)
                    fs[FRED_OFF + (wm * 64 + a * 16 + half * 8 + lr) * 4 + wn] = psum[a][half];
        }
        asm volatile("cp.async.wait_group 0;" ::: "memory");
        __syncthreads();

        if (wn == 0 && lc == 0) {
            #pragma unroll
            for (int a = 0; a < 4; a++)
                #pragma unroll
                for (int half = 0; half < 2; half++) {
                    int r = wm * 64 + a * 16 + half * 8 + lr;
                    float s4 = fs[FRED_OFF + r*4] + fs[FRED_OFF + r*4 + 1]
                             + fs[FRED_OFF + r*4 + 2] + fs[FRED_OFF + r*4 + 3];
                    fs[FL_OFF + r] = fs[FL_OFF + r] * fs[FC_OFF + r] + s4;
                }
        }

        const float* Vs = fs + FV_OFF;
        #pragma unroll
        for (int kk = 0; kk < 16; kk++) {
            uint32_t afr[4][4], bfr[4][2];
            #pragma unroll
            for (int a = 0; a < 4; a++) {
                const float* ab = Ps + (wm * 64 + a * 16 + lr) * FSTR + kk * 8 + lc;
                afr[a][0] = __float_as_uint(ab[0]);
                afr[a][1] = __float_as_uint(ab[8 * FSTR]);
                afr[a][2] = __float_as_uint(ab[4]);
                afr[a][3] = __float_as_uint(ab[8 * FSTR + 4]);
            }
            #pragma unroll
            for (int jt = 0; jt < 4; jt++) {
                const float* bb = Vs + (wn * 32 + jt * 8 + lr) * FSTR + kk * 8 + lc;
                bfr[jt][0] = __float_as_uint(bb[0]);
                bfr[jt][1] = __float_as_uint(bb[4]);
            }
            #pragma unroll
            for (int a = 0; a < 4; a++)
                #pragma unroll
                for (int jt = 0; jt < 4; jt++)
                    mma_tf32(oacc[a][jt], afr[a], bfr[jt]);
        }
        __syncthreads();
    }

    float* og = o + ((long long)(b * TT + i * 128)) * EE + h * HD;
    #pragma unroll
    for (int a = 0; a < 4; a++)
        #pragma unroll
        for (int half = 0; half < 2; half++) {
            int r = wm * 64 + a * 16 + half * 8 + lr;
            float linv = 1.0f / fs[FL_OFF + r];
            float* orow = og + (long long)r * EE;
            #pragma unroll
            for (int jt = 0; jt < 4; jt++) {
                int nc = wn * 32 + jt * 8 + 2 * lc;
                float v0 = rna_tf32(oacc[a][jt][half*2 + 0] * linv);
                float v1 = rna_tf32(oacc[a][jt][half*2 + 1] * linv);
                *(float2*)(orow + nc) = make_float2(v0, v1);
            }
        }
}

// ---------------- per-row NLL via streaming logsumexp ----------------
__global__ void loss_rows_kernel(const float* __restrict__ logits,
                                 const void* __restrict__ tgtv,
                                 float* __restrict__ nll) {
    int r = blockIdx.x;
    const float* row = logits + (long long)r * VV;
    int tid = threadIdx.x;
    float m = -1e30f, s = 0.0f;
    for (int j = tid; j < VV; j += 256) {
        float v = row[j];
        if (v > m) { s = s * __expf(m - v) + 1.0f; m = v; }
        else       { s += __expf(v - m); }
    }
    __shared__ float sm[256], ss[256];
    sm[tid] = m; ss[tid] = s; __syncthreads();
    for (int k = 128; k > 0; k >>= 1) {
        if (tid < k) {
            float m2 = sm[tid + k], s2 = ss[tid + k];
            float mm = fmaxf(sm[tid], m2);
            ss[tid] = ss[tid] * __expf(sm[tid] - mm) + s2 * __expf(m2 - mm);
            sm[tid] = mm;
        }
        __syncthreads();
    }
    if (tid == 0) {
        long long t = load_token(tgtv, r, g_is64_tgt);
        nll[r] = (sm[0] + logf(ss[0])) - row[t];
    }
}

__global__ void loss_final_kernel(const float* __restrict__ nll, float* __restrict__ out, int n) {
    __shared__ float red[256];
    int tid = threadIdx.x;
    float s = 0.0f;
    for (int j = tid; j < BT; j += 256) s += nll[j];
    red[tid] = s; __syncthreads();
    for (int k = 128; k > 0; k >>= 1) { if (tid < k) red[tid] += red[tid + k]; __syncthreads(); }
    float mean = red[0] * (1.0f / BT);
    for (int i = tid; i < n; i += 256) out[i] = mean;
}

// ---------------- host-side helpers ----------------
static void tcg(const float* A, int lda, const float* Bm, int ldb,
                float* C, int ldc, int M, int N, int K,
                const float* bias, int epi) {
    dim3 grid(N / 128, M / 128, 1);
    tc_gemm<<<grid, 256, TC_SMEM>>>(A, lda, Bm, ldb, C, ldc, K, bias, epi);
}

static void tcgw(const float* A, int lda, const float* Bm, int ldb,
                 float* C, int ldc, int M, int N, int K,
                 const float* bias, int epi) {
    dim3 grid(N / 256, M / 128, 1);
    tc_gemm_wide<<<grid, 256, TCW_SMEM>>>(A, lda, Bm, ldb, C, ldc, K, bias, epi);
}

static void tr(const float* s, float* d, int R, int C, int srs, int drs,
               long long sB, long long sH, long long dB, long long dH,
               int Hdiv, int Z) {
    dim3 grid(C / 32, R / 32, Z), blk(32, 8);
    transpose_kernel<<<grid, blk>>>(s, d, srs, drs, sB, sH, dB, dH, Hdiv);
}

extern "C" void kernel_launch(void* const* d_in, const int* in_sizes, int n_in,
                              void* d_out, int out_size) {
    const void*  idx  = d_in[0];
    const void*  tgt  = d_in[1];
    const float* tok  = (const float*)d_in[2];
    const float* pos  = (const float*)d_in[3];
    const float* Wq   = (const float*)d_in[4];
    const float* bq   = (const float*)d_in[5];
    const float* Wk   = (const float*)d_in[6];
    const float* bk   = (const float*)d_in[7];
    const float* Wv   = (const float*)d_in[8];
    const float* bv   = (const float*)d_in[9];
    const float* Wo   = (const float*)d_in[10];
    const float* bo   = (const float*)d_in[11];
    const float* w1   = (const float*)d_in[12];
    const float* b1   = (const float*)d_in[13];
    const float* w2   = (const float*)d_in[14];
    const float* b2   = (const float*)d_in[15];
    const float* ln1s = (const float*)d_in[16];
    const float* ln1b = (const float*)d_in[17];
    const float* ln2s = (const float*)d_in[18];
    const float* ln2b = (const float*)d_in[19];
    const float* lnfs = (const float*)d_in[20];
    const float* lnfb = (const float*)d_in[21];
    const float* Wlm  = (const float*)d_in[22];
    const float* blm  = (const float*)d_in[23];

    float *x, *h, *qkv, *o, *ff, *nll, *logits_fb;
    float *wqkvT, *bqkv, *woT, *w1T, *w2T, *wlmT, *vT;
    cudaGetSymbolAddress((void**)&x,    g_x);
    cudaGetSymbolAddress((void**)&h,    g_h);
    cudaGetSymbolAddress((void**)&qkv,  g_qkv);
    cudaGetSymbolAddress((void**)&o,    g_o);
    cudaGetSymbolAddress((void**)&ff,   g_ff);
    cudaGetSymbolAddress((void**)&nll,  g_nll);
    cudaGetSymbolAddress((void**)&logits_fb, g_logits_fb);
    cudaGetSymbolAddress((void**)&wqkvT, g_wqkvT);
    cudaGetSymbolAddress((void**)&bqkv,  g_bqkv);
    cudaGetSymbolAddress((void**)&woT,  g_woT);
    cudaGetSymbolAddress((void**)&w1T,  g_w1T);
    cudaGetSymbolAddress((void**)&w2T,  g_w2T);
    cudaGetSymbolAddress((void**)&wlmT, g_wlmT);
    cudaGetSymbolAddress((void**)&vT,   g_vT);

    cudaFuncSetAttribute(tc_gemm, cudaFuncAttributeMaxDynamicSharedMemorySize, TC_SMEM);
    cudaFuncSetAttribute(tc_gemm_wide, cudaFuncAttributeMaxDynamicSharedMemorySize, TCW_SMEM);
    cudaFuncSetAttribute(flash_kernel, cudaFuncAttributeMaxDynamicSharedMemorySize, FLASH_SMEM);

    float* out = (float*)d_out;
    float* logits = ((long long)out_size >= BTV) ? out : logits_fb;
    float* lossPtr = nullptr;
    int nLoss = 0;
    if ((long long)out_size > BTV) { lossPtr = out + BTV; nLoss = out_size - (int)BTV; }
    else if ((long long)out_size < BTV) { lossPtr = out; nLoss = out_size; }

    detect_kernel<<<1, 32>>>((const int*)idx, (const int*)tgt);
    embed_kernel<<<BT, 256>>>(idx, tok, pos, x);

    const long long E2   = (long long)EE * EE;
    const long long EF   = (long long)EE * FF;
    const long long LQ3  = (long long)QKV3 * EE;
    tr(Wq, wqkvT,             EE, EE, EE, EE, E2, 0, LQ3, 0, 1, LL);
    tr(Wk, wqkvT + EE*EE,     EE, EE, EE, EE, E2, 0, LQ3, 0, 1, LL);
    tr(Wv, wqkvT + 2*EE*EE,   EE, EE, EE, EE, E2, 0, LQ3, 0, 1, LL);
    concat_bias_kernel<<<dim3(9, LL), 256>>>(bq, bk, bv, bqkv);
    tr(Wo,  woT,  EE, EE, EE, EE, E2, 0, E2, 0, 1, LL);
    tr(w1,  w1T,  EE, FF, FF, EE, EF, 0, EF, 0, 1, LL);
    tr(w2,  w2T,  FF, EE, EE, FF, EF, 0, EF, 0, 1, LL);
    tr(Wlm, wlmT, EE, VV, VV, EE, 0, 0, 0, 0, 1, 1);

    const long long ZVT = (long long)HD * TT;

    for (int l = 0; l < LL; l++) {
        // h = rna(LN1(x))
        layernorm_kernel<<<BT, 256>>>(x, h, ln1s + l * EE, ln1b + l * EE);

        // qkv = rna(h @ Wqkv + bqkv)   [BT x 2304]  (wide tile)
        tcgw(h, EE, wqkvT + l * LQ3, EE, qkv, QKV3, BT, QKV3, EE,
             bqkv + l * QKV3, 4);

        // vT[b,h,d,t] = rna(v[b,t,h,d])
        tr(qkv + 2 * EE, vT, TT, HD, QKV3, TT,
           (long long)TT * QKV3, HD, (long long)HH * ZVT, ZVT, HH, BB * HH);

        // fused attention -> o (rna'd)
        flash_kernel<<<dim3(8, BB * HH), 256, FLASH_SMEM>>>(qkv, vT, o);

        // x += o @ Wo + bo
        tcg(o, EE, woT + l * E2, EE, x, EE, BT, EE, EE, bo + l * EE, 2);

        // h = rna(LN2(x))
        layernorm_kernel<<<BT, 256>>>(x, h, ln2s + l * EE, ln2b + l * EE);

        // ff = rna(relu(h @ w1 + b1))  (wide tile);  x += ff @ w2 + b2
        tcgw(h, EE, w1T + l * EF, EE, ff, FF, BT, FF, EE, b1 + (long long)l * FF, 5);
        tcg(ff, FF, w2T + l * EF, FF, x, EE, BT, EE, FF, b2 + l * EE, 2);
    }

    // final LN + LM head (wide tile)
    layernorm_kernel<<<BT, 256>>>(x, h, lnfs, lnfb);
    tcgw(h, EE, wlmT, EE, logits, VV, BT, VV, EE, blm, 0);

    // loss
    loss_rows_kernel<<<BT, 256>>>(logits, tgt, nll);
    if (nLoss > 0)
        loss_final_kernel<<<1, 256>>>(nll, lossPtr, nLoss);
}

// round 6
// speedup vs baseline: 3.5255x; 1.0076x over previous
#include <cuda_runtime.h>
#include <cuda_bf16.h>
#include <math.h>
#include <stdint.h>

// ---------------- problem constants ----------------
#define BB 4
#define TT 1024
#define EE 768
#define LL 6
#define HH 6
#define HD 128
#define VV 32000
#define FF (4*EE)          // 3072
#define BT (BB*TT)         // 4096
#define BTV ((long long)BT*VV)
#define QKV3 (3*EE)        // 2304

// ---------------- scratch (device globals; no allocations allowed) ----------------
__device__ float g_x [BT*EE];
__device__ float g_h [BT*EE];
__device__ float g_qkv[(long long)BT*QKV3];
__device__ float g_o [BT*EE];
__device__ float g_ff[BT*FF];
__device__ float g_nll[BT];
__device__ float g_logits_fb[BTV];
__device__ int   g_is64_idx;
__device__ int   g_is64_tgt;
// transposed (K-major [N,K]) operands, all pre-rounded to tf32 (rna)
__device__ float g_wqkvT[(long long)LL*QKV3*EE];
__device__ float g_bqkv [LL*QKV3];
__device__ float g_woT [LL*EE*EE];
__device__ float g_w1T [(long long)LL*EE*FF];
__device__ float g_w2T [(long long)LL*EE*FF];
__device__ float g_wlmT[(long long)EE*VV];
__device__ float g_vT  [(long long)BB*HH*HD*TT];

// ---------------- small helpers ----------------
__device__ __forceinline__ uint32_t smem_u32(const void* p) {
    uint32_t a;
    asm("{ .reg .u64 t; cvta.to.shared.u64 t, %1; cvt.u32.u64 %0, t; }" : "=r"(a) : "l"(p));
    return a;
}

__device__ __forceinline__ float rna_tf32(float x) {
    uint32_t u;
    asm("cvt.rna.tf32.f32 %0, %1;" : "=r"(u) : "f"(x));
    return __uint_as_float(u);
}

__device__ __forceinline__ void cp_async16(uint32_t saddr, const void* gaddr) {
    asm volatile("cp.async.cg.shared.global [%0], [%1], 16;" :: "r"(saddr), "l"(gaddr));
}

// tf32 mma.sync: D(16x8) += A(16x8) * B(8x8), row.col
__device__ __forceinline__ void mma_tf32(float* c, const uint32_t* a, const uint32_t* b) {
    asm volatile(
        "mma.sync.aligned.m16n8k8.row.col.f32.tf32.tf32.f32 "
        "{%0,%1,%2,%3}, {%4,%5,%6,%7}, {%8,%9}, {%0,%1,%2,%3};"
        : "+f"(c[0]), "+f"(c[1]), "+f"(c[2]), "+f"(c[3])
        : "r"(a[0]), "r"(a[1]), "r"(a[2]), "r"(a[3]), "r"(b[0]), "r"(b[1]));
}

// ---------------- int64-vs-int32 detection ----------------
__global__ void detect_kernel(const int* __restrict__ idx, const int* __restrict__ tgt) {
    if (threadIdx.x == 0 && blockIdx.x == 0) {
        int a = 1, b = 1;
        for (int i = 1; i < 129; i += 2) {
            if (idx[i] != 0) a = 0;
            if (tgt[i] != 0) b = 0;
        }
        g_is64_idx = a;
        g_is64_tgt = b;
    }
}

__device__ __forceinline__ long long load_token(const void* p, int r, int is64) {
    if (is64) return ((const long long*)p)[r];
    return (long long)((const int*)p)[r];
}

// ---------------- embedding ----------------
__global__ void embed_kernel(const void* __restrict__ idxv,
                             const float* __restrict__ tok,
                             const float* __restrict__ pos,
                             float* __restrict__ x) {
    int r = blockIdx.x;
    long long token = load_token(idxv, r, g_is64_idx);
    int t = r % TT;
    const float* te = tok + token * EE;
    const float* pe = pos + (long long)t * EE;
    float* xr = x + (long long)r * EE;
    for (int e = threadIdx.x; e < EE; e += blockDim.x)
        xr[e] = te[e] + pe[e];
}

// ---------------- layernorm (rna output: always feeds a GEMM) ----------------
__global__ void layernorm_kernel(const float* __restrict__ x, float* __restrict__ y,
                                 const float* __restrict__ s, const float* __restrict__ b) {
    int r = blockIdx.x;
    const float* row = x + (long long)r * EE;
    float* out = y + (long long)r * EE;
    int tid = threadIdx.x;
    __shared__ float red[256];

    float v0 = row[tid], v1 = row[tid + 256], v2 = row[tid + 512];
    red[tid] = v0 + v1 + v2; __syncthreads();
    for (int k = 128; k > 0; k >>= 1) { if (tid < k) red[tid] += red[tid + k]; __syncthreads(); }
    float mean = red[0] * (1.0f / EE);
    __syncthreads();

    float d0 = v0 - mean, d1 = v1 - mean, d2 = v2 - mean;
    red[tid] = d0*d0 + d1*d1 + d2*d2; __syncthreads();
    for (int k = 128; k > 0; k >>= 1) { if (tid < k) red[tid] += red[tid + k]; __syncthreads(); }
    float inv = rsqrtf(red[0] * (1.0f / EE) + 1e-5f);

    out[tid      ] = rna_tf32(d0 * inv * s[tid      ] + b[tid      ]);
    out[tid + 256] = rna_tf32(d1 * inv * s[tid + 256] + b[tid + 256]);
    out[tid + 512] = rna_tf32(d2 * inv * s[tid + 512] + b[tid + 512]);
}

// ---------------- generic batched transpose (rna output) ----------------
__global__ void transpose_kernel(const float* __restrict__ src, float* __restrict__ dst,
                                 int srs, int drs,
                                 long long sB, long long sH, long long dB, long long dH,
                                 int Hdiv) {
    int z = blockIdx.z, zb = z / Hdiv, zh = z - zb * Hdiv;
    src += zb * sB + zh * sH;
    dst += zb * dB + zh * dH;
    __shared__ float tile[32][33];
    int c0 = blockIdx.x * 32, r0 = blockIdx.y * 32;
    int tx = threadIdx.x, ty = threadIdx.y;   // 32 x 8
    #pragma unroll
    for (int i = 0; i < 32; i += 8)
        tile[ty + i][tx] = src[(long long)(r0 + ty + i) * srs + c0 + tx];
    __syncthreads();
    #pragma unroll
    for (int i = 0; i < 32; i += 8)
        dst[(long long)(c0 + ty + i) * drs + r0 + tx] = rna_tf32(tile[tx][ty + i]);
}

// ---------------- fused QKV weight transpose + bias concat (one launch) ----------------
// z in [0, 3*LL): transpose slice s=z/LL, layer l=z%LL of {Wq,Wk,Wv}[s] -> wqkvT
// z == 3*LL: copy concatenated biases.
__global__ void qkv_prep_kernel(const float* __restrict__ Wq, const float* __restrict__ Wk,
                                const float* __restrict__ Wv,
                                const float* __restrict__ bq, const float* __restrict__ bk,
                                const float* __restrict__ bv,
                                float* __restrict__ wqkvT, float* __restrict__ bqkv) {
    int z = blockIdx.z;
    int tx = threadIdx.x, ty = threadIdx.y;   // 32 x 8
    if (z == 3 * LL) {
        int i = (blockIdx.y * gridDim.x + blockIdx.x) * 256 + ty * 32 + tx;
        if (i < LL * QKV3) {
            int l = i / QKV3, n = i - l * QKV3;
            float v;
            if (n < EE)          v = bq[l * EE + n];
            else if (n < 2*EE)   v = bk[l * EE + n - EE];
            else                 v = bv[l * EE + n - 2*EE];
            bqkv[i] = v;
        }
        return;
    }
    int s = z / LL, l = z - s * LL;
    const float* src = (s == 0 ? Wq : (s == 1 ? Wk : Wv)) + (long long)l * EE * EE;
    float* dst = wqkvT + (long long)l * QKV3 * EE + (long long)s * EE * EE;
    __shared__ float tile[32][33];
    int c0 = blockIdx.x * 32, r0 = blockIdx.y * 32;
    #pragma unroll
    for (int i = 0; i < 32; i += 8)
        tile[ty + i][tx] = src[(long long)(r0 + ty + i) * EE + c0 + tx];
    __syncthreads();
    #pragma unroll
    for (int i = 0; i < 32; i += 8)
        dst[(long long)(c0 + ty + i) * EE + r0 + tx] = rna_tf32(tile[tx][ty + i]);
}

// ---------------- tf32 mma.sync GEMM (128x128 tile) ----------------
// C[m,n] = sum_k A[m,k] * B[n,k]   (A [M,K] K-major, B [N,K] K-major)
// epi bits: 1=relu, 2=residual-add, 4=rna output. bias applied if non-null.
#define NST 3
#define SSTRIDE 36
#define STAGE_F (2*128*SSTRIDE)
#define TC_SMEM (NST*STAGE_F*4)          // 110592 bytes

__device__ __forceinline__ void load_chunk(const float* __restrict__ A, int lda,
                                           const float* __restrict__ Bm, int ldb,
                                           uint32_t sA, uint32_t sB,
                                           int m0, int n0, int k0, int tid) {
    #pragma unroll
    for (int t = 0; t < 4; t++) {
        int seg = tid + t * 256;
        int row = seg >> 3, kq = seg & 7;
        cp_async16(sA + (uint32_t)(row * (SSTRIDE*4) + kq * 16),
                   A + (long long)(m0 + row) * lda + k0 + kq * 4);
    }
    #pragma unroll
    for (int t = 0; t < 4; t++) {
        int seg = tid + t * 256;
        int row = seg >> 3, kq = seg & 7;
        cp_async16(sB + (uint32_t)(row * (SSTRIDE*4) + kq * 16),
                   Bm + (long long)(n0 + row) * ldb + k0 + kq * 4);
    }
}

__global__ void __launch_bounds__(256, 2)
tc_gemm(const float* __restrict__ A, int lda,
        const float* __restrict__ Bm, int ldb,
        float* __restrict__ C, int ldc,
        int K, const float* __restrict__ bias, int epi) {
    int m0 = blockIdx.y * 128, n0 = blockIdx.x * 128;
    int nchunks = K >> 5;

    extern __shared__ float sm[];
    uint32_t sb = smem_u32(sm);
    int tid = threadIdx.x, wid = tid >> 5, lane = tid & 31;
    int wm = wid & 1, wn = wid >> 1;       // 2 x 4 warp grid; warp tile 64x32
    int lr = lane >> 2, lc = lane & 3;

    float acc[4][4][4];
    #pragma unroll
    for (int i = 0; i < 4; i++)
        #pragma unroll
        for (int j = 0; j < 4; j++)
            #pragma unroll
            for (int e = 0; e < 4; e++) acc[i][j][e] = 0.0f;

    #pragma unroll
    for (int s = 0; s < NST - 1; s++) {
        if (s < nchunks)
            load_chunk(A, lda, Bm, ldb, sb + s * (STAGE_F*4), sb + s * (STAGE_F*4) + 128*SSTRIDE*4,
                       m0, n0, s * 32, tid);
        asm volatile("cp.async.commit_group;" ::: "memory");
    }

    for (int c = 0; c < nchunks; c++) {
        asm volatile("cp.async.wait_group %0;" :: "n"(NST - 2) : "memory");
        __syncthreads();            // single barrier per chunk: separates prior
                                    // MMA reads of the stage we refill below

        int cn = c + NST - 1;
        if (cn < nchunks) {
            int sn = cn % NST;
            load_chunk(A, lda, Bm, ldb, sb + sn * (STAGE_F*4), sb + sn * (STAGE_F*4) + 128*SSTRIDE*4,
                       m0, n0, cn * 32, tid);
        }
        asm volatile("cp.async.commit_group;" ::: "memory");

        const float* As = sm + (c % NST) * STAGE_F;
        const float* Bs = As + 128 * SSTRIDE;

        #pragma unroll
        for (int ks = 0; ks < 4; ks++) {
            uint32_t afr[4][4], bfr[4][2];
            #pragma unroll
            for (int i = 0; i < 4; i++) {
                const float* ab = As + (wm * 64 + i * 16 + lr) * SSTRIDE + ks * 8 + lc;
                afr[i][0] = __float_as_uint(ab[0]);
                afr[i][1] = __float_as_uint(ab[8 * SSTRIDE]);
                afr[i][2] = __float_as_uint(ab[4]);
                afr[i][3] = __float_as_uint(ab[8 * SSTRIDE + 4]);
            }
            #pragma unroll
            for (int j = 0; j < 4; j++) {
                const float* bb = Bs + (wn * 32 + j * 8 + lr) * SSTRIDE + ks * 8 + lc;
                bfr[j][0] = __float_as_uint(bb[0]);
                bfr[j][1] = __float_as_uint(bb[4]);
            }
            #pragma unroll
            for (int i = 0; i < 4; i++)
                #pragma unroll
                for (int j = 0; j < 4; j++)
                    mma_tf32(acc[i][j], afr[i], bfr[j]);
        }
        // no trailing sync: next iteration's top sync provides the hazard barrier
    }

    #pragma unroll
    for (int i = 0; i < 4; i++) {
        #pragma unroll
        for (int half = 0; half < 2; half++) {
            int m = m0 + wm * 64 + i * 16 + half * 8 + lr;
            float* crow = C + (long long)m * ldc;
            #pragma unroll
            for (int j = 0; j < 4; j++) {
                int n = n0 + wn * 32 + j * 8 + lc * 2;
                float v0 = acc[i][j][half * 2 + 0];
                float v1 = acc[i][j][half * 2 + 1];
                if (bias) { v0 += bias[n]; v1 += bias[n + 1]; }
                if (epi & 1) { v0 = fmaxf(v0, 0.0f); v1 = fmaxf(v1, 0.0f); }
                if (epi & 2) { v0 += crow[n]; v1 += crow[n + 1]; }
                if (epi & 4) { v0 = rna_tf32(v0); v1 = rna_tf32(v1); }
                *(float2*)(crow + n) = make_float2(v0, v1);
            }
        }
    }
}

// ---------------- tf32 mma.sync GEMM (128x256 tile, warp tile 64x64) ----------------
// grid: (M/128, N/256) -- m-blocks vary FASTEST so a wave shares few B columns (L2 reuse)
#define WNST 3
#define WSTAGE_F ((128+256)*SSTRIDE)
#define TCW_SMEM (WNST*WSTAGE_F*4)         // 165888 bytes

__device__ __forceinline__ void load_chunk_w(const float* __restrict__ A, int lda,
                                             const float* __restrict__ Bm, int ldb,
                                             uint32_t sA, uint32_t sB,
                                             int m0, int n0, int k0, int tid) {
    #pragma unroll
    for (int t = 0; t < 4; t++) {
        int seg = tid + t * 256;
        int row = seg >> 3, kq = seg & 7;
        cp_async16(sA + (uint32_t)(row * (SSTRIDE*4) + kq * 16),
                   A + (long long)(m0 + row) * lda + k0 + kq * 4);
    }
    #pragma unroll
    for (int t = 0; t < 8; t++) {
        int seg = tid + t * 256;
        int row = seg >> 3, kq = seg & 7;
        cp_async16(sB + (uint32_t)(row * (SSTRIDE*4) + kq * 16),
                   Bm + (long long)(n0 + row) * ldb + k0 + kq * 4);
    }
}

__global__ void __launch_bounds__(256, 1)
tc_gemm_wide(const float* __restrict__ A, int lda,
             const float* __restrict__ Bm, int ldb,
             float* __restrict__ C, int ldc,
             int K, const float* __restrict__ bias, int epi) {
    int m0 = blockIdx.x * 128, n0 = blockIdx.y * 256;   // m fastest
    int nchunks = K >> 5;

    extern __shared__ float sm[];
    uint32_t sb = smem_u32(sm);
    int tid = threadIdx.x, wid = tid >> 5, lane = tid & 31;
    int wm = wid & 1, wn = wid >> 1;       // 2 x 4 warp grid; warp tile 64x64
    int lr = lane >> 2, lc = lane & 3;

    float acc[4][8][4];
    #pragma unroll
    for (int i = 0; i < 4; i++)
        #pragma unroll
        for (int j = 0; j < 8; j++)
            #pragma unroll
            for (int e = 0; e < 4; e++) acc[i][j][e] = 0.0f;

    #pragma unroll
    for (int s = 0; s < WNST - 1; s++) {
        if (s < nchunks)
            load_chunk_w(A, lda, Bm, ldb, sb + s * (WSTAGE_F*4), sb + s * (WSTAGE_F*4) + 128*SSTRIDE*4,
                         m0, n0, s * 32, tid);
        asm volatile("cp.async.commit_group;" ::: "memory");
    }

    for (int c = 0; c < nchunks; c++) {
        asm volatile("cp.async.wait_group %0;" :: "n"(WNST - 2) : "memory");
        __syncthreads();            // single barrier per chunk

        int cn = c + WNST - 1;
        if (cn < nchunks) {
            int sn = cn % WNST;
            load_chunk_w(A, lda, Bm, ldb, sb + sn * (WSTAGE_F*4), sb + sn * (WSTAGE_F*4) + 128*SSTRIDE*4,
                         m0, n0, cn * 32, tid);
        }
        asm volatile("cp.async.commit_group;" ::: "memory");

        const float* As = sm + (c % WNST) * WSTAGE_F;
        const float* Bs = As + 128 * SSTRIDE;

        #pragma unroll
        for (int ks = 0; ks < 4; ks++) {
            uint32_t afr[4][4];
            #pragma unroll
            for (int i = 0; i < 4; i++) {
                const float* ab = As + (wm * 64 + i * 16 + lr) * SSTRIDE + ks * 8 + lc;
                afr[i][0] = __float_as_uint(ab[0]);
                afr[i][1] = __float_as_uint(ab[8 * SSTRIDE]);
                afr[i][2] = __float_as_uint(ab[4]);
                afr[i][3] = __float_as_uint(ab[8 * SSTRIDE + 4]);
            }
            #pragma unroll
            for (int j = 0; j < 8; j++) {
                uint32_t bfr[2];
                const float* bb = Bs + (wn * 64 + j * 8 + lr) * SSTRIDE + ks * 8 + lc;
                bfr[0] = __float_as_uint(bb[0]);
                bfr[1] = __float_as_uint(bb[4]);
                #pragma unroll
                for (int i = 0; i < 4; i++)
                    mma_tf32(acc[i][j], afr[i], bfr);
            }
        }
        // no trailing sync
    }

    #pragma unroll
    for (int i = 0; i < 4; i++) {
        #pragma unroll
        for (int half = 0; half < 2; half++) {
            int m = m0 + wm * 64 + i * 16 + half * 8 + lr;
            float* crow = C + (long long)m * ldc;
            #pragma unroll
            for (int j = 0; j < 8; j++) {
                int n = n0 + wn * 64 + j * 8 + lc * 2;
                float v0 = acc[i][j][half * 2 + 0];
                float v1 = acc[i][j][half * 2 + 1];
                if (bias) { v0 += bias[n]; v1 += bias[n + 1]; }
                if (epi & 1) { v0 = fmaxf(v0, 0.0f); v1 = fmaxf(v1, 0.0f); }
                if (epi & 2) { v0 += crow[n]; v1 += crow[n + 1]; }
                if (epi & 4) { v0 = rna_tf32(v0); v1 = rna_tf32(v1); }
                *(float2*)(crow + n) = make_float2(v0, v1);
            }
        }
    }
}

// ---------------- fused flash attention ----------------
#define FSTR 132
#define FQ_OFF 0
#define FK_OFF (128*FSTR)
#define FV_OFF (2*128*FSTR)
#define FRED_OFF (3*128*FSTR)
#define FM_OFF  (FRED_OFF + 512)
#define FL_OFF  (FM_OFF + 128)
#define FC_OFF  (FL_OFF + 128)
#define FLASH_SMEM ((FC_OFF + 128)*4)

__device__ __forceinline__ void load_tile128(uint32_t sdst, const float* __restrict__ g,
                                             int ldg, int tid) {
    #pragma unroll
    for (int t = 0; t < 16; t++) {
        int seg = tid + t * 256;
        int row = seg >> 5, kq = seg & 31;
        cp_async16(sdst + (uint32_t)(row * (FSTR*4) + kq * 16),
                   g + (long long)row * ldg + kq * 4);
    }
}

__global__ void __launch_bounds__(256, 1)
flash_kernel(const float* __restrict__ qkv, const float* __restrict__ vT,
             float* __restrict__ o) {
    int i = 7 - blockIdx.x;
    int z = blockIdx.y;
    int b = z / HH, h = z - b * HH;

    extern __shared__ float fs[];
    uint32_t sb = smem_u32(fs);
    int tid = threadIdx.x, wid = tid >> 5, lane = tid & 31;
    int wm = wid & 1, wn = wid >> 1;
    int lr = lane >> 2, lc = lane & 3;

    const float* qg = qkv + ((long long)(b * TT + i * 128)) * QKV3 + h * HD;
    const float* kg = qkv + ((long long)(b * TT)) * QKV3 + EE + h * HD;
    const float* vg = vT + (long long)z * HD * TT;

    load_tile128(sb + FQ_OFF*4, qg, QKV3, tid);
    asm volatile("cp.async.commit_group;" ::: "memory");

    if (tid < 128) { fs[FM_OFF + tid] = -1e30f; fs[FL_OFF + tid] = 0.0f; }

    float oacc[4][4][4];
    #pragma unroll
    for (int a = 0; a < 4; a++)
        #pragma unroll
        for (int j = 0; j < 4; j++)
            #pragma unroll
            for (int e = 0; e < 4; e++) oacc[a][j][e] = 0.0f;

    const float scale = 0.0883883476483184406f;

    for (int j = 0; j <= i; j++) {
        load_tile128(sb + FK_OFF*4, kg + (long long)(j * 128) * QKV3, QKV3, tid);
        asm volatile("cp.async.commit_group;" ::: "memory");
        load_tile128(sb + FV_OFF*4, vg + j * 128, TT, tid);
        asm volatile("cp.async.commit_group;" ::: "memory");
        asm volatile("cp.async.wait_group 1;" ::: "memory");
        __syncthreads();

        float sacc[4][4][4];
        #pragma unroll
        for (int a = 0; a < 4; a++)
            #pragma unroll
            for (int jt = 0; jt < 4; jt++)
                #pragma unroll
                for (int e = 0; e < 4; e++) sacc[a][jt][e] = 0.0f;

        const float* Qs = fs + FQ_OFF;
        const float* Ks = fs + FK_OFF;
        #pragma unroll
        for (int kk = 0; kk < 16; kk++) {
            uint32_t afr[4][4], bfr[4][2];
            #pragma unroll
            for (int a = 0; a < 4; a++) {
                const float* ab = Qs + (wm * 64 + a * 16 + lr) * FSTR + kk * 8 + lc;
                afr[a][0] = __float_as_uint(ab[0]);
                afr[a][1] = __float_as_uint(ab[8 * FSTR]);
                afr[a][2] = __float_as_uint(ab[4]);
                afr[a][3] = __float_as_uint(ab[8 * FSTR + 4]);
            }
            #pragma unroll
            for (int jt = 0; jt < 4; jt++) {
                const float* bb = Ks + (wn * 32 + jt * 8 + lr) * FSTR + kk * 8 + lc;
                bfr[jt][0] = __float_as_uint(bb[0]);
                bfr[jt][1] = __float_as_uint(bb[4]);
            }
            #pragma unroll
            for (int a = 0; a < 4; a++)
                #pragma unroll
                for (int jt = 0; jt < 4; jt++)
                    mma_tf32(sacc[a][jt], afr[a], bfr[jt]);
        }

        float pmax[4][2];
        #pragma unroll
        for (int a = 0; a < 4; a++) { pmax[a][0] = -1e30f; pmax[a][1] = -1e30f; }
        #pragma unroll
        for (int a = 0; a < 4; a++)
            #pragma unroll
            for (int jt = 0; jt < 4; jt++)
                #pragma unroll
                for (int e = 0; e < 4; e++) {
                    int half = e >> 1;
                    float sv = sacc[a][jt][e] * scale;
                    if (j == i) {
                        int mr = wm * 64 + a * 16 + half * 8 + lr;
                        int nc = wn * 32 + jt * 8 + 2 * lc + (e & 1);
                        if (nc > mr) sv = -1e30f;
                    }
                    sacc[a][jt][e] = sv;
                    pmax[a][half] = fmaxf(pmax[a][half], sv);
                }
        #pragma unroll
        for (int a = 0; a < 4; a++)
            #pragma unroll
            for (int half = 0; half < 2; half++) {
                float v = pmax[a][half];
                v = fmaxf(v, __shfl_xor_sync(0xFFFFFFFF, v, 1));
                v = fmaxf(v, __shfl_xor_sync(0xFFFFFFFF, v, 2));
                pmax[a][half] = v;
            }
        if (lc == 0) {
            #pragma unroll
            for (int a = 0; a < 4; a++)
                #pragma unroll
                for (int half = 0; half < 2; half++)
                    fs[FRED_OFF + (wm * 64 + a * 16 + half * 8 + lr) * 4 + wn] = pmax[a][half];
        }
        __syncthreads();

        if (wn == 0 && lc == 0) {
            #pragma unroll
            for (int a = 0; a < 4; a++)
                #pragma unroll
                for (int half = 0; half < 2; half++) {
                    int r = wm * 64 + a * 16 + half * 8 + lr;
                    float m4 = fmaxf(fmaxf(fs[FRED_OFF + r*4], fs[FRED_OFF + r*4 + 1]),
                                     fmaxf(fs[FRED_OFF + r*4 + 2], fs[FRED_OFF + r*4 + 3]));
                    float mold = fs[FM_OFF + r];
                    float mnew = fmaxf(mold, m4);
                    fs[FC_OFF + r] = __expf(mold - mnew);
                    fs[FM_OFF + r] = mnew;
                }
        }
        __syncthreads();

        float mn[4][2], cr[4][2], psum[4][2];
        #pragma unroll
        for (int a = 0; a < 4; a++)
            #pragma unroll
            for (int half = 0; half < 2; half++) {
                int r = wm * 64 + a * 16 + half * 8 + lr;
                mn[a][half] = fs[FM_OFF + r];
                cr[a][half] = fs[FC_OFF + r];
                psum[a][half] = 0.0f;
            }
        float* Ps = fs + FK_OFF;
        #pragma unroll
        for (int a = 0; a < 4; a++)
            #pragma unroll
            for (int jt = 0; jt < 4; jt++) {
                #pragma unroll
                for (int half = 0; half < 2; half++) {
                    float p0 = __expf(sacc[a][jt][half*2 + 0] - mn[a][half]);
                    float p1 = __expf(sacc[a][jt][half*2 + 1] - mn[a][half]);
                    psum[a][half] += p0 + p1;
                    oacc[a][jt][half*2 + 0] *= cr[a][half];
                    oacc[a][jt][half*2 + 1] *= cr[a][half];
                    int r = wm * 64 + a * 16 + half * 8 + lr;
                    int nc = wn * 32 + jt * 8 + 2 * lc;
                    *(float2*)(Ps + r * FSTR + nc) = make_float2(rna_tf32(p0), rna_tf32(p1));
                }
            }
        #pragma unroll
        for (int a = 0; a < 4; a++)
            #pragma unroll
            for (int half = 0; half < 2; half++) {
                float v = psum[a][half];
                v += __shfl_xor_sync(0xFFFFFFFF, v, 1);
                v += __shfl_xor_sync(0xFFFFFFFF, v, 2);
                psum[a][half] = v;
            }
        if (lc == 0) {
            #pragma unroll
            for (int a = 0; a < 4; a++)
                #pragma unroll
                for (int half = 0; half < 2; half++)
                    fs[FRED_OFF + (wm * 64 + a * 16 + half * 8 + lr) * 4 + wn] = psum[a][half];
        }
        asm volatile("cp.async.wait_group 0;" ::: "memory");
        __syncthreads();

        if (wn == 0 && lc == 0) {
            #pragma unroll
            for (int a = 0; a < 4; a++)
                #pragma unroll
                for (int half = 0; half < 2; half++) {
                    int r = wm * 64 + a * 16 + half * 8 + lr;
                    float s4 = fs[FRED_OFF + r*4] + fs[FRED_OFF + r*4 + 1]
                             + fs[FRED_OFF + r*4 + 2] + fs[FRED_OFF + r*4 + 3];
                    fs[FL_OFF + r] = fs[FL_OFF + r] * fs[FC_OFF + r] + s4;
                }
        }

        const float* Vs = fs + FV_OFF;
        #pragma unroll
        for (int kk = 0; kk < 16; kk++) {
            uint32_t afr[4][4], bfr[4][2];
            #pragma unroll
            for (int a = 0; a < 4; a++) {
                const float* ab = Ps + (wm * 64 + a * 16 + lr) * FSTR + kk * 8 + lc;
                afr[a][0] = __float_as_uint(ab[0]);
                afr[a][1] = __float_as_uint(ab[8 * FSTR]);
                afr[a][2] = __float_as_uint(ab[4]);
                afr[a][3] = __float_as_uint(ab[8 * FSTR + 4]);
            }
            #pragma unroll
            for (int jt = 0; jt < 4; jt++) {
                const float* bb = Vs + (wn * 32 + jt * 8 + lr) * FSTR + kk * 8 + lc;
                bfr[jt][0] = __float_as_uint(bb[0]);
                bfr[jt][1] = __float_as_uint(bb[4]);
            }
            #pragma unroll
            for (int a = 0; a < 4; a++)
                #pragma unroll
                for (int jt = 0; jt < 4; jt++)
                    mma_tf32(oacc[a][jt], afr[a], bfr[jt]);
        }
        __syncthreads();
    }

    float* og = o + ((long long)(b * TT + i * 128)) * EE + h * HD;
    #pragma unroll
    for (int a = 0; a < 4; a++)
        #pragma unroll
        for (int half = 0; half < 2; half++) {
            int r = wm * 64 + a * 16 + half * 8 + lr;
            float linv = 1.0f / fs[FL_OFF + r];
            float* orow = og + (long long)r * EE;
            #pragma unroll
            for (int jt = 0; jt < 4; jt++) {
                int nc = wn * 32 + jt * 8 + 2 * lc;
                float v0 = rna_tf32(oacc[a][jt][half*2 + 0] * linv);
                float v1 = rna_tf32(oacc[a][jt][half*2 + 1] * linv);
                *(float2*)(orow + nc) = make_float2(v0, v1);
            }
        }
}

// ---------------- per-row NLL via streaming logsumexp ----------------
__global__ void loss_rows_kernel(const float* __restrict__ logits,
                                 const void* __restrict__ tgtv,
                                 float* __restrict__ nll) {
    int r = blockIdx.x;
    const float* row = logits + (long long)r * VV;
    int tid = threadIdx.x;
    float m = -1e30f, s = 0.0f;
    for (int j = tid; j < VV; j += 256) {
        float v = row[j];
        if (v > m) { s = s * __expf(m - v) + 1.0f; m = v; }
        else       { s += __expf(v - m); }
    }
    __shared__ float sm[256], ss[256];
    sm[tid] = m; ss[tid] = s; __syncthreads();
    for (int k = 128; k > 0; k >>= 1) {
        if (tid < k) {
            float m2 = sm[tid + k], s2 = ss[tid + k];
            float mm = fmaxf(sm[tid], m2);
            ss[tid] = ss[tid] * __expf(sm[tid] - mm) + s2 * __expf(m2 - mm);
            sm[tid] = mm;
        }
        __syncthreads();
    }
    if (tid == 0) {
        long long t = load_token(tgtv, r, g_is64_tgt);
        nll[r] = (sm[0] + logf(ss[0])) - row[t];
    }
}

__global__ void loss_final_kernel(const float* __restrict__ nll, float* __restrict__ out, int n) {
    __shared__ float red[256];
    int tid = threadIdx.x;
    float s = 0.0f;
    for (int j = tid; j < BT; j += 256) s += nll[j];
    red[tid] = s; __syncthreads();
    for (int k = 128; k > 0; k >>= 1) { if (tid < k) red[tid] += red[tid + k]; __syncthreads(); }
    float mean = red[0] * (1.0f / BT);
    for (int i = tid; i < n; i += 256) out[i] = mean;
}

// ---------------- host-side helpers ----------------
static void tcg(const float* A, int lda, const float* Bm, int ldb,
                float* C, int ldc, int M, int N, int K,
                const float* bias, int epi) {
    dim3 grid(N / 128, M / 128, 1);
    tc_gemm<<<grid, 256, TC_SMEM>>>(A, lda, Bm, ldb, C, ldc, K, bias, epi);
}

static void tcgw(const float* A, int lda, const float* Bm, int ldb,
                 float* C, int ldc, int M, int N, int K,
                 const float* bias, int epi) {
    dim3 grid(M / 128, N / 256, 1);   // m fastest
    tc_gemm_wide<<<grid, 256, TCW_SMEM>>>(A, lda, Bm, ldb, C, ldc, K, bias, epi);
}

static void tr(const float* s, float* d, int R, int C, int srs, int drs,
               long long sB, long long sH, long long dB, long long dH,
               int Hdiv, int Z) {
    dim3 grid(C / 32, R / 32, Z), blk(32, 8);
    transpose_kernel<<<grid, blk>>>(s, d, srs, drs, sB, sH, dB, dH, Hdiv);
}

extern "C" void kernel_launch(void* const* d_in, const int* in_sizes, int n_in,
                              void* d_out, int out_size) {
    const void*  idx  = d_in[0];
    const void*  tgt  = d_in[1];
    const float* tok  = (const float*)d_in[2];
    const float* pos  = (const float*)d_in[3];
    const float* Wq   = (const float*)d_in[4];
    const float* bq   = (const float*)d_in[5];
    const float* Wk   = (const float*)d_in[6];
    const float* bk   = (const float*)d_in[7];
    const float* Wv   = (const float*)d_in[8];
    const float* bv   = (const float*)d_in[9];
    const float* Wo   = (const float*)d_in[10];
    const float* bo   = (const float*)d_in[11];
    const float* w1   = (const float*)d_in[12];
    const float* b1   = (const float*)d_in[13];
    const float* w2   = (const float*)d_in[14];
    const float* b2   = (const float*)d_in[15];
    const float* ln1s = (const float*)d_in[16];
    const float* ln1b = (const float*)d_in[17];
    const float* ln2s = (const float*)d_in[18];
    const float* ln2b = (const float*)d_in[19];
    const float* lnfs = (const float*)d_in[20];
    const float* lnfb = (const float*)d_in[21];
    const float* Wlm  = (const float*)d_in[22];
    const float* blm  = (const float*)d_in[23];

    float *x, *h, *qkv, *o, *ff, *nll, *logits_fb;
    float *wqkvT, *bqkv, *woT, *w1T, *w2T, *wlmT, *vT;
    cudaGetSymbolAddress((void**)&x,    g_x);
    cudaGetSymbolAddress((void**)&h,    g_h);
    cudaGetSymbolAddress((void**)&qkv,  g_qkv);
    cudaGetSymbolAddress((void**)&o,    g_o);
    cudaGetSymbolAddress((void**)&ff,   g_ff);
    cudaGetSymbolAddress((void**)&nll,  g_nll);
    cudaGetSymbolAddress((void**)&logits_fb, g_logits_fb);
    cudaGetSymbolAddress((void**)&wqkvT, g_wqkvT);
    cudaGetSymbolAddress((void**)&bqkv,  g_bqkv);
    cudaGetSymbolAddress((void**)&woT,  g_woT);
    cudaGetSymbolAddress((void**)&w1T,  g_w1T);
    cudaGetSymbolAddress((void**)&w2T,  g_w2T);
    cudaGetSymbolAddress((void**)&wlmT, g_wlmT);
    cudaGetSymbolAddress((void**)&vT,   g_vT);

    cudaFuncSetAttribute(tc_gemm, cudaFuncAttributeMaxDynamicSharedMemorySize, TC_SMEM);
    cudaFuncSetAttribute(tc_gemm_wide, cudaFuncAttributeMaxDynamicSharedMemorySize, TCW_SMEM);
    cudaFuncSetAttribute(flash_kernel, cudaFuncAttributeMaxDynamicSharedMemorySize, FLASH_SMEM);

    float* out = (float*)d_out;
    float* logits = ((long long)out_size >= BTV) ? out : logits_fb;
    float* lossPtr = nullptr;
    int nLoss = 0;
    if ((long long)out_size > BTV) { lossPtr = out + BTV; nLoss = out_size - (int)BTV; }
    else if ((long long)out_size < BTV) { lossPtr = out; nLoss = out_size; }

    const long long E2   = (long long)EE * EE;
    const long long EF   = (long long)EE * FF;
    const long long LQ3  = (long long)QKV3 * EE;
    const long long ZVT  = (long long)HD * TT;

    // prologue arranged so the QKV GEMM is an early launch (ncu -s 5 target)
    detect_kernel<<<1, 32>>>((const int*)idx, (const int*)tgt);                 // 0
    embed_kernel<<<BT, 256>>>(idx, tok, pos, x);                                // 1
    {
        dim3 grid(EE / 32, EE / 32, 3 * LL + 1), blk(32, 8);
        qkv_prep_kernel<<<grid, blk>>>(Wq, Wk, Wv, bq, bk, bv, wqkvT, bqkv);    // 2
    }
    layernorm_kernel<<<BT, 256>>>(x, h, ln1s, ln1b);                            // 3
    tcgw(h, EE, wqkvT, EE, qkv, QKV3, BT, QKV3, EE, bqkv, 4);                   // 4 (QKV l=0)
    tr(qkv + 2 * EE, vT, TT, HD, QKV3, TT,
       (long long)TT * QKV3, HD, (long long)HH * ZVT, ZVT, HH, BB * HH);        // 5
    flash_kernel<<<dim3(8, BB * HH), 256, FLASH_SMEM>>>(qkv, vT, o);            // 6

    // remaining weight prep (before first use; in-order stream)
    tr(Wo,  woT,  EE, EE, EE, EE, E2, 0, E2, 0, 1, LL);
    tr(w1,  w1T,  EE, FF, FF, EE, EF, 0, EF, 0, 1, LL);
    tr(w2,  w2T,  FF, EE, EE, FF, EF, 0, EF, 0, 1, LL);
    tr(Wlm, wlmT, EE, VV, VV, EE, 0, 0, 0, 0, 1, 1);

    // finish layer 0
    tcg(o, EE, woT, EE, x, EE, BT, EE, EE, bo, 2);
    layernorm_kernel<<<BT, 256>>>(x, h, ln2s, ln2b);
    tcgw(h, EE, w1T, EE, ff, FF, BT, FF, EE, b1, 5);
    tcg(ff, FF, w2T, FF, x, EE, BT, EE, FF, b2, 2);

    for (int l = 1; l < LL; l++) {
        layernorm_kernel<<<BT, 256>>>(x, h, ln1s + l * EE, ln1b + l * EE);
        tcgw(h, EE, wqkvT + l * LQ3, EE, qkv, QKV3, BT, QKV3, EE,
             bqkv + l * QKV3, 4);
        tr(qkv + 2 * EE, vT, TT, HD, QKV3, TT,
           (long long)TT * QKV3, HD, (long long)HH * ZVT, ZVT, HH, BB * HH);
        flash_kernel<<<dim3(8, BB * HH), 256, FLASH_SMEM>>>(qkv, vT, o);
        tcg(o, EE, woT + l * E2, EE, x, EE, BT, EE, EE, bo + l * EE, 2);
        layernorm_kernel<<<BT, 256>>>(x, h, ln2s + l * EE, ln2b + l * EE);
        tcgw(h, EE, w1T + l * EF, EE, ff, FF, BT, FF, EE, b1 + (long long)l * FF, 5);
        tcg(ff, FF, w2T + l * EF, FF, x, EE, BT, EE, FF, b2 + l * EE, 2);
    }

    // final LN + LM head (wide tile, m-fastest grid for L2 reuse of B)
    layernorm_kernel<<<BT, 256>>>(x, h, lnfs, lnfb);
    tcgw(h, EE, wlmT, EE, logits, VV, BT, VV, EE, blm, 0);

    // loss
    loss_rows_kernel<<<BT, 256>>>(logits, tgt, nll);
    if (nLoss > 0)
        loss_final_kernel<<<1, 256>>>(nll, lossPtr, nLoss);
}

// round 9
// speedup vs baseline: 5.4958x; 1.5589x over previous
#include <cuda_runtime.h>
#include <cuda_fp16.h>
#include <math.h>
#include <stdint.h>

// ---------------- problem constants ----------------
#define BB 4
#define TT 1024
#define EE 768
#define LL 6
#define HH 6
#define HD 128
#define VV 32000
#define FF (4*EE)          // 3072
#define BT (BB*TT)         // 4096
#define BTV ((long long)BT*VV)
#define QKV3 (3*EE)        // 2304

// ---------------- scratch (device globals; no allocations allowed) ----------------
__device__ float  g_x  [BT*EE];                     // residual stream (fp32)
__device__ __half g_hh [BT*EE];                     // LN output (GEMM A)
__device__ __half g_qkvh[(long long)BT*QKV3];
__device__ __half g_vTh[(long long)BB*HH*HD*TT];
__device__ __half g_oh [BT*EE];
__device__ __half g_ffh[BT*FF];
__device__ float  g_nll[BT];
__device__ float  g_logits_fb[BTV];
__device__ int    g_is64_idx;
__device__ int    g_is64_tgt;
// fp16 K-major [N,K] weights
__device__ __half g_wqkvTh[(long long)LL*QKV3*EE];
__device__ float  g_bqkv  [LL*QKV3];
__device__ __half g_woTh [LL*EE*EE];
__device__ __half g_w1Th [(long long)LL*EE*FF];
__device__ __half g_w2Th [(long long)LL*EE*FF];
__device__ __half g_wlmTh[(long long)EE*VV];

// ---------------- small helpers ----------------
__device__ __forceinline__ uint32_t smem_u32(const void* p) {
    uint32_t a;
    asm("{ .reg .u64 t; cvta.to.shared.u64 t, %1; cvt.u32.u64 %0, t; }" : "=r"(a) : "l"(p));
    return a;
}

__device__ __forceinline__ void cp_async16(uint32_t saddr, const void* gaddr) {
    asm volatile("cp.async.cg.shared.global [%0], [%1], 16;" :: "r"(saddr), "l"(gaddr));
}

// fp16 mma.sync: D(16x8,f32) += A(16x16,f16) * B(16x8,f16), row.col
__device__ __forceinline__ void mma_f16(float* c, const uint32_t* a, const uint32_t* b) {
    asm volatile(
        "mma.sync.aligned.m16n8k16.row.col.f32.f16.f16.f32 "
        "{%0,%1,%2,%3}, {%4,%5,%6,%7}, {%8,%9}, {%0,%1,%2,%3};"
        : "+f"(c[0]), "+f"(c[1]), "+f"(c[2]), "+f"(c[3])
        : "r"(a[0]), "r"(a[1]), "r"(a[2]), "r"(a[3]), "r"(b[0]), "r"(b[1]));
}

// ---------------- int64-vs-int32 detection ----------------
__global__ void detect_kernel(const int* __restrict__ idx, const int* __restrict__ tgt) {
    if (threadIdx.x == 0 && blockIdx.x == 0) {
        int a = 1, b = 1;
        for (int i = 1; i < 129; i += 2) {
            if (idx[i] != 0) a = 0;
            if (tgt[i] != 0) b = 0;
        }
        g_is64_idx = a;
        g_is64_tgt = b;
    }
}

__device__ __forceinline__ long long load_token(const void* p, int r, int is64) {
    if (is64) return ((const long long*)p)[r];
    return (long long)((const int*)p)[r];
}

// ---------------- embedding ----------------
__global__ void embed_kernel(const void* __restrict__ idxv,
                             const float* __restrict__ tok,
                             const float* __restrict__ pos,
                             float* __restrict__ x) {
    int r = blockIdx.x;
    long long token = load_token(idxv, r, g_is64_idx);
    int t = r % TT;
    const float* te = tok + token * EE;
    const float* pe = pos + (long long)t * EE;
    float* xr = x + (long long)r * EE;
    for (int e = threadIdx.x; e < EE; e += blockDim.x)
        xr[e] = te[e] + pe[e];
}

// ---------------- layernorm (fp16 output: always feeds a GEMM) ----------------
__global__ void layernorm_kernel(const float* __restrict__ x, __half* __restrict__ y,
                                 const float* __restrict__ s, const float* __restrict__ b) {
    int r = blockIdx.x;
    const float* row = x + (long long)r * EE;
    __half* out = y + (long long)r * EE;
    int tid = threadIdx.x;
    __shared__ float red[256];

    float v0 = row[tid], v1 = row[tid + 256], v2 = row[tid + 512];
    red[tid] = v0 + v1 + v2; __syncthreads();
    for (int k = 128; k > 0; k >>= 1) { if (tid < k) red[tid] += red[tid + k]; __syncthreads(); }
    float mean = red[0] * (1.0f / EE);
    __syncthreads();

    float d0 = v0 - mean, d1 = v1 - mean, d2 = v2 - mean;
    red[tid] = d0*d0 + d1*d1 + d2*d2; __syncthreads();
    for (int k = 128; k > 0; k >>= 1) { if (tid < k) red[tid] += red[tid + k]; __syncthreads(); }
    float inv = rsqrtf(red[0] * (1.0f / EE) + 1e-5f);

    out[tid      ] = __float2half_rn(d0 * inv * s[tid      ] + b[tid      ]);
    out[tid + 256] = __float2half_rn(d1 * inv * s[tid + 256] + b[tid + 256]);
    out[tid + 512] = __float2half_rn(d2 * inv * s[tid + 512] + b[tid + 512]);
}

// ---------------- transposes ----------------
// float -> half (weights), batched over z
__global__ void transpose_f2h_kernel(const float* __restrict__ src, __half* __restrict__ dst,
                                     int srs, int drs, long long sZ, long long dZ) {
    int z = blockIdx.z;
    src += z * sZ;
    dst += z * dZ;
    __shared__ float tile[32][33];
    int c0 = blockIdx.x * 32, r0 = blockIdx.y * 32;
    int tx = threadIdx.x, ty = threadIdx.y;
    #pragma unroll
    for (int i = 0; i < 32; i += 8)
        tile[ty + i][tx] = src[(long long)(r0 + ty + i) * srs + c0 + tx];
    __syncthreads();
    #pragma unroll
    for (int i = 0; i < 32; i += 8)
        dst[(long long)(c0 + ty + i) * drs + r0 + tx] = __float2half_rn(tile[tx][ty + i]);
}

// half -> half (vT from qkv), z = (b,h) pairs via Hdiv
__global__ void transpose_h2h_kernel(const __half* __restrict__ src, __half* __restrict__ dst,
                                     int srs, int drs,
                                     long long sB, long long sH, long long dB, long long dH,
                                     int Hdiv) {
    int z = blockIdx.z, zb = z / Hdiv, zh = z - zb * Hdiv;
    src += zb * sB + zh * sH;
    dst += zb * dB + zh * dH;
    __shared__ float tile[32][33];
    int c0 = blockIdx.x * 32, r0 = blockIdx.y * 32;
    int tx = threadIdx.x, ty = threadIdx.y;
    #pragma unroll
    for (int i = 0; i < 32; i += 8)
        tile[ty + i][tx] = __half2float(src[(long long)(r0 + ty + i) * srs + c0 + tx]);
    __syncthreads();
    #pragma unroll
    for (int i = 0; i < 32; i += 8)
        dst[(long long)(c0 + ty + i) * drs + r0 + tx] = __float2half_rn(tile[tx][ty + i]);
}

// ---------------- fused QKV weight transpose + bias concat ----------------
__global__ void qkv_prep_kernel(const float* __restrict__ Wq, const float* __restrict__ Wk,
                                const float* __restrict__ Wv,
                                const float* __restrict__ bq, const float* __restrict__ bk,
                                const float* __restrict__ bv,
                                __half* __restrict__ wqkvT, float* __restrict__ bqkv) {
    int z = blockIdx.z;
    int tx = threadIdx.x, ty = threadIdx.y;
    if (z == 3 * LL) {
        int i = (blockIdx.y * gridDim.x + blockIdx.x) * 256 + ty * 32 + tx;
        if (i < LL * QKV3) {
            int l = i / QKV3, n = i - l * QKV3;
            float v;
            if (n < EE)          v = bq[l * EE + n];
            else if (n < 2*EE)   v = bk[l * EE + n - EE];
            else                 v = bv[l * EE + n - 2*EE];
            bqkv[i] = v;
        }
        return;
    }
    int s = z / LL, l = z - s * LL;
    const float* src = (s == 0 ? Wq : (s == 1 ? Wk : Wv)) + (long long)l * EE * EE;
    __half* dst = wqkvT + (long long)l * QKV3 * EE + (long long)s * EE * EE;
    __shared__ float tile[32][33];
    int c0 = blockIdx.x * 32, r0 = blockIdx.y * 32;
    #pragma unroll
    for (int i = 0; i < 32; i += 8)
        tile[ty + i][tx] = src[(long long)(r0 + ty + i) * EE + c0 + tx];
    __syncthreads();
    #pragma unroll
    for (int i = 0; i < 32; i += 8)
        dst[(long long)(c0 + ty + i) * EE + r0 + tx] = __float2half_rn(tile[tx][ty + i]);
}

// ---------------- fp16 mma.sync GEMM (128x128 tile, 2 CTAs/SM) ----------------
// C[m,n] = sum_k A[m,k] * B[n,k]   (A [M,K] K-major fp16, B [N,K] K-major fp16)
// K multiple of 32. grid (M/128, N/128) -- m fastest for L2 reuse of B.
// Output: Ch (fp16) if non-null, else Cf (fp32).
// epi bits: 1=relu, 2=residual-add (fp32 Cf read).  bias fp32 if non-null.
#define NST 3
#define SH 40                            // halfs per smem row (80 B, conflict-free)
#define STAGE_H (2*128*SH)               // halfs per stage (A+B)
#define TC_SMEM (NST*STAGE_H*2)          // 61440 bytes

__device__ __forceinline__ void load_chunk_h(const __half* __restrict__ A, int lda,
                                             const __half* __restrict__ Bm, int ldb,
                                             uint32_t sA, uint32_t sB,
                                             int m0, int n0, int k0, int tid) {
    #pragma unroll
    for (int t = 0; t < 2; t++) {
        int seg = tid + t * 256;              // 0..511
        int row = seg >> 2, kq = seg & 3;     // 4 x 16B per 64B row
        cp_async16(sA + (uint32_t)(row * (SH*2) + kq * 16),
                   A + (long long)(m0 + row) * lda + k0 + kq * 8);
    }
    #pragma unroll
    for (int t = 0; t < 2; t++) {
        int seg = tid + t * 256;
        int row = seg >> 2, kq = seg & 3;
        cp_async16(sB + (uint32_t)(row * (SH*2) + kq * 16),
                   Bm + (long long)(n0 + row) * ldb + k0 + kq * 8);
    }
}

__global__ void __launch_bounds__(256, 2)
tc_gemm_h(const __half* __restrict__ A, int lda,
          const __half* __restrict__ Bm, int ldb,
          float* __restrict__ Cf, __half* __restrict__ Ch, int ldc,
          int K, const float* __restrict__ bias, int epi) {
    int m0 = blockIdx.x * 128, n0 = blockIdx.y * 128;   // m fastest
    int nchunks = K >> 5;

    extern __shared__ __half smh[];
    uint32_t sb = smem_u32(smh);
    int tid = threadIdx.x, wid = tid >> 5, lane = tid & 31;
    int wm = wid & 1, wn = wid >> 1;       // 2 x 4 warp grid; warp tile 64x32
    int lr = lane >> 2, lc = lane & 3;

    float acc[4][4][4];
    #pragma unroll
    for (int i = 0; i < 4; i++)
        #pragma unroll
        for (int j = 0; j < 4; j++)
            #pragma unroll
            for (int e = 0; e < 4; e++) acc[i][j][e] = 0.0f;

    #pragma unroll
    for (int s = 0; s < NST - 1; s++) {
        if (s < nchunks)
            load_chunk_h(A, lda, Bm, ldb, sb + s * (STAGE_H*2), sb + s * (STAGE_H*2) + 128*SH*2,
                         m0, n0, s * 32, tid);
        asm volatile("cp.async.commit_group;" ::: "memory");
    }

    for (int c = 0; c < nchunks; c++) {
        asm volatile("cp.async.wait_group %0;" :: "n"(NST - 2) : "memory");
        __syncthreads();

        int cn = c + NST - 1;
        if (cn < nchunks) {
            int sn = cn % NST;
            load_chunk_h(A, lda, Bm, ldb, sb + sn * (STAGE_H*2), sb + sn * (STAGE_H*2) + 128*SH*2,
                         m0, n0, cn * 32, tid);
        }
        asm volatile("cp.async.commit_group;" ::: "memory");

        const __half* As = smh + (c % NST) * STAGE_H;
        const __half* Bs = As + 128 * SH;

        #pragma unroll
        for (int ks = 0; ks < 2; ks++) {          // two k16 steps per 32-K chunk
            uint32_t afr[4][4], bfr[4][2];
            #pragma unroll
            for (int i = 0; i < 4; i++) {
                const __half* ab = As + (wm * 64 + i * 16 + lr) * SH + ks * 16 + lc * 2;
                afr[i][0] = *(const uint32_t*)(ab);
                afr[i][1] = *(const uint32_t*)(ab + 8 * SH);
                afr[i][2] = *(const uint32_t*)(ab + 8);
                afr[i][3] = *(const uint32_t*)(ab + 8 * SH + 8);
            }
            #pragma unroll
            for (int j = 0; j < 4; j++) {
                const __half* bb = Bs + (wn * 32 + j * 8 + lr) * SH + ks * 16 + lc * 2;
                bfr[j][0] = *(const uint32_t*)(bb);
                bfr[j][1] = *(const uint32_t*)(bb + 8);
            }
            #pragma unroll
            for (int i = 0; i < 4; i++)
                #pragma unroll
                for (int j = 0; j < 4; j++)
                    mma_f16(acc[i][j], afr[i], bfr[j]);
        }
    }

    #pragma unroll
    for (int i = 0; i < 4; i++) {
        #pragma unroll
        for (int half = 0; half < 2; half++) {
            int m = m0 + wm * 64 + i * 16 + half * 8 + lr;
            float* crow = Cf ? Cf + (long long)m * ldc : nullptr;
            __half* chrow = Ch ? Ch + (long long)m * ldc : nullptr;
            #pragma unroll
            for (int j = 0; j < 4; j++) {
                int n = n0 + wn * 32 + j * 8 + lc * 2;
                float v0 = acc[i][j][half * 2 + 0];
                float v1 = acc[i][j][half * 2 + 1];
                if (bias) { v0 += bias[n]; v1 += bias[n + 1]; }
                if (epi & 1) { v0 = fmaxf(v0, 0.0f); v1 = fmaxf(v1, 0.0f); }
                if (epi & 2) { v0 += crow[n]; v1 += crow[n + 1]; }
                if (chrow) *(__half2*)(chrow + n) = __floats2half2_rn(v0, v1);
                else       *(float2*)(crow + n) = make_float2(v0, v1);
            }
        }
    }
}

// ---------------- fused flash attention (fp16 operands, fp32 softmax/accum) ----------------
#define FSH 136                               // halfs per tile row (272 B)
#define F_TILE_H (128*FSH)
#define F_STATS_OFF (3*F_TILE_H)              // in halfs; stats are floats after tiles
#define FLASH_SMEM (F_STATS_OFF*2 + (512+128+128+128)*4)

__device__ __forceinline__ void load_tile128_h(uint32_t sdst, const __half* __restrict__ g,
                                               int ldg, int tid) {
    #pragma unroll
    for (int t = 0; t < 8; t++) {
        int seg = tid + t * 256;              // 0..2047
        int row = seg >> 4, kq = seg & 15;    // 16 x 16B per 256B row
        cp_async16(sdst + (uint32_t)(row * (FSH*2) + kq * 16),
                   g + (long long)row * ldg + kq * 8);
    }
}

__global__ void __launch_bounds__(256, 1)
flash_kernel(const __half* __restrict__ qkv, const __half* __restrict__ vT,
             __half* __restrict__ o) {
    int i = 7 - blockIdx.x;
    int z = blockIdx.y;
    int b = z / HH, h = z - b * HH;

    extern __shared__ __half fsh[];
    float* st = (float*)(fsh + F_STATS_OFF);   // [512 red][128 m][128 l][128 corr]
    float* red_s = st;
    float* m_s = st + 512;
    float* l_s = st + 640;
    float* c_s = st + 768;
    uint32_t sb = smem_u32(fsh);
    int tid = threadIdx.x, wid = tid >> 5, lane = tid & 31;
    int wm = wid & 1, wn = wid >> 1;
    int lr = lane >> 2, lc = lane & 3;

    const __half* qg = qkv + ((long long)(b * TT + i * 128)) * QKV3 + h * HD;
    const __half* kg = qkv + ((long long)(b * TT)) * QKV3 + EE + h * HD;
    const __half* vg = vT + (long long)z * HD * TT;

    load_tile128_h(sb, qg, QKV3, tid);
    asm volatile("cp.async.commit_group;" ::: "memory");

    if (tid < 128) { m_s[tid] = -1e30f; l_s[tid] = 0.0f; }

    float oacc[4][4][4];
    #pragma unroll
    for (int a = 0; a < 4; a++)
        #pragma unroll
        for (int j = 0; j < 4; j++)
            #pragma unroll
            for (int e = 0; e < 4; e++) oacc[a][j][e] = 0.0f;

    const float scale = 0.0883883476483184406f;

    for (int j = 0; j <= i; j++) {
        load_tile128_h(sb + F_TILE_H*2, kg + (long long)(j * 128) * QKV3, QKV3, tid);
        asm volatile("cp.async.commit_group;" ::: "memory");
        load_tile128_h(sb + 2*F_TILE_H*2, vg + j * 128, TT, tid);
        asm volatile("cp.async.commit_group;" ::: "memory");
        asm volatile("cp.async.wait_group 1;" ::: "memory");
        __syncthreads();

        // ---- S = Q K^T ----
        float sacc[4][4][4];
        #pragma unroll
        for (int a = 0; a < 4; a++)
            #pragma unroll
            for (int jt = 0; jt < 4; jt++)
                #pragma unroll
                for (int e = 0; e < 4; e++) sacc[a][jt][e] = 0.0f;

        const __half* Qs = fsh;
        const __half* Ks = fsh + F_TILE_H;
        #pragma unroll
        for (int kk = 0; kk < 8; kk++) {          // 8 x k16 over HD=128
            uint32_t afr[4][4], bfr[4][2];
            #pragma unroll
            for (int a = 0; a < 4; a++) {
                const __half* ab = Qs + (wm * 64 + a * 16 + lr) * FSH + kk * 16 + lc * 2;
                afr[a][0] = *(const uint32_t*)(ab);
                afr[a][1] = *(const uint32_t*)(ab + 8 * FSH);
                afr[a][2] = *(const uint32_t*)(ab + 8);
                afr[a][3] = *(const uint32_t*)(ab + 8 * FSH + 8);
            }
            #pragma unroll
            for (int jt = 0; jt < 4; jt++) {
                const __half* bb = Ks + (wn * 32 + jt * 8 + lr) * FSH + kk * 16 + lc * 2;
                bfr[jt][0] = *(const uint32_t*)(bb);
                bfr[jt][1] = *(const uint32_t*)(bb + 8);
            }
            #pragma unroll
            for (int a = 0; a < 4; a++)
                #pragma unroll
                for (int jt = 0; jt < 4; jt++)
                    mma_f16(sacc[a][jt], afr[a], bfr[jt]);
        }

        // ---- scale + causal mask + row max ----
        float pmax[4][2];
        #pragma unroll
        for (int a = 0; a < 4; a++) { pmax[a][0] = -1e30f; pmax[a][1] = -1e30f; }
        #pragma unroll
        for (int a = 0; a < 4; a++)
            #pragma unroll
            for (int jt = 0; jt < 4; jt++)
                #pragma unroll
                for (int e = 0; e < 4; e++) {
                    int half = e >> 1;
                    float sv = sacc[a][jt][e] * scale;
                    if (j == i) {
                        int mr = wm * 64 + a * 16 + half * 8 + lr;
                        int nc = wn * 32 + jt * 8 + 2 * lc + (e & 1);
                        if (nc > mr) sv = -1e30f;
                    }
                    sacc[a][jt][e] = sv;
                    pmax[a][half] = fmaxf(pmax[a][half], sv);
                }
        #pragma unroll
        for (int a = 0; a < 4; a++)
            #pragma unroll
            for (int half = 0; half < 2; half++) {
                float v = pmax[a][half];
                v = fmaxf(v, __shfl_xor_sync(0xFFFFFFFF, v, 1));
                v = fmaxf(v, __shfl_xor_sync(0xFFFFFFFF, v, 2));
                pmax[a][half] = v;
            }
        if (lc == 0) {
            #pragma unroll
            for (int a = 0; a < 4; a++)
                #pragma unroll
                for (int half = 0; half < 2; half++)
                    red_s[(wm * 64 + a * 16 + half * 8 + lr) * 4 + wn] = pmax[a][half];
        }
        __syncthreads();

        if (wn == 0 && lc == 0) {
            #pragma unroll
            for (int a = 0; a < 4; a++)
                #pragma unroll
                for (int half = 0; half < 2; half++) {
                    int r = wm * 64 + a * 16 + half * 8 + lr;
                    float m4 = fmaxf(fmaxf(red_s[r*4], red_s[r*4 + 1]),
                                     fmaxf(red_s[r*4 + 2], red_s[r*4 + 3]));
                    float mold = m_s[r];
                    float mnew = fmaxf(mold, m4);
                    c_s[r] = __expf(mold - mnew);
                    m_s[r] = mnew;
                }
        }
        __syncthreads();

        // ---- P = exp(S - m) -> fp16 (K buffer); rescale O; row sums ----
        float mn[4][2], cr[4][2], psum[4][2];
        #pragma unroll
        for (int a = 0; a < 4; a++)
            #pragma unroll
            for (int half = 0; half < 2; half++) {
                int r = wm * 64 + a * 16 + half * 8 + lr;
                mn[a][half] = m_s[r];
                cr[a][half] = c_s[r];
                psum[a][half] = 0.0f;
            }
        __half* Ps = fsh + F_TILE_H;
        #pragma unroll
        for (int a = 0; a < 4; a++)
            #pragma unroll
            for (int jt = 0; jt < 4; jt++) {
                #pragma unroll
                for (int half = 0; half < 2; half++) {
                    float p0 = __expf(sacc[a][jt][half*2 + 0] - mn[a][half]);
                    float p1 = __expf(sacc[a][jt][half*2 + 1] - mn[a][half]);
                    psum[a][half] += p0 + p1;
                    oacc[a][jt][half*2 + 0] *= cr[a][half];
                    oacc[a][jt][half*2 + 1] *= cr[a][half];
                    int r = wm * 64 + a * 16 + half * 8 + lr;
                    int nc = wn * 32 + jt * 8 + 2 * lc;
                    *(__half2*)(Ps + r * FSH + nc) = __floats2half2_rn(p0, p1);
                }
            }
        #pragma unroll
        for (int a = 0; a < 4; a++)
            #pragma unroll
            for (int half = 0; half < 2; half++) {
                float v = psum[a][half];
                v += __shfl_xor_sync(0xFFFFFFFF, v, 1);
                v += __shfl_xor_sync(0xFFFFFFFF, v, 2);
                psum[a][half] = v;
            }
        if (lc == 0) {
            #pragma unroll
            for (int a = 0; a < 4; a++)
                #pragma unroll
                for (int half = 0; half < 2; half++)
                    red_s[(wm * 64 + a * 16 + half * 8 + lr) * 4 + wn] = psum[a][half];
        }
        asm volatile("cp.async.wait_group 0;" ::: "memory");
        __syncthreads();

        if (wn == 0 && lc == 0) {
            #pragma unroll
            for (int a = 0; a < 4; a++)
                #pragma unroll
                for (int half = 0; half < 2; half++) {
                    int r = wm * 64 + a * 16 + half * 8 + lr;
                    float s4 = red_s[r*4] + red_s[r*4 + 1] + red_s[r*4 + 2] + red_s[r*4 + 3];
                    l_s[r] = l_s[r] * c_s[r] + s4;
                }
        }

        // ---- O += P V ----
        const __half* Vs = fsh + 2 * F_TILE_H;
        #pragma unroll
        for (int kk = 0; kk < 8; kk++) {
            uint32_t afr[4][4], bfr[4][2];
            #pragma unroll
            for (int a = 0; a < 4; a++) {
                const __half* ab = Ps + (wm * 64 + a * 16 + lr) * FSH + kk * 16 + lc * 2;
                afr[a][0] = *(const uint32_t*)(ab);
                afr[a][1] = *(const uint32_t*)(ab + 8 * FSH);
                afr[a][2] = *(const uint32_t*)(ab + 8);
                afr[a][3] = *(const uint32_t*)(ab + 8 * FSH + 8);
            }
            #pragma unroll
            for (int jt = 0; jt < 4; jt++) {
                const __half* bb = Vs + (wn * 32 + jt * 8 + lr) * FSH + kk * 16 + lc * 2;
                bfr[jt][0] = *(const uint32_t*)(bb);
                bfr[jt][1] = *(const uint32_t*)(bb + 8);
            }
            #pragma unroll
            for (int a = 0; a < 4; a++)
                #pragma unroll
                for (int jt = 0; jt < 4; jt++)
                    mma_f16(oacc[a][jt], afr[a], bfr[jt]);
        }
        __syncthreads();
    }

    __half* og = o + ((long long)(b * TT + i * 128)) * EE + h * HD;
    #pragma unroll
    for (int a = 0; a < 4; a++)
        #pragma unroll
        for (int half = 0; half < 2; half++) {
            int r = wm * 64 + a * 16 + half * 8 + lr;
            float linv = 1.0f / l_s[r];
            __half* orow = og + (long long)r * EE;
            #pragma unroll
            for (int jt = 0; jt < 4; jt++) {
                int nc = wn * 32 + jt * 8 + 2 * lc;
                *(__half2*)(orow + nc) =
                    __floats2half2_rn(oacc[a][jt][half*2 + 0] * linv,
                                      oacc[a][jt][half*2 + 1] * linv);
            }
        }
}

// ---------------- per-row NLL via streaming logsumexp ----------------
__global__ void loss_rows_kernel(const float* __restrict__ logits,
                                 const void* __restrict__ tgtv,
                                 float* __restrict__ nll) {
    int r = blockIdx.x;
    const float* row = logits + (long long)r * VV;
    int tid = threadIdx.x;
    float m = -1e30f, s = 0.0f;
    for (int j = tid; j < VV; j += 256) {
        float v = row[j];
        if (v > m) { s = s * __expf(m - v) + 1.0f; m = v; }
        else       { s += __expf(v - m); }
    }
    __shared__ float sm[256], ss[256];
    sm[tid] = m; ss[tid] = s; __syncthreads();
    for (int k = 128; k > 0; k >>= 1) {
        if (tid < k) {
            float m2 = sm[tid + k], s2 = ss[tid + k];
            float mm = fmaxf(sm[tid], m2);
            ss[tid] = ss[tid] * __expf(sm[tid] - mm) + s2 * __expf(m2 - mm);
            sm[tid] = mm;
        }
        __syncthreads();
    }
    if (tid == 0) {
        long long t = load_token(tgtv, r, g_is64_tgt);
        nll[r] = (sm[0] + logf(ss[0])) - row[t];
    }
}

__global__ void loss_final_kernel(const float* __restrict__ nll, float* __restrict__ out, int n) {
    __shared__ float red[256];
    int tid = threadIdx.x;
    float s = 0.0f;
    for (int j = tid; j < BT; j += 256) s += nll[j];
    red[tid] = s; __syncthreads();
    for (int k = 128; k > 0; k >>= 1) { if (tid < k) red[tid] += red[tid + k]; __syncthreads(); }
    float mean = red[0] * (1.0f / BT);
    for (int i = tid; i < n; i += 256) out[i] = mean;
}

// ---------------- host-side helpers ----------------
static void tcg(const __half* A, int lda, const __half* Bm, int ldb,
                float* Cf, __half* Ch, int ldc, int M, int N, int K,
                const float* bias, int epi) {
    dim3 grid(M / 128, N / 128, 1);   // m fastest
    tc_gemm_h<<<grid, 256, TC_SMEM>>>(A, lda, Bm, ldb, Cf, Ch, ldc, K, bias, epi);
}

extern "C" void kernel_launch(void* const* d_in, const int* in_sizes, int n_in,
                              void* d_out, int out_size) {
    const void*  idx  = d_in[0];
    const void*  tgt  = d_in[1];
    const float* tok  = (const float*)d_in[2];
    const float* pos  = (const float*)d_in[3];
    const float* Wq   = (const float*)d_in[4];
    const float* bq   = (const float*)d_in[5];
    const float* Wk   = (const float*)d_in[6];
    const float* bk   = (const float*)d_in[7];
    const float* Wv   = (const float*)d_in[8];
    const float* bv   = (const float*)d_in[9];
    const float* Wo   = (const float*)d_in[10];
    const float* bo   = (const float*)d_in[11];
    const float* w1   = (const float*)d_in[12];
    const float* b1   = (const float*)d_in[13];
    const float* w2   = (const float*)d_in[14];
    const float* b2   = (const float*)d_in[15];
    const float* ln1s = (const float*)d_in[16];
    const float* ln1b = (const float*)d_in[17];
    const float* ln2s = (const float*)d_in[18];
    const float* ln2b = (const float*)d_in[19];
    const float* lnfs = (const float*)d_in[20];
    const float* lnfb = (const float*)d_in[21];
    const float* Wlm  = (const float*)d_in[22];
    const float* blm  = (const float*)d_in[23];

    float *x, *nll, *logits_fb, *bqkv;
    __half *hh, *qkvh, *vTh, *oh, *ffh, *wqkvTh, *woTh, *w1Th, *w2Th, *wlmTh;
    cudaGetSymbolAddress((void**)&x,     g_x);
    cudaGetSymbolAddress((void**)&hh,    g_hh);
    cudaGetSymbolAddress((void**)&qkvh,  g_qkvh);
    cudaGetSymbolAddress((void**)&vTh,   g_vTh);
    cudaGetSymbolAddress((void**)&oh,    g_oh);
    cudaGetSymbolAddress((void**)&ffh,   g_ffh);
    cudaGetSymbolAddress((void**)&nll,   g_nll);
    cudaGetSymbolAddress((void**)&logits_fb, g_logits_fb);
    cudaGetSymbolAddress((void**)&wqkvTh, g_wqkvTh);
    cudaGetSymbolAddress((void**)&bqkv,   g_bqkv);
    cudaGetSymbolAddress((void**)&woTh,  g_woTh);
    cudaGetSymbolAddress((void**)&w1Th,  g_w1Th);
    cudaGetSymbolAddress((void**)&w2Th,  g_w2Th);
    cudaGetSymbolAddress((void**)&wlmTh, g_wlmTh);

    cudaFuncSetAttribute(tc_gemm_h, cudaFuncAttributeMaxDynamicSharedMemorySize, TC_SMEM);
    cudaFuncSetAttribute(flash_kernel, cudaFuncAttributeMaxDynamicSharedMemorySize, FLASH_SMEM);

    float* out = (float*)d_out;
    float* logits = ((long long)out_size >= BTV) ? out : logits_fb;
    float* lossPtr = nullptr;
    int nLoss = 0;
    if ((long long)out_size > BTV) { lossPtr = out + BTV; nLoss = out_size - (int)BTV; }
    else if ((long long)out_size < BTV) { lossPtr = out; nLoss = out_size; }

    const long long E2  = (long long)EE * EE;
    const long long EF  = (long long)EE * FF;
    const long long LQ3 = (long long)QKV3 * EE;
    const long long ZVT = (long long)HD * TT;

    detect_kernel<<<1, 32>>>((const int*)idx, (const int*)tgt);
    embed_kernel<<<BT, 256>>>(idx, tok, pos, x);
    {
        dim3 grid(EE / 32, EE / 32, 3 * LL + 1), blk(32, 8);
        qkv_prep_kernel<<<grid, blk>>>(Wq, Wk, Wv, bq, bk, bv, wqkvTh, bqkv);
    }
    {
        dim3 blk(32, 8);
        transpose_f2h_kernel<<<dim3(EE/32, EE/32, LL), blk>>>(Wo, woTh, EE, EE, E2, E2);
        transpose_f2h_kernel<<<dim3(FF/32, EE/32, LL), blk>>>(w1, w1Th, FF, EE, EF, EF);
        transpose_f2h_kernel<<<dim3(EE/32, FF/32, LL), blk>>>(w2, w2Th, EE, FF, EF, EF);
        transpose_f2h_kernel<<<dim3(VV/32, EE/32, 1), blk>>>(Wlm, wlmTh, VV, EE, 0, 0);
    }

    for (int l = 0; l < LL; l++) {
        // h = fp16(LN1(x))
        layernorm_kernel<<<BT, 256>>>(x, hh, ln1s + l * EE, ln1b + l * EE);

        // qkv = fp16(h @ Wqkv + bqkv)
        tcg(hh, EE, wqkvTh + l * LQ3, EE, nullptr, qkvh, QKV3, BT, QKV3, EE,
            bqkv + l * QKV3, 0);

        // vT[b,h,d,t] = v[b,t,h,d]
        {
            dim3 grid(HD / 32, TT / 32, BB * HH), blk(32, 8);
            transpose_h2h_kernel<<<grid, blk>>>(qkvh + 2 * EE, vTh, QKV3, TT,
                (long long)TT * QKV3, HD, (long long)HH * ZVT, ZVT, HH);
        }

        // fused attention -> o (fp16)
        flash_kernel<<<dim3(8, BB * HH), 256, FLASH_SMEM>>>(qkvh, vTh, oh);

        // x += o @ Wo + bo   (fp32 out)
        tcg(oh, EE, woTh + l * E2, EE, x, nullptr, EE, BT, EE, EE, bo + l * EE, 2);

        // h = fp16(LN2(x))
        layernorm_kernel<<<BT, 256>>>(x, hh, ln2s + l * EE, ln2b + l * EE);

        // ff = fp16(relu(h @ w1 + b1));  x += ff @ w2 + b2
        tcg(hh, EE, w1Th + l * EF, EE, nullptr, ffh, FF, BT, FF, EE,
            b1 + (long long)l * FF, 1);
        tcg(ffh, FF, w2Th + l * EF, FF, x, nullptr, EE, BT, EE, FF, b2 + l * EE, 2);
    }

    // final LN + LM head (fp32 logits)
    layernorm_kernel<<<BT, 256>>>(x, hh, lnfs, lnfb);
    tcg(hh, EE, wlmTh, EE, logits, nullptr, VV, BT, VV, EE, blm, 0);

    // loss
    loss_rows_kernel<<<BT, 256>>>(logits, tgt, nll);
    if (nLoss > 0)
        loss_final_kernel<<<1, 256>>>(nll, lossPtr, nLoss);
}

// round 13
// speedup vs baseline: 5.6439x; 1.0269x over previous
#include <cuda_runtime.h>
#include <cuda_fp16.h>
#include <math.h>
#include <stdint.h>

// ---------------- problem constants ----------------
#define BB 4
#define TT 1024
#define EE 768
#define LL 6
#define HH 6
#define HD 128
#define VV 32000
#define FF (4*EE)          // 3072
#define BT (BB*TT)         // 4096
#define BTV ((long long)BT*VV)
#define QKV3 (3*EE)        // 2304

// ---------------- scratch (device globals; no allocations allowed) ----------------
__device__ float  g_x  [BT*EE];                     // residual stream (fp32)
__device__ __half g_hh [BT*EE];                     // LN output (GEMM A)
__device__ __half g_qkvh[(long long)BT*QKV3];
__device__ __half g_vTh[(long long)BB*HH*HD*TT];
__device__ __half g_oh [BT*EE];
__device__ __half g_ffh[BT*FF];
__device__ float  g_nll[BT];
__device__ float  g_logits_fb[BTV];
__device__ int    g_is64_idx;
__device__ int    g_is64_tgt;
// fp16 K-major [N,K] weights
__device__ __half g_wqkvTh[(long long)LL*QKV3*EE];
__device__ float  g_bqkv  [LL*QKV3];
__device__ __half g_woTh [LL*EE*EE];
__device__ __half g_w1Th [(long long)LL*EE*FF];
__device__ __half g_w2Th [(long long)LL*EE*FF];
__device__ __half g_wlmTh[(long long)EE*VV];

// ---------------- small helpers ----------------
__device__ __forceinline__ uint32_t smem_u32(const void* p) {
    uint32_t a;
    asm("{ .reg .u64 t; cvta.to.shared.u64 t, %1; cvt.u32.u64 %0, t; }" : "=r"(a) : "l"(p));
    return a;
}

__device__ __forceinline__ void cp_async16(uint32_t saddr, const void* gaddr) {
    asm volatile("cp.async.cg.shared.global [%0], [%1], 16;" :: "r"(saddr), "l"(gaddr));
}

// fp16 mma.sync: D(16x8,f32) += A(16x16,f16) * B(16x8,f16), row.col
__device__ __forceinline__ void mma_f16(float* c, const uint32_t* a, const uint32_t* b) {
    asm volatile(
        "mma.sync.aligned.m16n8k16.row.col.f32.f16.f16.f32 "
        "{%0,%1,%2,%3}, {%4,%5,%6,%7}, {%8,%9}, {%0,%1,%2,%3};"
        : "+f"(c[0]), "+f"(c[1]), "+f"(c[2]), "+f"(c[3])
        : "r"(a[0]), "r"(a[1]), "r"(a[2]), "r"(a[3]), "r"(b[0]), "r"(b[1]));
}

// ---------------- int64-vs-int32 detection ----------------
__global__ void detect_kernel(const int* __restrict__ idx, const int* __restrict__ tgt) {
    if (threadIdx.x == 0 && blockIdx.x == 0) {
        int a = 1, b = 1;
        for (int i = 1; i < 129; i += 2) {
            if (idx[i] != 0) a = 0;
            if (tgt[i] != 0) b = 0;
        }
        g_is64_idx = a;
        g_is64_tgt = b;
    }
}

__device__ __forceinline__ long long load_token(const void* p, int r, int is64) {
    if (is64) return ((const long long*)p)[r];
    return (long long)((const int*)p)[r];
}

// ---------------- embedding ----------------
__global__ void embed_kernel(const void* __restrict__ idxv,
                             const float* __restrict__ tok,
                             const float* __restrict__ pos,
                             float* __restrict__ x) {
    int r = blockIdx.x;
    long long token = load_token(idxv, r, g_is64_idx);
    int t = r % TT;
    const float* te = tok + token * EE;
    const float* pe = pos + (long long)t * EE;
    float* xr = x + (long long)r * EE;
    for (int e = threadIdx.x; e < EE; e += blockDim.x)
        xr[e] = te[e] + pe[e];
}

// ---------------- layernorm (fp16 out; warp-shuffle reductions, 4 syncs) ----------------
__global__ void layernorm_kernel(const float* __restrict__ x, __half* __restrict__ y,
                                 const float* __restrict__ s, const float* __restrict__ b) {
    int r = blockIdx.x;
    const float* row = x + (long long)r * EE;
    __half* out = y + (long long)r * EE;
    int tid = threadIdx.x, wid = tid >> 5, lane = tid & 31;
    __shared__ float wred[8];
    __shared__ float sMean, sInv;

    float v0 = row[tid], v1 = row[tid + 256], v2 = row[tid + 512];
    float sm = v0 + v1 + v2;
    #pragma unroll
    for (int o = 16; o; o >>= 1) sm += __shfl_xor_sync(0xFFFFFFFFu, sm, o);
    if (lane == 0) wred[wid] = sm;
    __syncthreads();
    if (tid == 0) {
        float t = 0.0f;
        #pragma unroll
        for (int i = 0; i < 8; i++) t += wred[i];
        sMean = t * (1.0f / EE);
    }
    __syncthreads();
    float mean = sMean;

    float d0 = v0 - mean, d1 = v1 - mean, d2 = v2 - mean;
    float q = d0*d0 + d1*d1 + d2*d2;
    #pragma unroll
    for (int o = 16; o; o >>= 1) q += __shfl_xor_sync(0xFFFFFFFFu, q, o);
    if (lane == 0) wred[wid] = q;
    __syncthreads();
    if (tid == 0) {
        float t = 0.0f;
        #pragma unroll
        for (int i = 0; i < 8; i++) t += wred[i];
        sInv = rsqrtf(t * (1.0f / EE) + 1e-5f);
    }
    __syncthreads();
    float inv = sInv;

    out[tid      ] = __float2half_rn(d0 * inv * s[tid      ] + b[tid      ]);
    out[tid + 256] = __float2half_rn(d1 * inv * s[tid + 256] + b[tid + 256]);
    out[tid + 512] = __float2half_rn(d2 * inv * s[tid + 512] + b[tid + 512]);
}

// ---------------- weight transpose: float -> half ----------------
__global__ void transpose_f2h_kernel(const float* __restrict__ src, __half* __restrict__ dst,
                                     int srs, int drs, long long sZ, long long dZ) {
    int z = blockIdx.z;
    src += z * sZ;
    dst += z * dZ;
    __shared__ float tile[32][33];
    int c0 = blockIdx.x * 32, r0 = blockIdx.y * 32;
    int tx = threadIdx.x, ty = threadIdx.y;
    #pragma unroll
    for (int i = 0; i < 32; i += 8)
        tile[ty + i][tx] = src[(long long)(r0 + ty + i) * srs + c0 + tx];
    __syncthreads();
    #pragma unroll
    for (int i = 0; i < 32; i += 8)
        dst[(long long)(c0 + ty + i) * drs + r0 + tx] = __float2half_rn(tile[tx][ty + i]);
}

// ---------------- fused QKV weight transpose + bias concat ----------------
__global__ void qkv_prep_kernel(const float* __restrict__ Wq, const float* __restrict__ Wk,
                                const float* __restrict__ Wv,
                                const float* __restrict__ bq, const float* __restrict__ bk,
                                const float* __restrict__ bv,
                                __half* __restrict__ wqkvT, float* __restrict__ bqkv) {
    int z = blockIdx.z;
    int tx = threadIdx.x, ty = threadIdx.y;
    if (z == 3 * LL) {
        int i = (blockIdx.y * gridDim.x + blockIdx.x) * 256 + ty * 32 + tx;
        if (i < LL * QKV3) {
            int l = i / QKV3, n = i - l * QKV3;
            float v;
            if (n < EE)          v = bq[l * EE + n];
            else if (n < 2*EE)   v = bk[l * EE + n - EE];
            else                 v = bv[l * EE + n - 2*EE];
            bqkv[i] = v;
        }
        return;
    }
    int s = z / LL, l = z - s * LL;
    const float* src = (s == 0 ? Wq : (s == 1 ? Wk : Wv)) + (long long)l * EE * EE;
    __half* dst = wqkvT + (long long)l * QKV3 * EE + (long long)s * EE * EE;
    __shared__ float tile[32][33];
    int c0 = blockIdx.x * 32, r0 = blockIdx.y * 32;
    #pragma unroll
    for (int i = 0; i < 32; i += 8)
        tile[ty + i][tx] = src[(long long)(r0 + ty + i) * EE + c0 + tx];
    __syncthreads();
    #pragma unroll
    for (int i = 0; i < 32; i += 8)
        dst[(long long)(c0 + ty + i) * EE + r0 + tx] = __float2half_rn(tile[tx][ty + i]);
}

// ---------------- fp16 mma.sync GEMM (128x128 tile, 4 stages, 2 CTAs/SM) ----------------
// C[m,n] = sum_k A[m,k] * B[n,k]   (A [M,K] K-major fp16, B [N,K] K-major fp16)
// grid (M/128, N/128) -- m fastest for L2 reuse of B.
// Output: Ch (fp16) if non-null, else Cf (fp32).
// epi bits: 1=relu, 2=residual-add (fp32 Cf read).
// vt non-null (QKV GEMM): tiles with n >= 2*EE also scatter fp16 into vT[b,h,d,t].
#define NST 4
#define SH 40                            // halfs per smem row (80 B, conflict-free)
#define STAGE_H (2*128*SH)               // halfs per stage (A+B)
#define TC_SMEM (NST*STAGE_H*2)          // 81920 bytes

__device__ __forceinline__ void load_chunk_h(const __half* __restrict__ A, int lda,
                                             const __half* __restrict__ Bm, int ldb,
                                             uint32_t sA, uint32_t sB,
                                             int m0, int n0, int k0, int tid) {
    #pragma unroll
    for (int t = 0; t < 2; t++) {
        int seg = tid + t * 256;              // 0..511
        int row = seg >> 2, kq = seg & 3;     // 4 x 16B per 64B row
        cp_async16(sA + (uint32_t)(row * (SH*2) + kq * 16),
                   A + (long long)(m0 + row) * lda + k0 + kq * 8);
    }
    #pragma unroll
    for (int t = 0; t < 2; t++) {
        int seg = tid + t * 256;
        int row = seg >> 2, kq = seg & 3;
        cp_async16(sB + (uint32_t)(row * (SH*2) + kq * 16),
                   Bm + (long long)(n0 + row) * ldb + k0 + kq * 8);
    }
}

__global__ void __launch_bounds__(256, 2)
tc_gemm_h(const __half* __restrict__ A, int lda,
          const __half* __restrict__ Bm, int ldb,
          float* __restrict__ Cf, __half* __restrict__ Ch, int ldc,
          int K, const float* __restrict__ bias, int epi,
          __half* __restrict__ vt) {
    int m0 = blockIdx.x * 128, n0 = blockIdx.y * 128;   // m fastest
    int nchunks = K >> 5;

    extern __shared__ __half smh[];
    uint32_t sb = smem_u32(smh);
    int tid = threadIdx.x, wid = tid >> 5, lane = tid & 31;
    int wm = wid & 1, wn = wid >> 1;       // 2 x 4 warp grid; warp tile 64x32
    int lr = lane >> 2, lc = lane & 3;

    float acc[4][4][4];
    #pragma unroll
    for (int i = 0; i < 4; i++)
        #pragma unroll
        for (int j = 0; j < 4; j++)
            #pragma unroll
            for (int e = 0; e < 4; e++) acc[i][j][e] = 0.0f;

    #pragma unroll
    for (int s = 0; s < NST - 1; s++) {
        if (s < nchunks)
            load_chunk_h(A, lda, Bm, ldb, sb + s * (STAGE_H*2), sb + s * (STAGE_H*2) + 128*SH*2,
                         m0, n0, s * 32, tid);
        asm volatile("cp.async.commit_group;" ::: "memory");
    }

    for (int c = 0; c < nchunks; c++) {
        asm volatile("cp.async.wait_group %0;" :: "n"(NST - 2) : "memory");
        __syncthreads();

        int cn = c + NST - 1;
        if (cn < nchunks) {
            int sn = cn % NST;
            load_chunk_h(A, lda, Bm, ldb, sb + sn * (STAGE_H*2), sb + sn * (STAGE_H*2) + 128*SH*2,
                         m0, n0, cn * 32, tid);
        }
        asm volatile("cp.async.commit_group;" ::: "memory");

        const __half* As = smh + (c % NST) * STAGE_H;
        const __half* Bs = As + 128 * SH;

        #pragma unroll
        for (int ks = 0; ks < 2; ks++) {          // two k16 steps per 32-K chunk
            uint32_t afr[4][4], bfr[4][2];
            #pragma unroll
            for (int i = 0; i < 4; i++) {
                const __half* ab = As + (wm * 64 + i * 16 + lr) * SH + ks * 16 + lc * 2;
                afr[i][0] = *(const uint32_t*)(ab);
                afr[i][1] = *(const uint32_t*)(ab + 8 * SH);
                afr[i][2] = *(const uint32_t*)(ab + 8);
                afr[i][3] = *(const uint32_t*)(ab + 8 * SH + 8);
            }
            #pragma unroll
            for (int j = 0; j < 4; j++) {
                const __half* bb = Bs + (wn * 32 + j * 8 + lr) * SH + ks * 16 + lc * 2;
                bfr[j][0] = *(const uint32_t*)(bb);
                bfr[j][1] = *(const uint32_t*)(bb + 8);
            }
            #pragma unroll
            for (int i = 0; i < 4; i++)
                #pragma unroll
                for (int j = 0; j < 4; j++)
                    mma_f16(acc[i][j], afr[i], bfr[j]);
        }
    }

    bool vtile = (vt != nullptr) && (n0 >= 2 * EE);
    #pragma unroll
    for (int i = 0; i < 4; i++) {
        #pragma unroll
        for (int half = 0; half < 2; half++) {
            int m = m0 + wm * 64 + i * 16 + half * 8 + lr;
            float* crow = Cf ? Cf + (long long)m * ldc : nullptr;
            __half* chrow = Ch ? Ch + (long long)m * ldc : nullptr;
            int bI = m >> 10, t = m & (TT - 1);
            #pragma unroll
            for (int j = 0; j < 4; j++) {
                int n = n0 + wn * 32 + j * 8 + lc * 2;
                float v0 = acc[i][j][half * 2 + 0];
                float v1 = acc[i][j][half * 2 + 1];
                if (bias) { v0 += bias[n]; v1 += bias[n + 1]; }
                if (epi & 1) { v0 = fmaxf(v0, 0.0f); v1 = fmaxf(v1, 0.0f); }
                if (epi & 2) { v0 += crow[n]; v1 += crow[n + 1]; }
                if (chrow) {
                    __half2 hv = __floats2half2_rn(v0, v1);
                    *(__half2*)(chrow + n) = hv;
                    if (vtile) {
                        int vd = n - 2 * EE;
                        int vh = vd >> 7; vd &= 127;
                        __half* vrow = vt + (((long long)(bI * HH + vh) * HD + vd)) * TT + t;
                        vrow[0]  = __low2half(hv);
                        vrow[TT] = __high2half(hv);
                    }
                } else {
                    *(float2*)(crow + n) = make_float2(v0, v1);
                }
            }
        }
    }
}

// ---------------- fused flash attention (fp16 operands, fp32 softmax/accum) ----------------
#define FSH 136                               // halfs per tile row (272 B)
#define F_TILE_H (128*FSH)
#define F_STATS_OFF (3*F_TILE_H)              // in halfs; stats are floats after tiles
#define FLASH_SMEM (F_STATS_OFF*2 + (512+128+128+128)*4)

__device__ __forceinline__ void load_tile128_h(uint32_t sdst, const __half* __restrict__ g,
                                               int ldg, int tid) {
    #pragma unroll
    for (int t = 0; t < 8; t++) {
        int seg = tid + t * 256;              // 0..2047
        int row = seg >> 4, kq = seg & 15;    // 16 x 16B per 256B row
        cp_async16(sdst + (uint32_t)(row * (FSH*2) + kq * 16),
                   g + (long long)row * ldg + kq * 8);
    }
}

__global__ void __launch_bounds__(256, 1)
flash_kernel(const __half* __restrict__ qkv, const __half* __restrict__ vT,
             __half* __restrict__ o) {
    int i = 7 - blockIdx.x;
    int z = blockIdx.y;
    int b = z / HH, h = z - b * HH;

    extern __shared__ __half fsh[];
    float* st = (float*)(fsh + F_STATS_OFF);   // [512 red][128 m][128 l][128 corr]
    float* red_s = st;
    float* m_s = st + 512;
    float* l_s = st + 640;
    float* c_s = st + 768;
    uint32_t sb = smem_u32(fsh);
    int tid = threadIdx.x, wid = tid >> 5, lane = tid & 31;
    int wm = wid & 1, wn = wid >> 1;
    int lr = lane >> 2, lc = lane & 3;

    const __half* qg = qkv + ((long long)(b * TT + i * 128)) * QKV3 + h * HD;
    const __half* kg = qkv + ((long long)(b * TT)) * QKV3 + EE + h * HD;
    const __half* vg = vT + (long long)z * HD * TT;

    load_tile128_h(sb, qg, QKV3, tid);
    asm volatile("cp.async.commit_group;" ::: "memory");

    if (tid < 128) { m_s[tid] = -1e30f; l_s[tid] = 0.0f; }

    float oacc[4][4][4];
    #pragma unroll
    for (int a = 0; a < 4; a++)
        #pragma unroll
        for (int j = 0; j < 4; j++)
            #pragma unroll
            for (int e = 0; e < 4; e++) oacc[a][j][e] = 0.0f;

    const float scale = 0.0883883476483184406f;

    for (int j = 0; j <= i; j++) {
        load_tile128_h(sb + F_TILE_H*2, kg + (long long)(j * 128) * QKV3, QKV3, tid);
        asm volatile("cp.async.commit_group;" ::: "memory");
        load_tile128_h(sb + 2*F_TILE_H*2, vg + j * 128, TT, tid);
        asm volatile("cp.async.commit_group;" ::: "memory");
        asm volatile("cp.async.wait_group 1;" ::: "memory");
        __syncthreads();

        // ---- S = Q K^T ----
        float sacc[4][4][4];
        #pragma unroll
        for (int a = 0; a < 4; a++)
            #pragma unroll
            for (int jt = 0; jt < 4; jt++)
                #pragma unroll
                for (int e = 0; e < 4; e++) sacc[a][jt][e] = 0.0f;

        const __half* Qs = fsh;
        const __half* Ks = fsh + F_TILE_H;
        #pragma unroll
        for (int kk = 0; kk < 8; kk++) {
            uint32_t afr[4][4], bfr[4][2];
            #pragma unroll
            for (int a = 0; a < 4; a++) {
                const __half* ab = Qs + (wm * 64 + a * 16 + lr) * FSH + kk * 16 + lc * 2;
                afr[a][0] = *(const uint32_t*)(ab);
                afr[a][1] = *(const uint32_t*)(ab + 8 * FSH);
                afr[a][2] = *(const uint32_t*)(ab + 8);
                afr[a][3] = *(const uint32_t*)(ab + 8 * FSH + 8);
            }
            #pragma unroll
            for (int jt = 0; jt < 4; jt++) {
                const __half* bb = Ks + (wn * 32 + jt * 8 + lr) * FSH + kk * 16 + lc * 2;
                bfr[jt][0] = *(const uint32_t*)(bb);
                bfr[jt][1] = *(const uint32_t*)(bb + 8);
            }
            #pragma unroll
            for (int a = 0; a < 4; a++)
                #pragma unroll
                for (int jt = 0; jt < 4; jt++)
                    mma_f16(sacc[a][jt], afr[a], bfr[jt]);
        }

        // ---- scale + causal mask + row max ----
        float pmax[4][2];
        #pragma unroll
        for (int a = 0; a < 4; a++) { pmax[a][0] = -1e30f; pmax[a][1] = -1e30f; }
        #pragma unroll
        for (int a = 0; a < 4; a++)
            #pragma unroll
            for (int jt = 0; jt < 4; jt++)
                #pragma unroll
                for (int e = 0; e < 4; e++) {
                    int half = e >> 1;
                    float sv = sacc[a][jt][e] * scale;
                    if (j == i) {
                        int mr = wm * 64 + a * 16 + half * 8 + lr;
                        int nc = wn * 32 + jt * 8 + 2 * lc + (e & 1);
                        if (nc > mr) sv = -1e30f;
                    }
                    sacc[a][jt][e] = sv;
                    pmax[a][half] = fmaxf(pmax[a][half], sv);
                }
        #pragma unroll
        for (int a = 0; a < 4; a++)
            #pragma unroll
            for (int half = 0; half < 2; half++) {
                float v = pmax[a][half];
                v = fmaxf(v, __shfl_xor_sync(0xFFFFFFFF, v, 1));
                v = fmaxf(v, __shfl_xor_sync(0xFFFFFFFF, v, 2));
                pmax[a][half] = v;
            }
        if (lc == 0) {
            #pragma unroll
            for (int a = 0; a < 4; a++)
                #pragma unroll
                for (int half = 0; half < 2; half++)
                    red_s[(wm * 64 + a * 16 + half * 8 + lr) * 4 + wn] = pmax[a][half];
        }
        __syncthreads();

        if (wn == 0 && lc == 0) {
            #pragma unroll
            for (int a = 0; a < 4; a++)
                #pragma unroll
                for (int half = 0; half < 2; half++) {
                    int r = wm * 64 + a * 16 + half * 8 + lr;
                    float m4 = fmaxf(fmaxf(red_s[r*4], red_s[r*4 + 1]),
                                     fmaxf(red_s[r*4 + 2], red_s[r*4 + 3]));
                    float mold = m_s[r];
                    float mnew = fmaxf(mold, m4);
                    c_s[r] = __expf(mold - mnew);
                    m_s[r] = mnew;
                }
        }
        __syncthreads();

        // ---- P = exp(S - m) -> fp16 (K buffer); rescale O; row sums ----
        float mn[4][2], cr[4][2], psum[4][2];
        #pragma unroll
        for (int a = 0; a < 4; a++)
            #pragma unroll
            for (int half = 0; half < 2; half++) {
                int r = wm * 64 + a * 16 + half * 8 + lr;
                mn[a][half] = m_s[r];
                cr[a][half] = c_s[r];
                psum[a][half] = 0.0f;
            }
        __half* Ps = fsh + F_TILE_H;
        #pragma unroll
        for (int a = 0; a < 4; a++)
            #pragma unroll
            for (int jt = 0; jt < 4; jt++) {
                #pragma unroll
                for (int half = 0; half < 2; half++) {
                    float p0 = __expf(sacc[a][jt][half*2 + 0] - mn[a][half]);
                    float p1 = __expf(sacc[a][jt][half*2 + 1] - mn[a][half]);
                    psum[a][half] += p0 + p1;
                    oacc[a][jt][half*2 + 0] *= cr[a][half];
                    oacc[a][jt][half*2 + 1] *= cr[a][half];
                    int r = wm * 64 + a * 16 + half * 8 + lr;
                    int nc = wn * 32 + jt * 8 + 2 * lc;
                    *(__half2*)(Ps + r * FSH + nc) = __floats2half2_rn(p0, p1);
                }
            }
        #pragma unroll
        for (int a = 0; a < 4; a++)
            #pragma unroll
            for (int half = 0; half < 2; half++) {
                float v = psum[a][half];
                v += __shfl_xor_sync(0xFFFFFFFF, v, 1);
                v += __shfl_xor_sync(0xFFFFFFFF, v, 2);
                psum[a][half] = v;
            }
        if (lc == 0) {
            #pragma unroll
            for (int a = 0; a < 4; a++)
                #pragma unroll
                for (int half = 0; half < 2; half++)
                    red_s[(wm * 64 + a * 16 + half * 8 + lr) * 4 + wn] = psum[a][half];
        }
        asm volatile("cp.async.wait_group 0;" ::: "memory");
        __syncthreads();

        if (wn == 0 && lc == 0) {
            #pragma unroll
            for (int a = 0; a < 4; a++)
                #pragma unroll
                for (int half = 0; half < 2; half++) {
                    int r = wm * 64 + a * 16 + half * 8 + lr;
                    float s4 = red_s[r*4] + red_s[r*4 + 1] + red_s[r*4 + 2] + red_s[r*4 + 3];
                    l_s[r] = l_s[r] * c_s[r] + s4;
                }
        }

        // ---- O += P V ----
        const __half* Vs = fsh + 2 * F_TILE_H;
        #pragma unroll
        for (int kk = 0; kk < 8; kk++) {
            uint32_t afr[4][4], bfr[4][2];
            #pragma unroll
            for (int a = 0; a < 4; a++) {
                const __half* ab = Ps + (wm * 64 + a * 16 + lr) * FSH + kk * 16 + lc * 2;
                afr[a][0] = *(const uint32_t*)(ab);
                afr[a][1] = *(const uint32_t*)(ab + 8 * FSH);
                afr[a][2] = *(const uint32_t*)(ab + 8);
                afr[a][3] = *(const uint32_t*)(ab + 8 * FSH + 8);
            }
            #pragma unroll
            for (int jt = 0; jt < 4; jt++) {
                const __half* bb = Vs + (wn * 32 + jt * 8 + lr) * FSH + kk * 16 + lc * 2;
                bfr[jt][0] = *(const uint32_t*)(bb);
                bfr[jt][1] = *(const uint32_t*)(bb + 8);
            }
            #pragma unroll
            for (int a = 0; a < 4; a++)
                #pragma unroll
                for (int jt = 0; jt < 4; jt++)
                    mma_f16(oacc[a][jt], afr[a], bfr[jt]);
        }
        __syncthreads();
    }

    __half* og = o + ((long long)(b * TT + i * 128)) * EE + h * HD;
    #pragma unroll
    for (int a = 0; a < 4; a++)
        #pragma unroll
        for (int half = 0; half < 2; half++) {
            int r = wm * 64 + a * 16 + half * 8 + lr;
            float linv = 1.0f / l_s[r];
            __half* orow = og + (long long)r * EE;
            #pragma unroll
            for (int jt = 0; jt < 4; jt++) {
                int nc = wn * 32 + jt * 8 + 2 * lc;
                *(__half2*)(orow + nc) =
                    __floats2half2_rn(oacc[a][jt][half*2 + 0] * linv,
                                      oacc[a][jt][half*2 + 1] * linv);
            }
        }
}

// ---------------- per-row NLL: two-pass (max, then exp from L2) ----------------
__global__ void __launch_bounds__(512)
loss_rows_kernel(const float* __restrict__ logits,
                 const void* __restrict__ tgtv,
                 float* __restrict__ nll) {
    int r = blockIdx.x;
    const float* row = logits + (long long)r * VV;
    const float4* row4 = (const float4*)row;
    int tid = threadIdx.x, wid = tid >> 5, lane = tid & 31;
    __shared__ float wred[16];
    __shared__ float sMax;

    // pass 1: max
    float m = -1e30f;
    for (int j = tid; j < VV / 4; j += 512) {
        float4 v = row4[j];
        m = fmaxf(m, fmaxf(fmaxf(v.x, v.y), fmaxf(v.z, v.w)));
    }
    #pragma unroll
    for (int o = 16; o; o >>= 1) m = fmaxf(m, __shfl_xor_sync(0xFFFFFFFFu, m, o));
    if (lane == 0) wred[wid] = m;
    __syncthreads();
    if (tid == 0) {
        float t = wred[0];
        #pragma unroll
        for (int i = 1; i < 16; i++) t = fmaxf(t, wred[i]);
        sMax = t;
    }
    __syncthreads();
    m = sMax;

    // pass 2: sum exp (row hot in L2)
    float s = 0.0f;
    for (int j = tid; j < VV / 4; j += 512) {
        float4 v = row4[j];
        s += __expf(v.x - m) + __expf(v.y - m) + __expf(v.z - m) + __expf(v.w - m);
    }
    #pragma unroll
    for (int o = 16; o; o >>= 1) s += __shfl_xor_sync(0xFFFFFFFFu, s, o);
    __syncthreads();
    if (lane == 0) wred[wid] = s;
    __syncthreads();
    if (tid == 0) {
        float t = 0.0f;
        #pragma unroll
        for (int i = 0; i < 16; i++) t += wred[i];
        long long tgt = load_token(tgtv, r, g_is64_tgt);
        nll[r] = (m + logf(t)) - row[tgt];
    }
}

__global__ void loss_final_kernel(const float* __restrict__ nll, float* __restrict__ out, int n) {
    __shared__ float red[256];
    int tid = threadIdx.x;
    float s = 0.0f;
    for (int j = tid; j < BT; j += 256) s += nll[j];
    red[tid] = s; __syncthreads();
    for (int k = 128; k > 0; k >>= 1) { if (tid < k) red[tid] += red[tid + k]; __syncthreads(); }
    float mean = red[0] * (1.0f / BT);
    for (int i = tid; i < n; i += 256) out[i] = mean;
}

// ---------------- host-side helpers ----------------
static void tcg(const __half* A, int lda, const __half* Bm, int ldb,
                float* Cf, __half* Ch, int ldc, int M, int N, int K,
                const float* bias, int epi, __half* vt = nullptr) {
    dim3 grid(M / 128, N / 128, 1);   // m fastest
    tc_gemm_h<<<grid, 256, TC_SMEM>>>(A, lda, Bm, ldb, Cf, Ch, ldc, K, bias, epi, vt);
}

extern "C" void kernel_launch(void* const* d_in, const int* in_sizes, int n_in,
                              void* d_out, int out_size) {
    const void*  idx  = d_in[0];
    const void*  tgt  = d_in[1];
    const float* tok  = (const float*)d_in[2];
    const float* pos  = (const float*)d_in[3];
    const float* Wq   = (const float*)d_in[4];
    const float* bq   = (const float*)d_in[5];
    const float* Wk   = (const float*)d_in[6];
    const float* bk   = (const float*)d_in[7];
    const float* Wv   = (const float*)d_in[8];
    const float* bv   = (const float*)d_in[9];
    const float* Wo   = (const float*)d_in[10];
    const float* bo   = (const float*)d_in[11];
    const float* w1   = (const float*)d_in[12];
    const float* b1   = (const float*)d_in[13];
    const float* w2   = (const float*)d_in[14];
    const float* b2   = (const float*)d_in[15];
    const float* ln1s = (const float*)d_in[16];
    const float* ln1b = (const float*)d_in[17];
    const float* ln2s = (const float*)d_in[18];
    const float* ln2b = (const float*)d_in[19];
    const float* lnfs = (const float*)d_in[20];
    const float* lnfb = (const float*)d_in[21];
    const float* Wlm  = (const float*)d_in[22];
    const float* blm  = (const float*)d_in[23];

    float *x, *nll, *logits_fb, *bqkv;
    __half *hh, *qkvh, *vTh, *oh, *ffh, *wqkvTh, *woTh, *w1Th, *w2Th, *wlmTh;
    cudaGetSymbolAddress((void**)&x,     g_x);
    cudaGetSymbolAddress((void**)&hh,    g_hh);
    cudaGetSymbolAddress((void**)&qkvh,  g_qkvh);
    cudaGetSymbolAddress((void**)&vTh,   g_vTh);
    cudaGetSymbolAddress((void**)&oh,    g_oh);
    cudaGetSymbolAddress((void**)&ffh,   g_ffh);
    cudaGetSymbolAddress((void**)&nll,   g_nll);
    cudaGetSymbolAddress((void**)&logits_fb, g_logits_fb);
    cudaGetSymbolAddress((void**)&wqkvTh, g_wqkvTh);
    cudaGetSymbolAddress((void**)&bqkv,   g_bqkv);
    cudaGetSymbolAddress((void**)&woTh,  g_woTh);
    cudaGetSymbolAddress((void**)&w1Th,  g_w1Th);
    cudaGetSymbolAddress((void**)&w2Th,  g_w2Th);
    cudaGetSymbolAddress((void**)&wlmTh, g_wlmTh);

    cudaFuncSetAttribute(tc_gemm_h, cudaFuncAttributeMaxDynamicSharedMemorySize, TC_SMEM);
    cudaFuncSetAttribute(flash_kernel, cudaFuncAttributeMaxDynamicSharedMemorySize, FLASH_SMEM);

    float* out = (float*)d_out;
    float* logits = ((long long)out_size >= BTV) ? out : logits_fb;
    float* lossPtr = nullptr;
    int nLoss = 0;
    if ((long long)out_size > BTV) { lossPtr = out + BTV; nLoss = out_size - (int)BTV; }
    else if ((long long)out_size < BTV) { lossPtr = out; nLoss = out_size; }

    const long long E2  = (long long)EE * EE;
    const long long EF  = (long long)EE * FF;
    const long long LQ3 = (long long)QKV3 * EE;

    detect_kernel<<<1, 32>>>((const int*)idx, (const int*)tgt);
    embed_kernel<<<BT, 256>>>(idx, tok, pos, x);
    {
        dim3 grid(EE / 32, EE / 32, 3 * LL + 1), blk(32, 8);
        qkv_prep_kernel<<<grid, blk>>>(Wq, Wk, Wv, bq, bk, bv, wqkvTh, bqkv);
    }
    {
        dim3 blk(32, 8);
        transpose_f2h_kernel<<<dim3(EE/32, EE/32, LL), blk>>>(Wo, woTh, EE, EE, E2, E2);
        transpose_f2h_kernel<<<dim3(FF/32, EE/32, LL), blk>>>(w1, w1Th, FF, EE, EF, EF);
        transpose_f2h_kernel<<<dim3(EE/32, FF/32, LL), blk>>>(w2, w2Th, EE, FF, EF, EF);
        transpose_f2h_kernel<<<dim3(VV/32, EE/32, 1), blk>>>(Wlm, wlmTh, VV, EE, 0, 0);
    }

    for (int l = 0; l < LL; l++) {
        // h = fp16(LN1(x))
        layernorm_kernel<<<BT, 256>>>(x, hh, ln1s + l * EE, ln1b + l * EE);

        // qkv = fp16(h @ Wqkv + bqkv); V tiles also scattered into vT
        tcg(hh, EE, wqkvTh + l * LQ3, EE, nullptr, qkvh, QKV3, BT, QKV3, EE,
            bqkv + l * QKV3, 0, vTh);

        // fused attention -> o (fp16)
        flash_kernel<<<dim3(8, BB * HH), 256, FLASH_SMEM>>>(qkvh, vTh, oh);

        // x += o @ Wo + bo   (fp32 out)
        tcg(oh, EE, woTh + l * E2, EE, x, nullptr, EE, BT, EE, EE, bo + l * EE, 2);

        // h = fp16(LN2(x))
        layernorm_kernel<<<BT, 256>>>(x, hh, ln2s + l * EE, ln2b + l * EE);

        // ff = fp16(relu(h @ w1 + b1));  x += ff @ w2 + b2
        tcg(hh, EE, w1Th + l * EF, EE, nullptr, ffh, FF, BT, FF, EE,
            b1 + (long long)l * FF, 1);
        tcg(ffh, FF, w2Th + l * EF, FF, x, nullptr, EE, BT, EE, FF, b2 + l * EE, 2);
    }

    // final LN + LM head (fp32 logits)
    layernorm_kernel<<<BT, 256>>>(x, hh, lnfs, lnfb);
    tcg(hh, EE, wlmTh, EE, logits, nullptr, VV, BT, VV, EE, blm, 0);

    // loss
    loss_rows_kernel<<<BT, 512>>>(logits, tgt, nll);
    if (nLoss > 0)
        loss_final_kernel<<<1, 256>>>(nll, lossPtr, nLoss);
}

// round 15
// speedup vs baseline: 5.8035x; 1.0283x over previous
#include <cuda_runtime.h>
#include <cuda_fp16.h>
#include <math.h>
#include <stdint.h>

// ---------------- problem constants ----------------
#define BB 4
#define TT 1024
#define EE 768
#define LL 6
#define HH 6
#define HD 128
#define VV 32000
#define FF (4*EE)          // 3072
#define BT (BB*TT)         // 4096
#define BTV ((long long)BT*VV)
#define QKV3 (3*EE)        // 2304
#define NTL (VV/128)       // 250 LM-head n-tiles

// ---------------- scratch (device globals; no allocations allowed) ----------------
__device__ float  g_x  [BT*EE];                     // residual stream (fp32)
__device__ __half g_hh [BT*EE];                     // LN output (GEMM A)
__device__ __half g_qkvh[(long long)BT*QKV3];
__device__ __half g_vTh[(long long)BB*HH*HD*TT];
__device__ __half g_oh [BT*EE];
__device__ __half g_ffh[BT*FF];
__device__ float  g_nll[BT];
__device__ float  g_lsm[(long long)BT*NTL];         // per-tile row max
__device__ float  g_lss[(long long)BT*NTL];         // per-tile row sumexp
__device__ float  g_logits_fb[BTV];
__device__ int    g_is64_idx;
__device__ int    g_is64_tgt;
// fp16 K-major [N,K] weights
__device__ __half g_wqkvTh[(long long)LL*QKV3*EE];
__device__ float  g_bqkv  [LL*QKV3];
__device__ __half g_woTh [LL*EE*EE];
__device__ __half g_w1Th [(long long)LL*EE*FF];
__device__ __half g_w2Th [(long long)LL*EE*FF];
__device__ __half g_wlmTh[(long long)EE*VV];

// ---------------- small helpers ----------------
__device__ __forceinline__ uint32_t smem_u32(const void* p) {
    uint32_t a;
    asm("{ .reg .u64 t; cvta.to.shared.u64 t, %1; cvt.u32.u64 %0, t; }" : "=r"(a) : "l"(p));
    return a;
}

__device__ __forceinline__ void cp_async16(uint32_t saddr, const void* gaddr) {
    asm volatile("cp.async.cg.shared.global [%0], [%1], 16;" :: "r"(saddr), "l"(gaddr));
}

// fp16 mma.sync: D(16x8,f32) += A(16x16,f16) * B(16x8,f16), row.col
__device__ __forceinline__ void mma_f16(float* c, const uint32_t* a, const uint32_t* b) {
    asm volatile(
        "mma.sync.aligned.m16n8k16.row.col.f32.f16.f16.f32 "
        "{%0,%1,%2,%3}, {%4,%5,%6,%7}, {%8,%9}, {%0,%1,%2,%3};"
        : "+f"(c[0]), "+f"(c[1]), "+f"(c[2]), "+f"(c[3])
        : "r"(a[0]), "r"(a[1]), "r"(a[2]), "r"(a[3]), "r"(b[0]), "r"(b[1]));
}

// ---------------- int64-vs-int32 detection ----------------
__global__ void detect_kernel(const int* __restrict__ idx, const int* __restrict__ tgt) {
    if (threadIdx.x == 0 && blockIdx.x == 0) {
        int a = 1, b = 1;
        for (int i = 1; i < 129; i += 2) {
            if (idx[i] != 0) a = 0;
            if (tgt[i] != 0) b = 0;
        }
        g_is64_idx = a;
        g_is64_tgt = b;
    }
}

__device__ __forceinline__ long long load_token(const void* p, int r, int is64) {
    if (is64) return ((const long long*)p)[r];
    return (long long)((const int*)p)[r];
}

// ---------------- embedding ----------------
__global__ void embed_kernel(const void* __restrict__ idxv,
                             const float* __restrict__ tok,
                             const float* __restrict__ pos,
                             float* __restrict__ x) {
    int r = blockIdx.x;
    long long token = load_token(idxv, r, g_is64_idx);
    int t = r % TT;
    const float* te = tok + token * EE;
    const float* pe = pos + (long long)t * EE;
    float* xr = x + (long long)r * EE;
    for (int e = threadIdx.x; e < EE; e += blockDim.x)
        xr[e] = te[e] + pe[e];
}

// ---------------- layernorm (fp16 out; warp-shuffle reductions) ----------------
__global__ void layernorm_kernel(const float* __restrict__ x, __half* __restrict__ y,
                                 const float* __restrict__ s, const float* __restrict__ b) {
    int r = blockIdx.x;
    const float* row = x + (long long)r * EE;
    __half* out = y + (long long)r * EE;
    int tid = threadIdx.x, wid = tid >> 5, lane = tid & 31;
    __shared__ float wred[8];
    __shared__ float sMean, sInv;

    float v0 = row[tid], v1 = row[tid + 256], v2 = row[tid + 512];
    float sm = v0 + v1 + v2;
    #pragma unroll
    for (int o = 16; o; o >>= 1) sm += __shfl_xor_sync(0xFFFFFFFFu, sm, o);
    if (lane == 0) wred[wid] = sm;
    __syncthreads();
    if (tid == 0) {
        float t = 0.0f;
        #pragma unroll
        for (int i = 0; i < 8; i++) t += wred[i];
        sMean = t * (1.0f / EE);
    }
    __syncthreads();
    float mean = sMean;

    float d0 = v0 - mean, d1 = v1 - mean, d2 = v2 - mean;
    float q = d0*d0 + d1*d1 + d2*d2;
    #pragma unroll
    for (int o = 16; o; o >>= 1) q += __shfl_xor_sync(0xFFFFFFFFu, q, o);
    if (lane == 0) wred[wid] = q;
    __syncthreads();
    if (tid == 0) {
        float t = 0.0f;
        #pragma unroll
        for (int i = 0; i < 8; i++) t += wred[i];
        sInv = rsqrtf(t * (1.0f / EE) + 1e-5f);
    }
    __syncthreads();
    float inv = sInv;

    out[tid      ] = __float2half_rn(d0 * inv * s[tid      ] + b[tid      ]);
    out[tid + 256] = __float2half_rn(d1 * inv * s[tid + 256] + b[tid + 256]);
    out[tid + 512] = __float2half_rn(d2 * inv * s[tid + 512] + b[tid + 512]);
}

// ---------------- weight transpose: float -> half ----------------
__global__ void transpose_f2h_kernel(const float* __restrict__ src, __half* __restrict__ dst,
                                     int srs, int drs, long long sZ, long long dZ) {
    int z = blockIdx.z;
    src += z * sZ;
    dst += z * dZ;
    __shared__ float tile[32][33];
    int c0 = blockIdx.x * 32, r0 = blockIdx.y * 32;
    int tx = threadIdx.x, ty = threadIdx.y;
    #pragma unroll
    for (int i = 0; i < 32; i += 8)
        tile[ty + i][tx] = src[(long long)(r0 + ty + i) * srs + c0 + tx];
    __syncthreads();
    #pragma unroll
    for (int i = 0; i < 32; i += 8)
        dst[(long long)(c0 + ty + i) * drs + r0 + tx] = __float2half_rn(tile[tx][ty + i]);
}

// ---------------- fused QKV weight transpose + bias concat ----------------
__global__ void qkv_prep_kernel(const float* __restrict__ Wq, const float* __restrict__ Wk,
                                const float* __restrict__ Wv,
                                const float* __restrict__ bq, const float* __restrict__ bk,
                                const float* __restrict__ bv,
                                __half* __restrict__ wqkvT, float* __restrict__ bqkv) {
    int z = blockIdx.z;
    int tx = threadIdx.x, ty = threadIdx.y;
    if (z == 3 * LL) {
        int i = (blockIdx.y * gridDim.x + blockIdx.x) * 256 + ty * 32 + tx;
        if (i < LL * QKV3) {
            int l = i / QKV3, n = i - l * QKV3;
            float v;
            if (n < EE)          v = bq[l * EE + n];
            else if (n < 2*EE)   v = bk[l * EE + n - EE];
            else                 v = bv[l * EE + n - 2*EE];
            bqkv[i] = v;
        }
        return;
    }
    int s = z / LL, l = z - s * LL;
    const float* src = (s == 0 ? Wq : (s == 1 ? Wk : Wv)) + (long long)l * EE * EE;
    __half* dst = wqkvT + (long long)l * QKV3 * EE + (long long)s * EE * EE;
    __shared__ float tile[32][33];
    int c0 = blockIdx.x * 32, r0 = blockIdx.y * 32;
    #pragma unroll
    for (int i = 0; i < 32; i += 8)
        tile[ty + i][tx] = src[(long long)(r0 + ty + i) * EE + c0 + tx];
    __syncthreads();
    #pragma unroll
    for (int i = 0; i < 32; i += 8)
        dst[(long long)(c0 + ty + i) * EE + r0 + tx] = __float2half_rn(tile[tx][ty + i]);
}

// ---------------- fp16 mma.sync GEMM (128x128 tile, 4 stages, 2 CTAs/SM) ----------------
// C[m,n] = sum_k A[m,k] * B[n,k]
// Output: Ch (fp16) if non-null, else Cf (fp32).
// epi bits: 1=relu, 2=residual-add (fp32 Cf read).
// vt non-null (QKV GEMM): tiles with n >= 2*EE also scatter fp16 into vT[b,h,d,t].
// lsm/lss non-null (LM head): epilogue also emits per-row (max, sumexp) for this n-tile.
#define NST 4
#define SH 40                            // halfs per smem row (80 B, conflict-free)
#define STAGE_H (2*128*SH)               // halfs per stage (A+B)
#define TC_SMEM (NST*STAGE_H*2)          // 81920 bytes

__device__ __forceinline__ void load_chunk_h(const __half* __restrict__ A, int lda,
                                             const __half* __restrict__ Bm, int ldb,
                                             uint32_t sA, uint32_t sB,
                                             int m0, int n0, int k0, int tid) {
    #pragma unroll
    for (int t = 0; t < 2; t++) {
        int seg = tid + t * 256;              // 0..511
        int row = seg >> 2, kq = seg & 3;     // 4 x 16B per 64B row
        cp_async16(sA + (uint32_t)(row * (SH*2) + kq * 16),
                   A + (long long)(m0 + row) * lda + k0 + kq * 8);
    }
    #pragma unroll
    for (int t = 0; t < 2; t++) {
        int seg = tid + t * 256;
        int row = seg >> 2, kq = seg & 3;
        cp_async16(sB + (uint32_t)(row * (SH*2) + kq * 16),
                   Bm + (long long)(n0 + row) * ldb + k0 + kq * 8);
    }
}

__global__ void __launch_bounds__(256, 2)
tc_gemm_h(const __half* __restrict__ A, int lda,
          const __half* __restrict__ Bm, int ldb,
          float* __restrict__ Cf, __half* __restrict__ Ch, int ldc,
          int K, const float* __restrict__ bias, int epi,
          __half* __restrict__ vt,
          float* __restrict__ lsm, float* __restrict__ lss) {
    int m0 = blockIdx.x * 128, n0 = blockIdx.y * 128;   // m fastest
    int nchunks = K >> 5;

    extern __shared__ __half smh[];
    __shared__ float ls_red[512];
    uint32_t sb = smem_u32(smh);
    int tid = threadIdx.x, wid = tid >> 5, lane = tid & 31;
    int wm = wid & 1, wn = wid >> 1;       // 2 x 4 warp grid; warp tile 64x32
    int lr = lane >> 2, lc = lane & 3;

    float acc[4][4][4];
    #pragma unroll
    for (int i = 0; i < 4; i++)
        #pragma unroll
        for (int j = 0; j < 4; j++)
            #pragma unroll
            for (int e = 0; e < 4; e++) acc[i][j][e] = 0.0f;

    #pragma unroll
    for (int s = 0; s < NST - 1; s++) {
        if (s < nchunks)
            load_chunk_h(A, lda, Bm, ldb, sb + s * (STAGE_H*2), sb + s * (STAGE_H*2) + 128*SH*2,
                         m0, n0, s * 32, tid);
        asm volatile("cp.async.commit_group;" ::: "memory");
    }

    for (int c = 0; c < nchunks; c++) {
        asm volatile("cp.async.wait_group %0;" :: "n"(NST - 2) : "memory");
        __syncthreads();

        int cn = c + NST - 1;
        if (cn < nchunks) {
            int sn = cn % NST;
            load_chunk_h(A, lda, Bm, ldb, sb + sn * (STAGE_H*2), sb + sn * (STAGE_H*2) + 128*SH*2,
                         m0, n0, cn * 32, tid);
        }
        asm volatile("cp.async.commit_group;" ::: "memory");

        const __half* As = smh + (c % NST) * STAGE_H;
        const __half* Bs = As + 128 * SH;

        #pragma unroll
        for (int ks = 0; ks < 2; ks++) {
            uint32_t afr[4][4], bfr[4][2];
            #pragma unroll
            for (int i = 0; i < 4; i++) {
                const __half* ab = As + (wm * 64 + i * 16 + lr) * SH + ks * 16 + lc * 2;
                afr[i][0] = *(const uint32_t*)(ab);
                afr[i][1] = *(const uint32_t*)(ab + 8 * SH);
                afr[i][2] = *(const uint32_t*)(ab + 8);
                afr[i][3] = *(const uint32_t*)(ab + 8 * SH + 8);
            }
            #pragma unroll
            for (int j = 0; j < 4; j++) {
                const __half* bb = Bs + (wn * 32 + j * 8 + lr) * SH + ks * 16 + lc * 2;
                bfr[j][0] = *(const uint32_t*)(bb);
                bfr[j][1] = *(const uint32_t*)(bb + 8);
            }
            #pragma unroll
            for (int i = 0; i < 4; i++)
                #pragma unroll
                for (int j = 0; j < 4; j++)
                    mma_f16(acc[i][j], afr[i], bfr[j]);
        }
    }

    bool vtile = (vt != nullptr) && (n0 >= 2 * EE);
    float tmax[4][2];
    #pragma unroll
    for (int i = 0; i < 4; i++) { tmax[i][0] = -1e30f; tmax[i][1] = -1e30f; }

    #pragma unroll
    for (int i = 0; i < 4; i++) {
        #pragma unroll
        for (int half = 0; half < 2; half++) {
            int m = m0 + wm * 64 + i * 16 + half * 8 + lr;
            float* crow = Cf ? Cf + (long long)m * ldc : nullptr;
            __half* chrow = Ch ? Ch + (long long)m * ldc : nullptr;
            int bI = m >> 10, t = m & (TT - 1);
            #pragma unroll
            for (int j = 0; j < 4; j++) {
                int n = n0 + wn * 32 + j * 8 + lc * 2;
                float v0 = acc[i][j][half * 2 + 0];
                float v1 = acc[i][j][half * 2 + 1];
                if (bias) { v0 += bias[n]; v1 += bias[n + 1]; }
                if (epi & 1) { v0 = fmaxf(v0, 0.0f); v1 = fmaxf(v1, 0.0f); }
                if (epi & 2) { v0 += crow[n]; v1 += crow[n + 1]; }
                if (lsm) tmax[i][half] = fmaxf(tmax[i][half], fmaxf(v0, v1));
                if (chrow) {
                    __half2 hv = __floats2half2_rn(v0, v1);
                    *(__half2*)(chrow + n) = hv;
                    if (vtile) {
                        int vd = n - 2 * EE;
                        int vh = vd >> 7; vd &= 127;
                        __half* vrow = vt + (((long long)(bI * HH + vh) * HD + vd)) * TT + t;
                        vrow[0]  = __low2half(hv);
                        vrow[TT] = __high2half(hv);
                    }
                } else {
                    *(float2*)(crow + n) = make_float2(v0, v1);
                }
            }
        }
    }

    // ---- fused logsumexp partials (LM head only) ----
    if (lsm) {
        int nt = blockIdx.y;
        // quad-reduce max over lc, then smem over wn
        #pragma unroll
        for (int i = 0; i < 4; i++)
            #pragma unroll
            for (int half = 0; half < 2; half++) {
                float v = tmax[i][half];
                v = fmaxf(v, __shfl_xor_sync(0xFFFFFFFFu, v, 1));
                v = fmaxf(v, __shfl_xor_sync(0xFFFFFFFFu, v, 2));
                if (lc == 0)
                    ls_red[(wm * 64 + i * 16 + half * 8 + lr) * 4 + wn] = v;
            }
        __syncthreads();
        float rmax[4][2];
        #pragma unroll
        for (int i = 0; i < 4; i++)
            #pragma unroll
            for (int half = 0; half < 2; half++) {
                int lrow = wm * 64 + i * 16 + half * 8 + lr;
                rmax[i][half] = fmaxf(fmaxf(ls_red[lrow*4], ls_red[lrow*4+1]),
                                      fmaxf(ls_red[lrow*4+2], ls_red[lrow*4+3]));
            }
        __syncthreads();
        // sumexp
        #pragma unroll
        for (int i = 0; i < 4; i++)
            #pragma unroll
            for (int half = 0; half < 2; half++) {
                float s = 0.0f;
                #pragma unroll
                for (int j = 0; j < 4; j++) {
                    int n = n0 + wn * 32 + j * 8 + lc * 2;
                    float v0 = acc[i][j][half * 2 + 0] + bias[n];
                    float v1 = acc[i][j][half * 2 + 1] + bias[n + 1];
                    s += __expf(v0 - rmax[i][half]) + __expf(v1 - rmax[i][half]);
                }
                s += __shfl_xor_sync(0xFFFFFFFFu, s, 1);
                s += __shfl_xor_sync(0xFFFFFFFFu, s, 2);
                if (lc == 0)
                    ls_red[(wm * 64 + i * 16 + half * 8 + lr) * 4 + wn] = s;
            }
        __syncthreads();
        if (wn == 0 && lc == 0) {
            #pragma unroll
            for (int i = 0; i < 4; i++)
                #pragma unroll
                for (int half = 0; half < 2; half++) {
                    int lrow = wm * 64 + i * 16 + half * 8 + lr;
                    int m = m0 + lrow;
                    float s4 = ls_red[lrow*4] + ls_red[lrow*4+1]
                             + ls_red[lrow*4+2] + ls_red[lrow*4+3];
                    lsm[(long long)m * NTL + nt] = rmax[i][half];
                    lss[(long long)m * NTL + nt] = s4;
                }
        }
    }
}

// ---------------- fused flash attention (fp16 operands, fp32 softmax/accum) ----------------
#define FSH 136                               // halfs per tile row (272 B)
#define F_TILE_H (128*FSH)
#define F_STATS_OFF (3*F_TILE_H)
#define FLASH_SMEM (F_STATS_OFF*2 + (512+128+128+128)*4)

__device__ __forceinline__ void load_tile128_h(uint32_t sdst, const __half* __restrict__ g,
                                               int ldg, int tid) {
    #pragma unroll
    for (int t = 0; t < 8; t++) {
        int seg = tid + t * 256;
        int row = seg >> 4, kq = seg & 15;
        cp_async16(sdst + (uint32_t)(row * (FSH*2) + kq * 16),
                   g + (long long)row * ldg + kq * 8);
    }
}

__global__ void __launch_bounds__(256, 1)
flash_kernel(const __half* __restrict__ qkv, const __half* __restrict__ vT,
             __half* __restrict__ o) {
    int i = 7 - blockIdx.x;
    int z = blockIdx.y;
    int b = z / HH, h = z - b * HH;

    extern __shared__ __half fsh[];
    float* st = (float*)(fsh + F_STATS_OFF);
    float* red_s = st;
    float* m_s = st + 512;
    float* l_s = st + 640;
    float* c_s = st + 768;
    uint32_t sb = smem_u32(fsh);
    int tid = threadIdx.x, wid = tid >> 5, lane = tid & 31;
    int wm = wid & 1, wn = wid >> 1;
    int lr = lane >> 2, lc = lane & 3;

    const __half* qg = qkv + ((long long)(b * TT + i * 128)) * QKV3 + h * HD;
    const __half* kg = qkv + ((long long)(b * TT)) * QKV3 + EE + h * HD;
    const __half* vg = vT + (long long)z * HD * TT;

    load_tile128_h(sb, qg, QKV3, tid);
    asm volatile("cp.async.commit_group;" ::: "memory");

    if (tid < 128) { m_s[tid] = -1e30f; l_s[tid] = 0.0f; }

    float oacc[4][4][4];
    #pragma unroll
    for (int a = 0; a < 4; a++)
        #pragma unroll
        for (int j = 0; j < 4; j++)
            #pragma unroll
            for (int e = 0; e < 4; e++) oacc[a][j][e] = 0.0f;

    const float scale = 0.0883883476483184406f;

    for (int j = 0; j <= i; j++) {
        load_tile128_h(sb + F_TILE_H*2, kg + (long long)(j * 128) * QKV3, QKV3, tid);
        asm volatile("cp.async.commit_group;" ::: "memory");
        load_tile128_h(sb + 2*F_TILE_H*2, vg + j * 128, TT, tid);
        asm volatile("cp.async.commit_group;" ::: "memory");
        asm volatile("cp.async.wait_group 1;" ::: "memory");
        __syncthreads();

        float sacc[4][4][4];
        #pragma unroll
        for (int a = 0; a < 4; a++)
            #pragma unroll
            for (int jt = 0; jt < 4; jt++)
                #pragma unroll
                for (int e = 0; e < 4; e++) sacc[a][jt][e] = 0.0f;

        const __half* Qs = fsh;
        const __half* Ks = fsh + F_TILE_H;
        #pragma unroll
        for (int kk = 0; kk < 8; kk++) {
            uint32_t afr[4][4], bfr[4][2];
            #pragma unroll
            for (int a = 0; a < 4; a++) {
                const __half* ab = Qs + (wm * 64 + a * 16 + lr) * FSH + kk * 16 + lc * 2;
                afr[a][0] = *(const uint32_t*)(ab);
                afr[a][1] = *(const uint32_t*)(ab + 8 * FSH);
                afr[a][2] = *(const uint32_t*)(ab + 8);
                afr[a][3] = *(const uint32_t*)(ab + 8 * FSH + 8);
            }
            #pragma unroll
            for (int jt = 0; jt < 4; jt++) {
                const __half* bb = Ks + (wn * 32 + jt * 8 + lr) * FSH + kk * 16 + lc * 2;
                bfr[jt][0] = *(const uint32_t*)(bb);
                bfr[jt][1] = *(const uint32_t*)(bb + 8);
            }
            #pragma unroll
            for (int a = 0; a < 4; a++)
                #pragma unroll
                for (int jt = 0; jt < 4; jt++)
                    mma_f16(sacc[a][jt], afr[a], bfr[jt]);
        }

        float pmax[4][2];
        #pragma unroll
        for (int a = 0; a < 4; a++) { pmax[a][0] = -1e30f; pmax[a][1] = -1e30f; }
        #pragma unroll
        for (int a = 0; a < 4; a++)
            #pragma unroll
            for (int jt = 0; jt < 4; jt++)
                #pragma unroll
                for (int e = 0; e < 4; e++) {
                    int half = e >> 1;
                    float sv = sacc[a][jt][e] * scale;
                    if (j == i) {
                        int mr = wm * 64 + a * 16 + half * 8 + lr;
                        int nc = wn * 32 + jt * 8 + 2 * lc + (e & 1);
                        if (nc > mr) sv = -1e30f;
                    }
                    sacc[a][jt][e] = sv;
                    pmax[a][half] = fmaxf(pmax[a][half], sv);
                }
        #pragma unroll
        for (int a = 0; a < 4; a++)
            #pragma unroll
            for (int half = 0; half < 2; half++) {
                float v = pmax[a][half];
                v = fmaxf(v, __shfl_xor_sync(0xFFFFFFFF, v, 1));
                v = fmaxf(v, __shfl_xor_sync(0xFFFFFFFF, v, 2));
                pmax[a][half] = v;
            }
        if (lc == 0) {
            #pragma unroll
            for (int a = 0; a < 4; a++)
                #pragma unroll
                for (int half = 0; half < 2; half++)
                    red_s[(wm * 64 + a * 16 + half * 8 + lr) * 4 + wn] = pmax[a][half];
        }
        __syncthreads();

        if (wn == 0 && lc == 0) {
            #pragma unroll
            for (int a = 0; a < 4; a++)
                #pragma unroll
                for (int half = 0; half < 2; half++) {
                    int r = wm * 64 + a * 16 + half * 8 + lr;
                    float m4 = fmaxf(fmaxf(red_s[r*4], red_s[r*4 + 1]),
                                     fmaxf(red_s[r*4 + 2], red_s[r*4 + 3]));
                    float mold = m_s[r];
                    float mnew = fmaxf(mold, m4);
                    c_s[r] = __expf(mold - mnew);
                    m_s[r] = mnew;
                }
        }
        __syncthreads();

        float mn[4][2], cr[4][2], psum[4][2];
        #pragma unroll
        for (int a = 0; a < 4; a++)
            #pragma unroll
            for (int half = 0; half < 2; half++) {
                int r = wm * 64 + a * 16 + half * 8 + lr;
                mn[a][half] = m_s[r];
                cr[a][half] = c_s[r];
                psum[a][half] = 0.0f;
            }
        __half* Ps = fsh + F_TILE_H;
        #pragma unroll
        for (int a = 0; a < 4; a++)
            #pragma unroll
            for (int jt = 0; jt < 4; jt++) {
                #pragma unroll
                for (int half = 0; half < 2; half++) {
                    float p0 = __expf(sacc[a][jt][half*2 + 0] - mn[a][half]);
                    float p1 = __expf(sacc[a][jt][half*2 + 1] - mn[a][half]);
                    psum[a][half] += p0 + p1;
                    oacc[a][jt][half*2 + 0] *= cr[a][half];
                    oacc[a][jt][half*2 + 1] *= cr[a][half];
                    int r = wm * 64 + a * 16 + half * 8 + lr;
                    int nc = wn * 32 + jt * 8 + 2 * lc;
                    *(__half2*)(Ps + r * FSH + nc) = __floats2half2_rn(p0, p1);
                }
            }
        #pragma unroll
        for (int a = 0; a < 4; a++)
            #pragma unroll
            for (int half = 0; half < 2; half++) {
                float v = psum[a][half];
                v += __shfl_xor_sync(0xFFFFFFFF, v, 1);
                v += __shfl_xor_sync(0xFFFFFFFF, v, 2);
                psum[a][half] = v;
            }
        if (lc == 0) {
            #pragma unroll
            for (int a = 0; a < 4; a++)
                #pragma unroll
                for (int half = 0; half < 2; half++)
                    red_s[(wm * 64 + a * 16 + half * 8 + lr) * 4 + wn] = psum[a][half];
        }
        asm volatile("cp.async.wait_group 0;" ::: "memory");
        __syncthreads();

        if (wn == 0 && lc == 0) {
            #pragma unroll
            for (int a = 0; a < 4; a++)
                #pragma unroll
                for (int half = 0; half < 2; half++) {
                    int r = wm * 64 + a * 16 + half * 8 + lr;
                    float s4 = red_s[r*4] + red_s[r*4 + 1] + red_s[r*4 + 2] + red_s[r*4 + 3];
                    l_s[r] = l_s[r] * c_s[r] + s4;
                }
        }

        const __half* Vs = fsh + 2 * F_TILE_H;
        #pragma unroll
        for (int kk = 0; kk < 8; kk++) {
            uint32_t afr[4][4], bfr[4][2];
            #pragma unroll
            for (int a = 0; a < 4; a++) {
                const __half* ab = Ps + (wm * 64 + a * 16 + lr) * FSH + kk * 16 + lc * 2;
                afr[a][0] = *(const uint32_t*)(ab);
                afr[a][1] = *(const uint32_t*)(ab + 8 * FSH);
                afr[a][2] = *(const uint32_t*)(ab + 8);
                afr[a][3] = *(const uint32_t*)(ab + 8 * FSH + 8);
            }
            #pragma unroll
            for (int jt = 0; jt < 4; jt++) {
                const __half* bb = Vs + (wn * 32 + jt * 8 + lr) * FSH + kk * 16 + lc * 2;
                bfr[jt][0] = *(const uint32_t*)(bb);
                bfr[jt][1] = *(const uint32_t*)(bb + 8);
            }
            #pragma unroll
            for (int a = 0; a < 4; a++)
                #pragma unroll
                for (int jt = 0; jt < 4; jt++)
                    mma_f16(oacc[a][jt], afr[a], bfr[jt]);
        }
        __syncthreads();
    }

    __half* og = o + ((long long)(b * TT + i * 128)) * EE + h * HD;
    #pragma unroll
    for (int a = 0; a < 4; a++)
        #pragma unroll
        for (int half = 0; half < 2; half++) {
            int r = wm * 64 + a * 16 + half * 8 + lr;
            float linv = 1.0f / l_s[r];
            __half* orow = og + (long long)r * EE;
            #pragma unroll
            for (int jt = 0; jt < 4; jt++) {
                int nc = wn * 32 + jt * 8 + 2 * lc;
                *(__half2*)(orow + nc) =
                    __floats2half2_rn(oacc[a][jt][half*2 + 0] * linv,
                                      oacc[a][jt][half*2 + 1] * linv);
            }
        }
}

// ---------------- loss combine: merge per-tile partials ----------------
__global__ void loss_combine_kernel(const float* __restrict__ lsm,
                                    const float* __restrict__ lss,
                                    const float* __restrict__ logits,
                                    const void* __restrict__ tgtv,
                                    float* __restrict__ nll) {
    int r = blockIdx.x;
    int tid = threadIdx.x, wid = tid >> 5, lane = tid & 31;
    const float* rm = lsm + (long long)r * NTL;
    const float* rs = lss + (long long)r * NTL;
    __shared__ float wred[8];
    __shared__ float sMax;

    float m = -1e30f;
    for (int j = tid; j < NTL; j += 256) m = fmaxf(m, rm[j]);
    #pragma unroll
    for (int o = 16; o; o >>= 1) m = fmaxf(m, __shfl_xor_sync(0xFFFFFFFFu, m, o));
    if (lane == 0) wred[wid] = m;
    __syncthreads();
    if (tid == 0) {
        float t = wred[0];
        #pragma unroll
        for (int i = 1; i < 8; i++) t = fmaxf(t, wred[i]);
        sMax = t;
    }
    __syncthreads();
    m = sMax;

    float s = 0.0f;
    for (int j = tid; j < NTL; j += 256) s += rs[j] * __expf(rm[j] - m);
    #pragma unroll
    for (int o = 16; o; o >>= 1) s += __shfl_xor_sync(0xFFFFFFFFu, s, o);
    __syncthreads();
    if (lane == 0) wred[wid] = s;
    __syncthreads();
    if (tid == 0) {
        float t = 0.0f;
        #pragma unroll
        for (int i = 0; i < 8; i++) t += wred[i];
        long long tgt = load_token(tgtv, r, g_is64_tgt);
        nll[r] = (m + logf(t)) - logits[(long long)r * VV + tgt];
    }
}

__global__ void loss_final_kernel(const float* __restrict__ nll, float* __restrict__ out, int n) {
    __shared__ float red[256];
    int tid = threadIdx.x;
    float s = 0.0f;
    for (int j = tid; j < BT; j += 256) s += nll[j];
    red[tid] = s; __syncthreads();
    for (int k = 128; k > 0; k >>= 1) { if (tid < k) red[tid] += red[tid + k]; __syncthreads(); }
    float mean = red[0] * (1.0f / BT);
    for (int i = tid; i < n; i += 256) out[i] = mean;
}

// ---------------- host-side helpers ----------------
static void tcg(const __half* A, int lda, const __half* Bm, int ldb,
                float* Cf, __half* Ch, int ldc, int M, int N, int K,
                const float* bias, int epi, __half* vt = nullptr,
                float* lsm = nullptr, float* lss = nullptr) {
    dim3 grid(M / 128, N / 128, 1);   // m fastest
    tc_gemm_h<<<grid, 256, TC_SMEM>>>(A, lda, Bm, ldb, Cf, Ch, ldc, K, bias, epi,
                                      vt, lsm, lss);
}

extern "C" void kernel_launch(void* const* d_in, const int* in_sizes, int n_in,
                              void* d_out, int out_size) {
    const void*  idx  = d_in[0];
    const void*  tgt  = d_in[1];
    const float* tok  = (const float*)d_in[2];
    const float* pos  = (const float*)d_in[3];
    const float* Wq   = (const float*)d_in[4];
    const float* bq   = (const float*)d_in[5];
    const float* Wk   = (const float*)d_in[6];
    const float* bk   = (const float*)d_in[7];
    const float* Wv   = (const float*)d_in[8];
    const float* bv   = (const float*)d_in[9];
    const float* Wo   = (const float*)d_in[10];
    const float* bo   = (const float*)d_in[11];
    const float* w1   = (const float*)d_in[12];
    const float* b1   = (const float*)d_in[13];
    const float* w2   = (const float*)d_in[14];
    const float* b2   = (const float*)d_in[15];
    const float* ln1s = (const float*)d_in[16];
    const float* ln1b = (const float*)d_in[17];
    const float* ln2s = (const float*)d_in[18];
    const float* ln2b = (const float*)d_in[19];
    const float* lnfs = (const float*)d_in[20];
    const float* lnfb = (const float*)d_in[21];
    const float* Wlm  = (const float*)d_in[22];
    const float* blm  = (const float*)d_in[23];

    float *x, *nll, *logits_fb, *bqkv, *lsm, *lss;
    __half *hh, *qkvh, *vTh, *oh, *ffh, *wqkvTh, *woTh, *w1Th, *w2Th, *wlmTh;
    cudaGetSymbolAddress((void**)&x,     g_x);
    cudaGetSymbolAddress((void**)&hh,    g_hh);
    cudaGetSymbolAddress((void**)&qkvh,  g_qkvh);
    cudaGetSymbolAddress((void**)&vTh,   g_vTh);
    cudaGetSymbolAddress((void**)&oh,    g_oh);
    cudaGetSymbolAddress((void**)&ffh,   g_ffh);
    cudaGetSymbolAddress((void**)&nll,   g_nll);
    cudaGetSymbolAddress((void**)&lsm,   g_lsm);
    cudaGetSymbolAddress((void**)&lss,   g_lss);
    cudaGetSymbolAddress((void**)&logits_fb, g_logits_fb);
    cudaGetSymbolAddress((void**)&wqkvTh, g_wqkvTh);
    cudaGetSymbolAddress((void**)&bqkv,   g_bqkv);
    cudaGetSymbolAddress((void**)&woTh,  g_woTh);
    cudaGetSymbolAddress((void**)&w1Th,  g_w1Th);
    cudaGetSymbolAddress((void**)&w2Th,  g_w2Th);
    cudaGetSymbolAddress((void**)&wlmTh, g_wlmTh);

    cudaFuncSetAttribute(tc_gemm_h, cudaFuncAttributeMaxDynamicSharedMemorySize, TC_SMEM);
    cudaFuncSetAttribute(flash_kernel, cudaFuncAttributeMaxDynamicSharedMemorySize, FLASH_SMEM);

    float* out = (float*)d_out;
    float* logits = ((long long)out_size >= BTV) ? out : logits_fb;
    float* lossPtr = nullptr;
    int nLoss = 0;
    if ((long long)out_size > BTV) { lossPtr = out + BTV; nLoss = out_size - (int)BTV; }
    else if ((long long)out_size < BTV) { lossPtr = out; nLoss = out_size; }

    const long long E2  = (long long)EE * EE;
    const long long EF  = (long long)EE * FF;
    const long long LQ3 = (long long)QKV3 * EE;

    detect_kernel<<<1, 32>>>((const int*)idx, (const int*)tgt);
    embed_kernel<<<BT, 256>>>(idx, tok, pos, x);
    {
        dim3 grid(EE / 32, EE / 32, 3 * LL + 1), blk(32, 8);
        qkv_prep_kernel<<<grid, blk>>>(Wq, Wk, Wv, bq, bk, bv, wqkvTh, bqkv);
    }
    {
        dim3 blk(32, 8);
        transpose_f2h_kernel<<<dim3(EE/32, EE/32, LL), blk>>>(Wo, woTh, EE, EE, E2, E2);
        transpose_f2h_kernel<<<dim3(FF/32, EE/32, LL), blk>>>(w1, w1Th, FF, EE, EF, EF);
        transpose_f2h_kernel<<<dim3(EE/32, FF/32, LL), blk>>>(w2, w2Th, EE, FF, EF, EF);
        transpose_f2h_kernel<<<dim3(VV/32, EE/32, 1), blk>>>(Wlm, wlmTh, VV, EE, 0, 0);
    }

    for (int l = 0; l < LL; l++) {
        // h = fp16(LN1(x))
        layernorm_kernel<<<BT, 256>>>(x, hh, ln1s + l * EE, ln1b + l * EE);

        // qkv = fp16(h @ Wqkv + bqkv); V tiles also scattered into vT
        tcg(hh, EE, wqkvTh + l * LQ3, EE, nullptr, qkvh, QKV3, BT, QKV3, EE,
            bqkv + l * QKV3, 0, vTh);

        // fused attention -> o (fp16)
        flash_kernel<<<dim3(8, BB * HH), 256, FLASH_SMEM>>>(qkvh, vTh, oh);

        // x += o @ Wo + bo   (fp32 out)
        tcg(oh, EE, woTh + l * E2, EE, x, nullptr, EE, BT, EE, EE, bo + l * EE, 2);

        // h = fp16(LN2(x))
        layernorm_kernel<<<BT, 256>>>(x, hh, ln2s + l * EE, ln2b + l * EE);

        // ff = fp16(relu(h @ w1 + b1));  x += ff @ w2 + b2
        tcg(hh, EE, w1Th + l * EF, EE, nullptr, ffh, FF, BT, FF, EE,
            b1 + (long long)l * FF, 1);
        tcg(ffh, FF, w2Th + l * EF, FF, x, nullptr, EE, BT, EE, FF, b2 + l * EE, 2);
    }

    // final LN + LM head (fp32 logits + fused logsumexp partials)
    layernorm_kernel<<<BT, 256>>>(x, hh, lnfs, lnfb);
    tcg(hh, EE, wlmTh, EE, logits, nullptr, VV, BT, VV, EE, blm, 0,
        nullptr, lsm, lss);

    // loss from partials (reads 8 MB instead of 1 GB)
    loss_combine_kernel<<<BT, 256>>>(lsm, lss, logits, tgt, nll);
    if (nLoss > 0)
        loss_final_kernel<<<1, 256>>>(nll, lossPtr, nLoss);
}